// round 4
// baseline (speedup 1.0000x reference)
#include <cuda_runtime.h>
#include <cuda_bf16.h>
#include <cstdint>

#define DIM 128
#define CDIM 40
#define NLAYER 4
#define NMAX 50000
#define EMAX 800000

// ---------------- device scratch (static: no allocations allowed) ----------
__device__ float g_xbuf[NMAX * DIM];
__device__ float g_gbuf[NMAX * DIM];
__device__ float g_hbuf[NMAX * DIM];
__device__ float g_wfold[DIM * DIM];
__device__ float g_bfold[DIM];
__device__ float g_colsum[DIM];
__device__ float g_colsumsq[DIM];
__device__ int   g_rowptr[NMAX + 1];
__device__ int   g_cnt[NMAX];      // zero-initialized; invariant: zero between replays
__device__ int   g_wcur[NMAX];
__device__ int   g_colidx[EMAX];
__device__ float g_vals[EMAX];

// ======================= helpers ===========================================
__device__ __forceinline__ uint32_t smem_u32(const void* p) {
    uint32_t a;
    asm("{ .reg .u64 t; cvta.to.shared.u64 t, %1; cvt.u32.u64 %0, t; }" : "=r"(a) : "l"(p));
    return a;
}
__device__ __forceinline__ void ldm_x4(uint32_t* r, uint32_t addr) {
    asm volatile("ldmatrix.sync.aligned.m8n8.x4.shared.b16 {%0,%1,%2,%3}, [%4];"
                 : "=r"(r[0]), "=r"(r[1]), "=r"(r[2]), "=r"(r[3]) : "r"(addr));
}
__device__ __forceinline__ void ldm_x4_t(uint32_t* r, uint32_t addr) {
    asm volatile("ldmatrix.sync.aligned.m8n8.x4.trans.shared.b16 {%0,%1,%2,%3}, [%4];"
                 : "=r"(r[0]), "=r"(r[1]), "=r"(r[2]), "=r"(r[3]) : "r"(addr));
}
__device__ __forceinline__ void mma_bf16(float* c, const uint32_t* a, const uint32_t* b) {
    asm volatile(
        "mma.sync.aligned.m16n8k16.row.col.f32.bf16.bf16.f32 "
        "{%0,%1,%2,%3}, {%4,%5,%6,%7}, {%8,%9}, {%0,%1,%2,%3};"
        : "+f"(c[0]), "+f"(c[1]), "+f"(c[2]), "+f"(c[3])
        : "r"(a[0]), "r"(a[1]), "r"(a[2]), "r"(a[3]), "r"(b[0]), "r"(b[1]));
}
__device__ __forceinline__ uint32_t pack_hi(float x, float y, uint32_t& lo) {
    __nv_bfloat16 hx = __float2bfloat16(x);
    __nv_bfloat16 hy = __float2bfloat16(y);
    __nv_bfloat16 lx = __float2bfloat16(x - __bfloat162float(hx));
    __nv_bfloat16 ly = __float2bfloat16(y - __bfloat162float(hy));
    lo = (uint32_t)__bfloat16_as_ushort(lx) | ((uint32_t)__bfloat16_as_ushort(ly) << 16);
    return (uint32_t)__bfloat16_as_ushort(hx) | ((uint32_t)__bfloat16_as_ushort(hy) << 16);
}

// ======================= mma.sync GEMM [n,128] x [128,128] ==================
// fp32 accuracy via bf16 hi/lo split: D = Ah*Bh + Ah*Bl + Al*Bh.
// 256 threads / 8 warps; warp tile m32 x n64. Padded smem (stride 136 bf16).
#define PADK 136
#define TILE_B (128 * PADK * 2)           // 34816 bytes per bf16 tile
#define GEMM_SMEM_BYTES (4 * TILE_B + 512)

__global__ __launch_bounds__(256) void gemm_mma_k(
    const float* __restrict__ A, const float* __restrict__ B,
    const float* __restrict__ bias, float* __restrict__ C, int n) {
    extern __shared__ char sm[];
    const int OFF_AH = 0, OFF_AL = TILE_B, OFF_BH = 2 * TILE_B, OFF_BL = 3 * TILE_B;
    float* sbias = reinterpret_cast<float*>(sm + 4 * TILE_B);
    uint32_t sb = smem_u32(sm);
    int tid = threadIdx.x, wid = tid >> 5, lane = tid & 31;
    int row0 = blockIdx.x * 128;

    if (tid < DIM) sbias[tid] = bias ? bias[tid] : 0.f;

    // stage: fp32 -> (hi, lo) bf16 tiles for A and B
    for (int g = tid; g < 4096; g += 256) {
        int r = g >> 5;
        int c = (g & 31) * 4;
        float4 av;
        if (row0 + r < n) av = *reinterpret_cast<const float4*>(&A[(size_t)(row0 + r) * DIM + c]);
        else av = make_float4(0.f, 0.f, 0.f, 0.f);
        float4 bv = *reinterpret_cast<const float4*>(&B[r * DIM + c]);
        uint32_t eoff = (uint32_t)(r * PADK + c) * 2u;
        uint32_t al0, al1, bl0, bl1;
        uint32_t ah0 = pack_hi(av.x, av.y, al0);
        uint32_t ah1 = pack_hi(av.z, av.w, al1);
        uint32_t bh0 = pack_hi(bv.x, bv.y, bl0);
        uint32_t bh1 = pack_hi(bv.z, bv.w, bl1);
        *reinterpret_cast<uint2*>(sm + OFF_AH + eoff) = make_uint2(ah0, ah1);
        *reinterpret_cast<uint2*>(sm + OFF_AL + eoff) = make_uint2(al0, al1);
        *reinterpret_cast<uint2*>(sm + OFF_BH + eoff) = make_uint2(bh0, bh1);
        *reinterpret_cast<uint2*>(sm + OFF_BL + eoff) = make_uint2(bl0, bl1);
    }
    __syncthreads();

    int wm = (wid & 3) * 32;       // warp row offset
    int wn = (wid >> 2) * 64;      // warp col offset
    float acc[2][8][4];
#pragma unroll
    for (int mg = 0; mg < 2; mg++)
#pragma unroll
        for (int ng = 0; ng < 8; ng++)
#pragma unroll
            for (int q = 0; q < 4; q++) acc[mg][ng][q] = 0.f;

    int lrow = lane & 15;
    int lcol8 = (lane >> 4) << 3;

#pragma unroll
    for (int t = 0; t < 3; t++) {
        uint32_t aBase = sb + ((t == 2) ? OFF_AL : OFF_AH);
        uint32_t bBase = sb + ((t == 1) ? OFF_BL : OFF_BH);
#pragma unroll
        for (int k0 = 0; k0 < 128; k0 += 16) {
            uint32_t a[2][4];
#pragma unroll
            for (int mg = 0; mg < 2; mg++) {
                uint32_t addr = aBase + (uint32_t)((wm + mg * 16 + lrow) * PADK + k0 + lcol8) * 2u;
                ldm_x4(a[mg], addr);
            }
            uint32_t b[4][4];
#pragma unroll
            for (int nc = 0; nc < 4; nc++) {
                uint32_t addr = bBase + (uint32_t)((k0 + lrow) * PADK + wn + nc * 16 + lcol8) * 2u;
                ldm_x4_t(b[nc], addr);
            }
#pragma unroll
            for (int mg = 0; mg < 2; mg++)
#pragma unroll
                for (int ng = 0; ng < 8; ng++)
                    mma_bf16(acc[mg][ng], a[mg], &b[ng >> 1][(ng & 1) * 2]);
        }
    }

    // epilogue: c0,c1 -> (row, col..col+1); c2,c3 -> (row+8, col..col+1)
    int rbase = row0 + wm + (lane >> 2);
    int cbase = wn + (lane & 3) * 2;
#pragma unroll
    for (int mg = 0; mg < 2; mg++) {
#pragma unroll
        for (int half = 0; half < 2; half++) {
            int row = rbase + mg * 16 + half * 8;
            if (row < n) {
#pragma unroll
                for (int ng = 0; ng < 8; ng++) {
                    int col = cbase + ng * 8;
                    float2 o;
                    o.x = acc[mg][ng][half * 2] + sbias[col];
                    o.y = acc[mg][ng][half * 2 + 1] + sbias[col + 1];
                    *reinterpret_cast<float2*>(&C[(size_t)row * DIM + col]) = o;
                }
            }
        }
    }
}

// ======================= stats / pairnorm ===================================
__global__ void col_stats_k(const float* __restrict__ x, int n) {
    int t = threadIdx.x;
    int lane = t & 31, rs = t >> 5;
    float4 s = make_float4(0.f, 0.f, 0.f, 0.f);
    float4 s2 = make_float4(0.f, 0.f, 0.f, 0.f);
    for (int row = blockIdx.x * 4 + rs; row < n; row += gridDim.x * 4) {
        float4 v = *reinterpret_cast<const float4*>(&x[(size_t)row * DIM + lane * 4]);
        s.x += v.x; s.y += v.y; s.z += v.z; s.w += v.w;
        s2.x += v.x * v.x; s2.y += v.y * v.y; s2.z += v.z * v.z; s2.w += v.w * v.w;
    }
    int c = lane * 4;
    atomicAdd(&g_colsum[c], s.x);     atomicAdd(&g_colsum[c + 1], s.y);
    atomicAdd(&g_colsum[c + 2], s.z); atomicAdd(&g_colsum[c + 3], s.w);
    atomicAdd(&g_colsumsq[c], s2.x);     atomicAdd(&g_colsumsq[c + 1], s2.y);
    atomicAdd(&g_colsumsq[c + 2], s2.z); atomicAdd(&g_colsumsq[c + 3], s2.w);
}

__global__ void fold_bn_k(const float* __restrict__ W, const float* __restrict__ b,
                          const float* __restrict__ gamma, const float* __restrict__ beta,
                          float n_inv) {
    int j = threadIdx.x;
    __shared__ float sc[DIM], sh[DIM];
    float mu = g_colsum[j] * n_inv;
    float var = g_colsumsq[j] * n_inv - mu * mu;
    float s = gamma[j] * rsqrtf(var + 1e-5f);
    sc[j] = s;
    sh[j] = beta[j] - mu * s;
    __syncthreads();
    float acc = b[j];
    for (int d = 0; d < DIM; d++) {
        float w = W[d * DIM + j];
        g_wfold[d * DIM + j] = sc[d] * w;
        acc += sh[d] * w;
    }
    g_bfold[j] = acc;
}

// Fused PairNorm finalize + apply.
__global__ __launch_bounds__(256) void pn_apply_k(
    const float* __restrict__ h, float* __restrict__ x, int n, int addold, float n_inv) {
    __shared__ float smu[DIM];
    __shared__ float red[DIM];
    __shared__ float sscale;
    int t = threadIdx.x;
    if (t < DIM) {
        float mu = g_colsum[t] * n_inv;
        smu[t] = mu;
        red[t] = g_colsumsq[t] * n_inv - mu * mu;
    }
    __syncthreads();
    for (int off = 64; off > 0; off >>= 1) {
        if (t < off) red[t] += red[t + off];
        __syncthreads();
    }
    if (t == 0) sscale = rsqrtf(1e-6f + red[0]);
    __syncthreads();
    float s = sscale;
    int total = n * (DIM / 4);
    for (int idx = blockIdx.x * 256 + t; idx < total; idx += gridDim.x * 256) {
        int col4 = idx & (DIM / 4 - 1);
        float4 hv = reinterpret_cast<const float4*>(h)[idx];
        float4 m = reinterpret_cast<const float4*>(smu)[col4];
        float4 r;
        r.x = fmaxf((hv.x - m.x) * s, 0.f);
        r.y = fmaxf((hv.y - m.y) * s, 0.f);
        r.z = fmaxf((hv.z - m.z) * s, 0.f);
        r.w = fmaxf((hv.w - m.w) * s, 0.f);
        if (addold) {
            float4 xo = reinterpret_cast<const float4*>(x)[idx];
            r.x += xo.x; r.y += xo.y; r.z += xo.z; r.w += xo.w;
        }
        reinterpret_cast<float4*>(x)[idx] = r;
    }
}

// ======================= CSR build ==========================================
__global__ void hist_k(const int* __restrict__ er, int e) {
    int i = blockIdx.x * blockDim.x + threadIdx.x;
    if (blockIdx.x == 0 && threadIdx.x < DIM) {
        g_colsum[threadIdx.x] = 0.f;
        g_colsumsq[threadIdx.x] = 0.f;
    }
    if (i < e) atomicAdd(&g_cnt[er[i]], 1);
}

__global__ __launch_bounds__(1024) void scan_rowptr_k(int n) {
    __shared__ int part[1024];
    int tid = threadIdx.x;
    int chunk = (n + 1023) / 1024;
    int start = min(tid * chunk, n);
    int end = min(start + chunk, n);
    int s = 0;
    for (int i = start; i < end; i++) s += g_cnt[i];
    part[tid] = s;
    __syncthreads();
    for (int off = 1; off < 1024; off <<= 1) {
        int v = (tid >= off) ? part[tid - off] : 0;
        __syncthreads();
        part[tid] += v;
        __syncthreads();
    }
    int pre = (tid == 0) ? 0 : part[tid - 1];
    for (int i = start; i < end; i++) {
        int c = g_cnt[i];
        g_rowptr[i] = pre;
        g_wcur[i] = pre;
        g_cnt[i] = 0;      // restore zero invariant for next replay
        pre += c;
    }
    if (tid == 0) g_rowptr[n] = part[1023];
}

__global__ void scatter_k(const int* __restrict__ er, const int* __restrict__ ec,
                          const float* __restrict__ ev, int e) {
    int i = blockIdx.x * blockDim.x + threadIdx.x;
    if (i < e) {
        int r = er[i];
        int pos = atomicAdd(&g_wcur[r], 1);
        g_colidx[pos] = ec[i];
        g_vals[pos] = ev[i];
    }
}

// ======================= SPMM (CSR gather, warp per row) ====================
__global__ void spmm_k(const float* __restrict__ g, const float* __restrict__ bias,
                       float* __restrict__ h, int n) {
    if (blockIdx.x == 0 && threadIdx.x < DIM) {
        g_colsum[threadIdx.x] = 0.f;
        g_colsumsq[threadIdx.x] = 0.f;
    }
    int warp = (blockIdx.x * blockDim.x + threadIdx.x) >> 5;
    int lane = threadIdx.x & 31;
    if (warp >= n) return;
    int s = g_rowptr[warp];
    int e = g_rowptr[warp + 1];
    float4 acc = make_float4(0.f, 0.f, 0.f, 0.f);
    int i = s;
    for (; i + 1 < e; i += 2) {
        int c0 = g_colidx[i], c1 = g_colidx[i + 1];
        float v0 = g_vals[i], v1 = g_vals[i + 1];
        float4 a0 = *reinterpret_cast<const float4*>(&g[(size_t)c0 * DIM + lane * 4]);
        float4 a1 = *reinterpret_cast<const float4*>(&g[(size_t)c1 * DIM + lane * 4]);
        acc.x += v0 * a0.x + v1 * a1.x;
        acc.y += v0 * a0.y + v1 * a1.y;
        acc.z += v0 * a0.z + v1 * a1.z;
        acc.w += v0 * a0.w + v1 * a1.w;
    }
    if (i < e) {
        int c0 = g_colidx[i];
        float v0 = g_vals[i];
        float4 a0 = *reinterpret_cast<const float4*>(&g[(size_t)c0 * DIM + lane * 4]);
        acc.x += v0 * a0.x; acc.y += v0 * a0.y; acc.z += v0 * a0.z; acc.w += v0 * a0.w;
    }
    float4 b4 = *reinterpret_cast<const float4*>(&bias[lane * 4]);
    acc.x += b4.x; acc.y += b4.y; acc.z += b4.z; acc.w += b4.w;
    *reinterpret_cast<float4*>(&h[(size_t)warp * DIM + lane * 4]) = acc;
}

// ======================= output GEMM [n,128] x [128,40] =====================
__global__ __launch_bounds__(256) void gemm_out_k(
    const float* __restrict__ X, const float* __restrict__ W,
    const float* __restrict__ b, float* __restrict__ out, int n) {
    __shared__ float sx[32 * DIM];
    __shared__ float sw[DIM * CDIM];
    int tid = threadIdx.x;
    int row0 = blockIdx.x * 32;
    for (int i = tid; i < DIM * CDIM; i += 256) sw[i] = W[i];
#pragma unroll
    for (int q = 0; q < 4; q++) {
        int flat = (q * 256 + tid) * 4;
        int r = flat >> 7, c = flat & 127;
        float4 v;
        if (row0 + r < n) v = *reinterpret_cast<const float4*>(&X[(size_t)(row0 + r) * DIM + c]);
        else v = make_float4(0.f, 0.f, 0.f, 0.f);
        *reinterpret_cast<float4*>(&sx[flat]) = v;
    }
    __syncthreads();
    int r = tid >> 3;
    int c0 = (tid & 7) * 5;
    float acc[5];
#pragma unroll
    for (int j = 0; j < 5; j++) acc[j] = b[c0 + j];
#pragma unroll 4
    for (int k = 0; k < DIM; k++) {
        float xv = sx[r * DIM + k];
#pragma unroll
        for (int j = 0; j < 5; j++) acc[j] += xv * sw[k * CDIM + c0 + j];
    }
    if (row0 + r < n) {
#pragma unroll
        for (int j = 0; j < 5; j++) out[(size_t)(row0 + r) * CDIM + c0 + j] = acc[j];
    }
}

// ======================= launch =============================================
extern "C" void kernel_launch(void* const* d_in, const int* in_sizes, int n_in,
                              void* d_out, int out_size) {
    const float* x      = (const float*)d_in[0];
    const int*   er     = (const int*)d_in[1];
    const int*   ec     = (const int*)d_in[2];
    const float* ev     = (const float*)d_in[3];
    const float* gamma  = (const float*)d_in[4];
    const float* beta   = (const float*)d_in[5];
    const float* fin_w  = (const float*)d_in[6];
    const float* fin_b  = (const float*)d_in[7];
    const float* gc_w   = (const float*)d_in[8];
    const float* gc_b   = (const float*)d_in[9];
    const float* fout_w = (const float*)d_in[10];
    const float* fout_b = (const float*)d_in[11];
    float* out = (float*)d_out;

    int n = in_sizes[0] / DIM;
    int e = in_sizes[1];
    float n_inv = 1.0f / (float)n;

    float *xbuf, *gbuf, *hbuf, *wfold, *bfold;
    cudaGetSymbolAddress((void**)&xbuf, g_xbuf);
    cudaGetSymbolAddress((void**)&gbuf, g_gbuf);
    cudaGetSymbolAddress((void**)&hbuf, g_hbuf);
    cudaGetSymbolAddress((void**)&wfold, g_wfold);
    cudaGetSymbolAddress((void**)&bfold, g_bfold);

    cudaFuncSetAttribute(gemm_mma_k, cudaFuncAttributeMaxDynamicSharedMemorySize, GEMM_SMEM_BYTES);

    int gblocks = (n + 127) / 128;

    // ---- CSR build (hist also zeroes BN stats) ----
    hist_k<<<(e + 255) / 256, 256>>>(er, e);
    scan_rowptr_k<<<1, 1024>>>(n);
    scatter_k<<<(e + 255) / 256, 256>>>(er, ec, ev, e);

    // ---- BN stats, fold into fc_in, fused tensor-core GEMM ----
    col_stats_k<<<512, 128>>>(x, n);
    fold_bn_k<<<1, DIM>>>(fin_w, fin_b, gamma, beta, n_inv);
    gemm_mma_k<<<gblocks, 256, GEMM_SMEM_BYTES>>>(x, wfold, bfold, xbuf, n);

    // ---- 4 GCN layers ----
    for (int i = 0; i < NLAYER; i++) {
        gemm_mma_k<<<gblocks, 256, GEMM_SMEM_BYTES>>>(xbuf, gc_w + i * DIM * DIM, nullptr, gbuf, n);
        spmm_k<<<(n + 7) / 8, 256>>>(gbuf, gc_b + i * DIM, hbuf, n);     // zeroes stats too
        col_stats_k<<<512, 128>>>(hbuf, n);
        pn_apply_k<<<1024, 256>>>(hbuf, xbuf, n, i > 0 ? 1 : 0, n_inv);  // fused finalize+apply
    }

    // ---- output projection ----
    gemm_out_k<<<(n + 31) / 32, 256>>>(xbuf, fout_w, fout_b, out, n);
}

// round 5
// speedup vs baseline: 1.3741x; 1.3741x over previous
#include <cuda_runtime.h>
#include <cuda_bf16.h>
#include <cstdint>

#define DIM 128
#define CDIM 40
#define NLAYER 4
#define NMAX 50000
#define EMAX 800000

// ---------------- device scratch (static: no allocations allowed) ----------
__device__ float g_xbuf[NMAX * DIM];
__device__ float g_gbuf[NMAX * DIM];
__device__ float g_hbuf[NMAX * DIM];
__device__ float g_wfold[DIM * DIM];
__device__ float g_bfold[DIM];
__device__ float g_cs[2][DIM];     // column sums   (parity slots)
__device__ float g_cq[2][DIM];     // column sumsq  (parity slots)
__device__ __nv_bfloat16 g_bwh[5 * DIM * DIM];  // weight hi parts (wfold, gc_w0..3)
__device__ __nv_bfloat16 g_bwl[5 * DIM * DIM];  // weight lo parts
__device__ int   g_rowptr[NMAX + 1];
__device__ int   g_cnt[NMAX];      // zero-initialized; invariant: zero between replays
__device__ int   g_wcur[NMAX];
__device__ int   g_colidx[EMAX];
__device__ float g_vals[EMAX];

// ======================= helpers ===========================================
__device__ __forceinline__ uint32_t smem_u32(const void* p) {
    uint32_t a;
    asm("{ .reg .u64 t; cvta.to.shared.u64 t, %1; cvt.u32.u64 %0, t; }" : "=r"(a) : "l"(p));
    return a;
}
__device__ __forceinline__ void ldm_x4(uint32_t* r, uint32_t addr) {
    asm volatile("ldmatrix.sync.aligned.m8n8.x4.shared.b16 {%0,%1,%2,%3}, [%4];"
                 : "=r"(r[0]), "=r"(r[1]), "=r"(r[2]), "=r"(r[3]) : "r"(addr));
}
__device__ __forceinline__ void ldm_x4_t(uint32_t* r, uint32_t addr) {
    asm volatile("ldmatrix.sync.aligned.m8n8.x4.trans.shared.b16 {%0,%1,%2,%3}, [%4];"
                 : "=r"(r[0]), "=r"(r[1]), "=r"(r[2]), "=r"(r[3]) : "r"(addr));
}
__device__ __forceinline__ void mma_bf16(float* c, const uint32_t* a, const uint32_t* b) {
    asm volatile(
        "mma.sync.aligned.m16n8k16.row.col.f32.bf16.bf16.f32 "
        "{%0,%1,%2,%3}, {%4,%5,%6,%7}, {%8,%9}, {%0,%1,%2,%3};"
        : "+f"(c[0]), "+f"(c[1]), "+f"(c[2]), "+f"(c[3])
        : "r"(a[0]), "r"(a[1]), "r"(a[2]), "r"(a[3]), "r"(b[0]), "r"(b[1]));
}
__device__ __forceinline__ uint32_t pack_hi(float x, float y, uint32_t& lo) {
    __nv_bfloat16 hx = __float2bfloat16(x);
    __nv_bfloat16 hy = __float2bfloat16(y);
    __nv_bfloat16 lx = __float2bfloat16(x - __bfloat162float(hx));
    __nv_bfloat16 ly = __float2bfloat16(y - __bfloat162float(hy));
    lo = (uint32_t)__bfloat16_as_ushort(lx) | ((uint32_t)__bfloat16_as_ushort(ly) << 16);
    return (uint32_t)__bfloat16_as_ushort(hx) | ((uint32_t)__bfloat16_as_ushort(hy) << 16);
}

// ======================= mma.sync GEMM [n,128] x [128,128] ==================
// fp32 accuracy via bf16 hi/lo split: D = Ah*Bh + Ah*Bl + Al*Bh.
// B pre-split to bf16 in global (g_bwh/g_bwl). Optional fused PairNorm on A:
//   a = relu((A - mu)*scale) [+ Xold]; optionally written back to Xwrite.
#define PADK 136
#define TILE_B (128 * PADK * 2)           // 34816 bytes per bf16 tile
#define GEMM_SMEM_BYTES (4 * TILE_B + 2048)

__global__ __launch_bounds__(256) void gemm_mma_k(
    const float* __restrict__ A, const float* __restrict__ Xold,
    float* __restrict__ Xwrite,
    const __nv_bfloat16* __restrict__ Bh, const __nv_bfloat16* __restrict__ Bl,
    const float* __restrict__ bias, float* __restrict__ C, int n,
    int pn_slot, int zero_slot, int addold, float n_inv) {
    extern __shared__ char sm[];
    const int OFF_AH = 0, OFF_AL = TILE_B, OFF_BH = 2 * TILE_B, OFF_BL = 3 * TILE_B;
    float* sbias = reinterpret_cast<float*>(sm + 4 * TILE_B);
    float* smu = sbias + DIM;
    float* red = smu + DIM;
    uint32_t sb = smem_u32(sm);
    int tid = threadIdx.x, wid = tid >> 5, lane = tid & 31;
    int row0 = blockIdx.x * 128;

    if (zero_slot >= 0 && blockIdx.x == 0 && tid < DIM) {
        g_cs[zero_slot][tid] = 0.f;
        g_cq[zero_slot][tid] = 0.f;
    }
    if (tid < DIM) sbias[tid] = bias ? bias[tid] : 0.f;

    float pscale = 0.f;
    if (pn_slot >= 0) {
        if (tid < DIM) {
            float mu = g_cs[pn_slot][tid] * n_inv;
            smu[tid] = mu;
            red[tid] = g_cq[pn_slot][tid] * n_inv - mu * mu;
        }
        __syncthreads();
        for (int off = 64; off > 0; off >>= 1) {
            if (tid < off) red[tid] += red[tid + off];
            __syncthreads();
        }
        if (tid == 0) red[0] = rsqrtf(1e-6f + red[0]);
        __syncthreads();
        pscale = red[0];
    }

    // stage A: optional PairNorm+relu+residual, then split to bf16 hi/lo
    for (int g = tid; g < 4096; g += 256) {
        int r = g >> 5;
        int c = (g & 31) * 4;
        int row = row0 + r;
        float4 av = make_float4(0.f, 0.f, 0.f, 0.f);
        if (row < n) {
            av = *reinterpret_cast<const float4*>(&A[(size_t)row * DIM + c]);
            if (pn_slot >= 0) {
                float4 m = *reinterpret_cast<const float4*>(&smu[c]);
                av.x = fmaxf((av.x - m.x) * pscale, 0.f);
                av.y = fmaxf((av.y - m.y) * pscale, 0.f);
                av.z = fmaxf((av.z - m.z) * pscale, 0.f);
                av.w = fmaxf((av.w - m.w) * pscale, 0.f);
                if (addold) {
                    float4 xo = *reinterpret_cast<const float4*>(&Xold[(size_t)row * DIM + c]);
                    av.x += xo.x; av.y += xo.y; av.z += xo.z; av.w += xo.w;
                }
                if (Xwrite)
                    *reinterpret_cast<float4*>(&Xwrite[(size_t)row * DIM + c]) = av;
            }
        }
        uint32_t eoff = (uint32_t)(r * PADK + c) * 2u;
        uint32_t al0, al1;
        uint32_t ah0 = pack_hi(av.x, av.y, al0);
        uint32_t ah1 = pack_hi(av.z, av.w, al1);
        *reinterpret_cast<uint2*>(sm + OFF_AH + eoff) = make_uint2(ah0, ah1);
        *reinterpret_cast<uint2*>(sm + OFF_AL + eoff) = make_uint2(al0, al1);
    }
    // stage B: plain bf16 copy (pre-split weights)
    for (int g = tid; g < 2048; g += 256) {
        int r = g >> 4;
        int c = (g & 15) * 8;
        uint4 vh = reinterpret_cast<const uint4*>(Bh)[g];
        uint4 vl = reinterpret_cast<const uint4*>(Bl)[g];
        uint32_t eoff = (uint32_t)(r * PADK + c) * 2u;
        *reinterpret_cast<uint4*>(sm + OFF_BH + eoff) = vh;
        *reinterpret_cast<uint4*>(sm + OFF_BL + eoff) = vl;
    }
    __syncthreads();

    int wm = (wid & 3) * 32;       // warp row offset
    int wn = (wid >> 2) * 64;      // warp col offset
    float acc[2][8][4];
#pragma unroll
    for (int mg = 0; mg < 2; mg++)
#pragma unroll
        for (int ng = 0; ng < 8; ng++)
#pragma unroll
            for (int q = 0; q < 4; q++) acc[mg][ng][q] = 0.f;

    int lrow = lane & 15;
    int lcol8 = (lane >> 4) << 3;

#pragma unroll
    for (int t = 0; t < 3; t++) {
        uint32_t aBase = sb + ((t == 2) ? OFF_AL : OFF_AH);
        uint32_t bBase = sb + ((t == 1) ? OFF_BL : OFF_BH);
#pragma unroll
        for (int k0 = 0; k0 < 128; k0 += 16) {
            uint32_t a[2][4];
#pragma unroll
            for (int mg = 0; mg < 2; mg++) {
                uint32_t addr = aBase + (uint32_t)((wm + mg * 16 + lrow) * PADK + k0 + lcol8) * 2u;
                ldm_x4(a[mg], addr);
            }
            uint32_t b[4][4];
#pragma unroll
            for (int nc = 0; nc < 4; nc++) {
                uint32_t addr = bBase + (uint32_t)((k0 + lrow) * PADK + wn + nc * 16 + lcol8) * 2u;
                ldm_x4_t(b[nc], addr);
            }
#pragma unroll
            for (int mg = 0; mg < 2; mg++)
#pragma unroll
                for (int ng = 0; ng < 8; ng++)
                    mma_bf16(acc[mg][ng], a[mg], &b[ng >> 1][(ng & 1) * 2]);
        }
    }

    int rbase = row0 + wm + (lane >> 2);
    int cbase = wn + (lane & 3) * 2;
#pragma unroll
    for (int mg = 0; mg < 2; mg++) {
#pragma unroll
        for (int half = 0; half < 2; half++) {
            int row = rbase + mg * 16 + half * 8;
            if (row < n) {
#pragma unroll
                for (int ng = 0; ng < 8; ng++) {
                    int col = cbase + ng * 8;
                    float2 o;
                    o.x = acc[mg][ng][half * 2] + sbias[col];
                    o.y = acc[mg][ng][half * 2 + 1] + sbias[col + 1];
                    *reinterpret_cast<float2*>(&C[(size_t)row * DIM + col]) = o;
                }
            }
        }
    }
}

// ======================= input BN stats (slot 0) ============================
// 512 blocks x 8 warps = 4096 warps; each warp: lane -> 4 cols, 4 rows in
// flight (MLP=4), then smem block reduction + one gmem atomic set per block.
__global__ __launch_bounds__(256) void col_stats_k(const float* __restrict__ x, int n) {
    __shared__ float red[256];
    int tid = threadIdx.x;
    red[tid] = 0.f;
    int w = tid >> 5, lane = tid & 31, c = lane * 4;
    int gw = blockIdx.x * 8 + w;
    const int STR = 512 * 8;
    float4 s = make_float4(0.f, 0.f, 0.f, 0.f);
    float4 q = make_float4(0.f, 0.f, 0.f, 0.f);
    __syncthreads();
    for (int r0 = gw; r0 < n; r0 += STR * 4) {
#pragma unroll
        for (int u = 0; u < 4; u++) {
            int row = r0 + u * STR;
            if (row < n) {
                float4 v = *reinterpret_cast<const float4*>(&x[(size_t)row * DIM + c]);
                s.x += v.x; s.y += v.y; s.z += v.z; s.w += v.w;
                q.x += v.x * v.x; q.y += v.y * v.y; q.z += v.z * v.z; q.w += v.w * v.w;
            }
        }
    }
    atomicAdd(&red[c], s.x);     atomicAdd(&red[c + 1], s.y);
    atomicAdd(&red[c + 2], s.z); atomicAdd(&red[c + 3], s.w);
    __syncthreads();
    __shared__ float redq[128];
    if (tid < 128) redq[tid] = 0.f;
    __syncthreads();
    atomicAdd(&redq[c], q.x);     atomicAdd(&redq[c + 1], q.y);
    atomicAdd(&redq[c + 2], q.z); atomicAdd(&redq[c + 3], q.w);
    __syncthreads();
    if (tid < 128) {
        atomicAdd(&g_cs[0][tid], red[tid]);
        atomicAdd(&g_cq[0][tid], redq[tid]);
    }
}

// Fold BatchNorm into fc_in (consumes slot 0).
__global__ void fold_bn_k(const float* __restrict__ W, const float* __restrict__ b,
                          const float* __restrict__ gamma, const float* __restrict__ beta,
                          float n_inv) {
    int j = threadIdx.x;
    __shared__ float sc[DIM], sh[DIM];
    float mu = g_cs[0][j] * n_inv;
    float var = g_cq[0][j] * n_inv - mu * mu;
    float s = gamma[j] * rsqrtf(var + 1e-5f);
    sc[j] = s;
    sh[j] = beta[j] - mu * s;
    __syncthreads();
    float acc = b[j];
    for (int d = 0; d < DIM; d++) {
        float w = W[d * DIM + j];
        g_wfold[d * DIM + j] = sc[d] * w;
        acc += sh[d] * w;
    }
    g_bfold[j] = acc;
}

// Pre-split the 5 weight matrices (wfold + 4 gc layers) into bf16 hi/lo.
__global__ void wconvert_k(const float* __restrict__ gc_w) {
    int i = blockIdx.x * 256 + threadIdx.x;
    if (i >= 5 * DIM * DIM) return;
    float v = (i < DIM * DIM) ? g_wfold[i] : gc_w[i - DIM * DIM];
    __nv_bfloat16 h = __float2bfloat16(v);
    g_bwh[i] = h;
    g_bwl[i] = __float2bfloat16(v - __bfloat162float(h));
}

// ======================= CSR build ==========================================
// hist also zeroes slot-0 stats (block 0). g_cnt zero on entry (invariant).
__global__ void hist_k(const int* __restrict__ er, int e) {
    int i = blockIdx.x * blockDim.x + threadIdx.x;
    if (blockIdx.x == 0 && threadIdx.x < DIM) {
        g_cs[0][threadIdx.x] = 0.f;
        g_cq[0][threadIdx.x] = 0.f;
    }
    if (i < e) atomicAdd(&g_cnt[er[i]], 1);
}

__global__ __launch_bounds__(1024) void scan_rowptr_k(int n) {
    __shared__ int part[1024];
    int tid = threadIdx.x;
    int chunk = (n + 1023) / 1024;
    int start = min(tid * chunk, n);
    int end = min(start + chunk, n);
    int s = 0;
    for (int i = start; i < end; i++) s += g_cnt[i];
    part[tid] = s;
    __syncthreads();
    for (int off = 1; off < 1024; off <<= 1) {
        int v = (tid >= off) ? part[tid - off] : 0;
        __syncthreads();
        part[tid] += v;
        __syncthreads();
    }
    int pre = (tid == 0) ? 0 : part[tid - 1];
    for (int i = start; i < end; i++) {
        int c = g_cnt[i];
        g_rowptr[i] = pre;
        g_wcur[i] = pre;
        g_cnt[i] = 0;      // restore zero invariant for next replay
        pre += c;
    }
    if (tid == 0) g_rowptr[n] = part[1023];
}

__global__ void scatter_k(const int* __restrict__ er, const int* __restrict__ ec,
                          const float* __restrict__ ev, int e) {
    int i = blockIdx.x * blockDim.x + threadIdx.x;
    if (i < e) {
        int r = er[i];
        int pos = atomicAdd(&g_wcur[r], 1);
        g_colidx[pos] = ec[i];
        g_vals[pos] = ev[i];
    }
}

// ======================= SPMM + fused PairNorm stats ========================
// Warp handles 4 rows; lane owns 4 columns. Output row stats (sum, sumsq)
// accumulated in registers -> smem -> one gmem atomic set per block.
__global__ __launch_bounds__(256) void spmm_k(
    const float* __restrict__ g, const float* __restrict__ bias,
    float* __restrict__ h, int n, int slot) {
    __shared__ float red[256];   // [0:128) sum, [128:256) sumsq
    int tid = threadIdx.x;
    red[tid] = 0.f;
    int w = tid >> 5, lane = tid & 31;
    int gw = blockIdx.x * 8 + w;
    int c = lane * 4;
    float4 b4 = *reinterpret_cast<const float4*>(&bias[c]);
    float4 ssum = make_float4(0.f, 0.f, 0.f, 0.f);
    float4 ssq = make_float4(0.f, 0.f, 0.f, 0.f);
    __syncthreads();
#pragma unroll
    for (int rr = 0; rr < 4; rr++) {
        int row = gw * 4 + rr;
        if (row >= n) break;
        int s = g_rowptr[row];
        int e = g_rowptr[row + 1];
        float4 acc = make_float4(0.f, 0.f, 0.f, 0.f);
        int i = s;
        for (; i + 1 < e; i += 2) {
            int c0 = g_colidx[i], c1 = g_colidx[i + 1];
            float v0 = g_vals[i], v1 = g_vals[i + 1];
            float4 a0 = *reinterpret_cast<const float4*>(&g[(size_t)c0 * DIM + c]);
            float4 a1 = *reinterpret_cast<const float4*>(&g[(size_t)c1 * DIM + c]);
            acc.x += v0 * a0.x + v1 * a1.x;
            acc.y += v0 * a0.y + v1 * a1.y;
            acc.z += v0 * a0.z + v1 * a1.z;
            acc.w += v0 * a0.w + v1 * a1.w;
        }
        if (i < e) {
            int c0 = g_colidx[i];
            float v0 = g_vals[i];
            float4 a0 = *reinterpret_cast<const float4*>(&g[(size_t)c0 * DIM + c]);
            acc.x += v0 * a0.x; acc.y += v0 * a0.y; acc.z += v0 * a0.z; acc.w += v0 * a0.w;
        }
        acc.x += b4.x; acc.y += b4.y; acc.z += b4.z; acc.w += b4.w;
        *reinterpret_cast<float4*>(&h[(size_t)row * DIM + c]) = acc;
        ssum.x += acc.x; ssum.y += acc.y; ssum.z += acc.z; ssum.w += acc.w;
        ssq.x += acc.x * acc.x; ssq.y += acc.y * acc.y;
        ssq.z += acc.z * acc.z; ssq.w += acc.w * acc.w;
    }
    atomicAdd(&red[c], ssum.x);     atomicAdd(&red[c + 1], ssum.y);
    atomicAdd(&red[c + 2], ssum.z); atomicAdd(&red[c + 3], ssum.w);
    atomicAdd(&red[128 + c], ssq.x);     atomicAdd(&red[128 + c + 1], ssq.y);
    atomicAdd(&red[128 + c + 2], ssq.z); atomicAdd(&red[128 + c + 3], ssq.w);
    __syncthreads();
    if (tid < 128) atomicAdd(&g_cs[slot][tid], red[tid]);
    else atomicAdd(&g_cq[slot][tid - 128], red[tid]);
}

// ======================= output GEMM + fused final PairNorm =================
__global__ __launch_bounds__(256) void gemm_out_k(
    const float* __restrict__ H, const float* __restrict__ Xold,
    const float* __restrict__ W, const float* __restrict__ b,
    float* __restrict__ out, int n, int pn_slot, float n_inv) {
    __shared__ float sx[32 * DIM];
    __shared__ float sw[DIM * CDIM];
    __shared__ float smu[DIM];
    __shared__ float red[DIM];
    int tid = threadIdx.x;
    int row0 = blockIdx.x * 32;
    for (int i = tid; i < DIM * CDIM; i += 256) sw[i] = W[i];
    if (tid < DIM) {
        float mu = g_cs[pn_slot][tid] * n_inv;
        smu[tid] = mu;
        red[tid] = g_cq[pn_slot][tid] * n_inv - mu * mu;
    }
    __syncthreads();
    for (int off = 64; off > 0; off >>= 1) {
        if (tid < off) red[tid] += red[tid + off];
        __syncthreads();
    }
    if (tid == 0) red[0] = rsqrtf(1e-6f + red[0]);
    __syncthreads();
    float s = red[0];
#pragma unroll
    for (int q = 0; q < 4; q++) {
        int flat = (q * 256 + tid) * 4;
        int r = flat >> 7, c = flat & 127;
        int row = row0 + r;
        float4 v = make_float4(0.f, 0.f, 0.f, 0.f);
        if (row < n) {
            float4 hv = *reinterpret_cast<const float4*>(&H[(size_t)row * DIM + c]);
            float4 m = *reinterpret_cast<const float4*>(&smu[c]);
            float4 xo = *reinterpret_cast<const float4*>(&Xold[(size_t)row * DIM + c]);
            v.x = fmaxf((hv.x - m.x) * s, 0.f) + xo.x;
            v.y = fmaxf((hv.y - m.y) * s, 0.f) + xo.y;
            v.z = fmaxf((hv.z - m.z) * s, 0.f) + xo.z;
            v.w = fmaxf((hv.w - m.w) * s, 0.f) + xo.w;
        }
        *reinterpret_cast<float4*>(&sx[flat]) = v;
    }
    __syncthreads();
    int r = tid >> 3;
    int c0 = (tid & 7) * 5;
    float acc[5];
#pragma unroll
    for (int j = 0; j < 5; j++) acc[j] = b[c0 + j];
#pragma unroll 4
    for (int k = 0; k < DIM; k++) {
        float xv = sx[r * DIM + k];
#pragma unroll
        for (int j = 0; j < 5; j++) acc[j] += xv * sw[k * CDIM + c0 + j];
    }
    if (row0 + r < n) {
#pragma unroll
        for (int j = 0; j < 5; j++) out[(size_t)(row0 + r) * CDIM + c0 + j] = acc[j];
    }
}

// ======================= launch =============================================
extern "C" void kernel_launch(void* const* d_in, const int* in_sizes, int n_in,
                              void* d_out, int out_size) {
    const float* x      = (const float*)d_in[0];
    const int*   er     = (const int*)d_in[1];
    const int*   ec     = (const int*)d_in[2];
    const float* ev     = (const float*)d_in[3];
    const float* gamma  = (const float*)d_in[4];
    const float* beta   = (const float*)d_in[5];
    const float* fin_w  = (const float*)d_in[6];
    const float* fin_b  = (const float*)d_in[7];
    const float* gc_w   = (const float*)d_in[8];
    const float* gc_b   = (const float*)d_in[9];
    const float* fout_w = (const float*)d_in[10];
    const float* fout_b = (const float*)d_in[11];
    float* out = (float*)d_out;

    int n = in_sizes[0] / DIM;
    int e = in_sizes[1];
    float n_inv = 1.0f / (float)n;

    float *xbuf, *gbuf, *hbuf, *bfold;
    __nv_bfloat16 *bwh, *bwl;
    cudaGetSymbolAddress((void**)&xbuf, g_xbuf);
    cudaGetSymbolAddress((void**)&gbuf, g_gbuf);
    cudaGetSymbolAddress((void**)&hbuf, g_hbuf);
    cudaGetSymbolAddress((void**)&bfold, g_bfold);
    cudaGetSymbolAddress((void**)&bwh, g_bwh);
    cudaGetSymbolAddress((void**)&bwl, g_bwl);

    cudaFuncSetAttribute(gemm_mma_k, cudaFuncAttributeMaxDynamicSharedMemorySize, GEMM_SMEM_BYTES);

    int gblocks = (n + 127) / 128;
    int sblocks = (n + 31) / 32;
    const int WMAT = DIM * DIM;

    // ---- CSR build (hist also zeroes slot-0 stats) ----
    hist_k<<<(e + 255) / 256, 256>>>(er, e);
    scan_rowptr_k<<<1, 1024>>>(n);
    scatter_k<<<(e + 255) / 256, 256>>>(er, ec, ev, e);

    // ---- BN stats -> fold -> weight pre-split ----
    col_stats_k<<<512, 256>>>(x, n);
    fold_bn_k<<<1, DIM>>>(fin_w, fin_b, gamma, beta, n_inv);
    wconvert_k<<<(5 * WMAT + 255) / 256, 256>>>(gc_w);

    // ---- fc_in GEMM (plain A = x); zero slot0 for layer-0 spmm stats ----
    gemm_mma_k<<<gblocks, 256, GEMM_SMEM_BYTES>>>(
        x, nullptr, nullptr, bwh, bwl, bfold, xbuf, n, -1, 0, 0, n_inv);

    // ---- layer 0 GEMM (plain A = xbuf) ----
    gemm_mma_k<<<gblocks, 256, GEMM_SMEM_BYTES>>>(
        xbuf, nullptr, nullptr, bwh + WMAT, bwl + WMAT, nullptr, gbuf, n, -1, -1, 0, n_inv);
    spmm_k<<<sblocks, 256>>>(gbuf, gc_b + 0 * DIM, hbuf, n, 0);

    // ---- layers 1..3: GEMM with fused PairNorm-apply on A ----
    // gemm layer i consumes slot[(i-1)&1], zeroes slot[i&1], addold = (i>=2)
    for (int i = 1; i < NLAYER; i++) {
        gemm_mma_k<<<gblocks, 256, GEMM_SMEM_BYTES>>>(
            hbuf, xbuf, xbuf, bwh + (i + 1) * WMAT, bwl + (i + 1) * WMAT, nullptr,
            gbuf, n, (i - 1) & 1, i & 1, (i >= 2) ? 1 : 0, n_inv);
        spmm_k<<<sblocks, 256>>>(gbuf, gc_b + i * DIM, hbuf, n, i & 1);
    }

    // ---- output projection with fused final PairNorm (slot 1, addold) ----
    gemm_out_k<<<sblocks, 256>>>(hbuf, xbuf, fout_w, fout_b, out, n, (NLAYER - 1) & 1, n_inv);
}

// round 7
// speedup vs baseline: 1.7487x; 1.2726x over previous
#include <cuda_runtime.h>
#include <cuda_bf16.h>
#include <cstdint>

#define DIM 128
#define CDIM 40
#define NLAYER 4
#define NMAX 50000
#define EMAX 800000

// ---------------- device scratch (static: no allocations allowed) ----------
__device__ float g_xbuf[NMAX * DIM];
__device__ float g_gbuf[NMAX * DIM];
__device__ float g_hbuf[NMAX * DIM];
__device__ float g_wfold[DIM * DIM];
__device__ float g_bfold[DIM];
__device__ float g_cs[2][DIM];     // column sums   (parity slots)
__device__ float g_cq[2][DIM];     // column sumsq  (parity slots)
__device__ __nv_bfloat16 g_bwh[5 * DIM * DIM];  // weight hi parts (wfold, gc_w0..3)
__device__ __nv_bfloat16 g_bwl[5 * DIM * DIM];  // weight lo parts
__device__ int   g_rowptr[NMAX + 1];
__device__ int   g_cnt[NMAX];      // zero-initialized; invariant: zero between replays
__device__ int   g_wcur[NMAX];
__device__ int   g_bsum[256];
__device__ int   g_boff[256];
__device__ int   g_colidx[EMAX];
__device__ float g_vals[EMAX];

// ======================= helpers ===========================================
__device__ __forceinline__ uint32_t smem_u32(const void* p) {
    uint32_t a;
    asm("{ .reg .u64 t; cvta.to.shared.u64 t, %1; cvt.u32.u64 %0, t; }" : "=r"(a) : "l"(p));
    return a;
}
__device__ __forceinline__ void ldm_x4(uint32_t* r, uint32_t addr) {
    asm volatile("ldmatrix.sync.aligned.m8n8.x4.shared.b16 {%0,%1,%2,%3}, [%4];"
                 : "=r"(r[0]), "=r"(r[1]), "=r"(r[2]), "=r"(r[3]) : "r"(addr));
}
__device__ __forceinline__ void ldm_x4_t(uint32_t* r, uint32_t addr) {
    asm volatile("ldmatrix.sync.aligned.m8n8.x4.trans.shared.b16 {%0,%1,%2,%3}, [%4];"
                 : "=r"(r[0]), "=r"(r[1]), "=r"(r[2]), "=r"(r[3]) : "r"(addr));
}
__device__ __forceinline__ void mma_bf16(float* c, const uint32_t* a, const uint32_t* b) {
    asm volatile(
        "mma.sync.aligned.m16n8k16.row.col.f32.bf16.bf16.f32 "
        "{%0,%1,%2,%3}, {%4,%5,%6,%7}, {%8,%9}, {%0,%1,%2,%3};"
        : "+f"(c[0]), "+f"(c[1]), "+f"(c[2]), "+f"(c[3])
        : "r"(a[0]), "r"(a[1]), "r"(a[2]), "r"(a[3]), "r"(b[0]), "r"(b[1]));
}
__device__ __forceinline__ uint32_t pack_hi(float x, float y, uint32_t& lo) {
    __nv_bfloat16 hx = __float2bfloat16(x);
    __nv_bfloat16 hy = __float2bfloat16(y);
    __nv_bfloat16 lx = __float2bfloat16(x - __bfloat162float(hx));
    __nv_bfloat16 ly = __float2bfloat16(y - __bfloat162float(hy));
    lo = (uint32_t)__bfloat16_as_ushort(lx) | ((uint32_t)__bfloat16_as_ushort(ly) << 16);
    return (uint32_t)__bfloat16_as_ushort(hx) | ((uint32_t)__bfloat16_as_ushort(hy) << 16);
}

// ======================= GEMM common pieces =================================
// 512 threads / 16 warps, warp grid 4x4, warp tile m32 x n32.
// fp32 accuracy via bf16 hi/lo split: D = Ah*Bh + Ah*Bl + Al*Bh.
#define PADK 136
#define TILE_B (128 * PADK * 2)           // 34816 bytes per bf16 tile
#define OFF_AH 0
#define OFF_AL TILE_B
#define OFF_BH (2 * TILE_B)
#define OFF_BL (3 * TILE_B)
#define GEMM_SMEM_BYTES (4 * TILE_B + 2048)

__device__ __forceinline__ void mma_mainloop(uint32_t sb, int wm, int wn, int lane,
                                             float acc[2][4][4]) {
    int lrow = lane & 15;
    int lcol8 = (lane >> 4) << 3;
#pragma unroll
    for (int t = 0; t < 3; t++) {
        uint32_t aBase = sb + ((t == 2) ? OFF_AL : OFF_AH);
        uint32_t bBase = sb + ((t == 1) ? OFF_BL : OFF_BH);
#pragma unroll
        for (int k0 = 0; k0 < 128; k0 += 16) {
            uint32_t a[2][4];
#pragma unroll
            for (int mg = 0; mg < 2; mg++)
                ldm_x4(a[mg], aBase + (uint32_t)((wm + mg * 16 + lrow) * PADK + k0 + lcol8) * 2u);
            uint32_t b[2][4];
#pragma unroll
            for (int nc = 0; nc < 2; nc++)
                ldm_x4_t(b[nc], bBase + (uint32_t)((k0 + lrow) * PADK + wn + nc * 16 + lcol8) * 2u);
#pragma unroll
            for (int mg = 0; mg < 2; mg++)
#pragma unroll
                for (int ng = 0; ng < 4; ng++)
                    mma_bf16(acc[mg][ng], a[mg], &b[ng >> 1][(ng & 1) * 2]);
        }
    }
}

__device__ __forceinline__ void stage_B(char* sm, const __nv_bfloat16* Bh,
                                        const __nv_bfloat16* Bl, int tid) {
    for (int g = tid; g < 2048; g += 512) {
        int r = g >> 4;
        int c = (g & 15) * 8;
        uint4 vh = reinterpret_cast<const uint4*>(Bh)[g];
        uint4 vl = reinterpret_cast<const uint4*>(Bl)[g];
        uint32_t eoff = (uint32_t)(r * PADK + c) * 2u;
        *reinterpret_cast<uint4*>(sm + OFF_BH + eoff) = vh;
        *reinterpret_cast<uint4*>(sm + OFF_BL + eoff) = vl;
    }
}

// ======================= main GEMM (optional fused PairNorm on A) ===========
__global__ __launch_bounds__(512) void gemm_mma_k(
    const float* __restrict__ A, const float* __restrict__ Xold,
    float* __restrict__ Xwrite,
    const __nv_bfloat16* __restrict__ Bh, const __nv_bfloat16* __restrict__ Bl,
    float* __restrict__ C, int n,
    int pn_slot, int zero_slot, int addold, float n_inv) {
    extern __shared__ char sm[];
    float* smu = reinterpret_cast<float*>(sm + 4 * TILE_B);
    float* red = smu + DIM;
    uint32_t sb = smem_u32(sm);
    int tid = threadIdx.x, wid = tid >> 5, lane = tid & 31;
    int row0 = blockIdx.x * 128;

    if (zero_slot >= 0 && blockIdx.x == 0 && tid < DIM) {
        g_cs[zero_slot][tid] = 0.f;
        g_cq[zero_slot][tid] = 0.f;
    }

    float pscale = 0.f;
    if (pn_slot >= 0) {
        if (tid < DIM) {
            float mu = g_cs[pn_slot][tid] * n_inv;
            smu[tid] = mu;
            red[tid] = g_cq[pn_slot][tid] * n_inv - mu * mu;
        }
        __syncthreads();
        for (int off = 64; off > 0; off >>= 1) {
            if (tid < off) red[tid] += red[tid + off];
            __syncthreads();
        }
        if (tid == 0) red[0] = rsqrtf(1e-6f + red[0]);
        __syncthreads();
        pscale = red[0];
    }

    // stage A: optional PairNorm+relu+residual, then split to bf16 hi/lo
    for (int g = tid; g < 4096; g += 512) {
        int r = g >> 5;
        int c = (g & 31) * 4;
        int row = row0 + r;
        float4 av = make_float4(0.f, 0.f, 0.f, 0.f);
        if (row < n) {
            av = *reinterpret_cast<const float4*>(&A[(size_t)row * DIM + c]);
            if (pn_slot >= 0) {
                float4 m = *reinterpret_cast<const float4*>(&smu[c]);
                av.x = fmaxf((av.x - m.x) * pscale, 0.f);
                av.y = fmaxf((av.y - m.y) * pscale, 0.f);
                av.z = fmaxf((av.z - m.z) * pscale, 0.f);
                av.w = fmaxf((av.w - m.w) * pscale, 0.f);
                if (addold) {
                    float4 xo = *reinterpret_cast<const float4*>(&Xold[(size_t)row * DIM + c]);
                    av.x += xo.x; av.y += xo.y; av.z += xo.z; av.w += xo.w;
                }
                if (Xwrite)
                    *reinterpret_cast<float4*>(&Xwrite[(size_t)row * DIM + c]) = av;
            }
        }
        uint32_t eoff = (uint32_t)(r * PADK + c) * 2u;
        uint32_t al0, al1;
        uint32_t ah0 = pack_hi(av.x, av.y, al0);
        uint32_t ah1 = pack_hi(av.z, av.w, al1);
        *reinterpret_cast<uint2*>(sm + OFF_AH + eoff) = make_uint2(ah0, ah1);
        *reinterpret_cast<uint2*>(sm + OFF_AL + eoff) = make_uint2(al0, al1);
    }
    stage_B(sm, Bh, Bl, tid);
    __syncthreads();

    int wm = (wid & 3) * 32;
    int wn = (wid >> 2) * 32;
    float acc[2][4][4];
#pragma unroll
    for (int mg = 0; mg < 2; mg++)
#pragma unroll
        for (int ng = 0; ng < 4; ng++)
#pragma unroll
            for (int q = 0; q < 4; q++) acc[mg][ng][q] = 0.f;

    mma_mainloop(sb, wm, wn, lane, acc);

    int rbase = row0 + wm + (lane >> 2);
    int cbase = wn + (lane & 3) * 2;
#pragma unroll
    for (int mg = 0; mg < 2; mg++)
#pragma unroll
        for (int half = 0; half < 2; half++) {
            int row = rbase + mg * 16 + half * 8;
            if (row < n) {
#pragma unroll
                for (int ng = 0; ng < 4; ng++) {
                    int col = cbase + ng * 8;
                    float2 o;
                    o.x = acc[mg][ng][half * 2];
                    o.y = acc[mg][ng][half * 2 + 1];
                    *reinterpret_cast<float2*>(&C[(size_t)row * DIM + col]) = o;
                }
            }
        }
}

// ======================= fused fc_in + layer-0 GEMM =========================
// C = (X @ Wfold + bfold) @ Wgc0 ; intermediate kept in smem (block owns full
// 128-wide rows). Zeroes stats slot 0 (block 0) for the following spmm.
__global__ __launch_bounds__(512) void gemm_fused_k(
    const float* __restrict__ X,
    const __nv_bfloat16* __restrict__ Bh1, const __nv_bfloat16* __restrict__ Bl1,
    const __nv_bfloat16* __restrict__ Bh2, const __nv_bfloat16* __restrict__ Bl2,
    const float* __restrict__ bias1, float* __restrict__ C, int n) {
    extern __shared__ char sm[];
    float* sbias = reinterpret_cast<float*>(sm + 4 * TILE_B);
    uint32_t sb = smem_u32(sm);
    int tid = threadIdx.x, wid = tid >> 5, lane = tid & 31;
    int row0 = blockIdx.x * 128;

    if (blockIdx.x == 0 && tid < DIM) {
        g_cs[0][tid] = 0.f;
        g_cq[0][tid] = 0.f;
    }
    if (tid < DIM) sbias[tid] = bias1[tid];

    for (int g = tid; g < 4096; g += 512) {
        int r = g >> 5;
        int c = (g & 31) * 4;
        int row = row0 + r;
        float4 av = make_float4(0.f, 0.f, 0.f, 0.f);
        if (row < n) av = *reinterpret_cast<const float4*>(&X[(size_t)row * DIM + c]);
        uint32_t eoff = (uint32_t)(r * PADK + c) * 2u;
        uint32_t al0, al1;
        uint32_t ah0 = pack_hi(av.x, av.y, al0);
        uint32_t ah1 = pack_hi(av.z, av.w, al1);
        *reinterpret_cast<uint2*>(sm + OFF_AH + eoff) = make_uint2(ah0, ah1);
        *reinterpret_cast<uint2*>(sm + OFF_AL + eoff) = make_uint2(al0, al1);
    }
    stage_B(sm, Bh1, Bl1, tid);
    __syncthreads();

    int wm = (wid & 3) * 32;
    int wn = (wid >> 2) * 32;
    float acc[2][4][4];
#pragma unroll
    for (int mg = 0; mg < 2; mg++)
#pragma unroll
        for (int ng = 0; ng < 4; ng++)
#pragma unroll
            for (int q = 0; q < 4; q++) acc[mg][ng][q] = 0.f;

    mma_mainloop(sb, wm, wn, lane, acc);
    __syncthreads();   // all warps done reading tiles

    // write intermediate (acc + bias) back into A smem tiles as bf16 hi/lo
    {
        int rl = wm + (lane >> 2);
        int cb = wn + (lane & 3) * 2;
#pragma unroll
        for (int mg = 0; mg < 2; mg++)
#pragma unroll
            for (int half = 0; half < 2; half++) {
                int r = rl + mg * 16 + half * 8;
#pragma unroll
                for (int ng = 0; ng < 4; ng++) {
                    int col = cb + ng * 8;
                    float v0 = acc[mg][ng][half * 2] + sbias[col];
                    float v1 = acc[mg][ng][half * 2 + 1] + sbias[col + 1];
                    uint32_t lo;
                    uint32_t hi = pack_hi(v0, v1, lo);
                    uint32_t eoff = (uint32_t)(r * PADK + col) * 2u;
                    *reinterpret_cast<uint32_t*>(sm + OFF_AH + eoff) = hi;
                    *reinterpret_cast<uint32_t*>(sm + OFF_AL + eoff) = lo;
                }
            }
    }
    stage_B(sm, Bh2, Bl2, tid);
    __syncthreads();

#pragma unroll
    for (int mg = 0; mg < 2; mg++)
#pragma unroll
        for (int ng = 0; ng < 4; ng++)
#pragma unroll
            for (int q = 0; q < 4; q++) acc[mg][ng][q] = 0.f;

    mma_mainloop(sb, wm, wn, lane, acc);

    int rbase = row0 + wm + (lane >> 2);
    int cbase = wn + (lane & 3) * 2;
#pragma unroll
    for (int mg = 0; mg < 2; mg++)
#pragma unroll
        for (int half = 0; half < 2; half++) {
            int row = rbase + mg * 16 + half * 8;
            if (row < n) {
#pragma unroll
                for (int ng = 0; ng < 4; ng++) {
                    int col = cbase + ng * 8;
                    float2 o;
                    o.x = acc[mg][ng][half * 2];
                    o.y = acc[mg][ng][half * 2 + 1];
                    *reinterpret_cast<float2*>(&C[(size_t)row * DIM + col]) = o;
                }
            }
        }
}

// ======================= input BN stats (slot 0) ============================
__global__ __launch_bounds__(256) void col_stats_k(const float* __restrict__ x, int n) {
    __shared__ float red[256];
    int tid = threadIdx.x;
    red[tid] = 0.f;
    int w = tid >> 5, lane = tid & 31, c = lane * 4;
    int gw = blockIdx.x * 8 + w;
    const int STR = 512 * 8;
    float4 s = make_float4(0.f, 0.f, 0.f, 0.f);
    float4 q = make_float4(0.f, 0.f, 0.f, 0.f);
    __syncthreads();
    for (int r0 = gw; r0 < n; r0 += STR * 4) {
#pragma unroll
        for (int u = 0; u < 4; u++) {
            int row = r0 + u * STR;
            if (row < n) {
                float4 v = *reinterpret_cast<const float4*>(&x[(size_t)row * DIM + c]);
                s.x += v.x; s.y += v.y; s.z += v.z; s.w += v.w;
                q.x += v.x * v.x; q.y += v.y * v.y; q.z += v.z * v.z; q.w += v.w * v.w;
            }
        }
    }
    atomicAdd(&red[c], s.x);     atomicAdd(&red[c + 1], s.y);
    atomicAdd(&red[c + 2], s.z); atomicAdd(&red[c + 3], s.w);
    __syncthreads();
    __shared__ float redq[128];
    if (tid < 128) redq[tid] = 0.f;
    __syncthreads();
    atomicAdd(&redq[c], q.x);     atomicAdd(&redq[c + 1], q.y);
    atomicAdd(&redq[c + 2], q.z); atomicAdd(&redq[c + 3], q.w);
    __syncthreads();
    if (tid < 128) {
        atomicAdd(&g_cs[0][tid], red[tid]);
        atomicAdd(&g_cq[0][tid], redq[tid]);
    }
}

__global__ void fold_bn_k(const float* __restrict__ W, const float* __restrict__ b,
                          const float* __restrict__ gamma, const float* __restrict__ beta,
                          float n_inv) {
    int j = threadIdx.x;
    __shared__ float sc[DIM], sh[DIM];
    float mu = g_cs[0][j] * n_inv;
    float var = g_cq[0][j] * n_inv - mu * mu;
    float s = gamma[j] * rsqrtf(var + 1e-5f);
    sc[j] = s;
    sh[j] = beta[j] - mu * s;
    __syncthreads();
    float acc = b[j];
    for (int d = 0; d < DIM; d++) {
        float w = W[d * DIM + j];
        g_wfold[d * DIM + j] = sc[d] * w;
        acc += sh[d] * w;
    }
    g_bfold[j] = acc;
}

__global__ void wconvert_k(const float* __restrict__ gc_w) {
    int i = blockIdx.x * 256 + threadIdx.x;
    if (i >= 5 * DIM * DIM) return;
    float v = (i < DIM * DIM) ? g_wfold[i] : gc_w[i - DIM * DIM];
    __nv_bfloat16 h = __float2bfloat16(v);
    g_bwh[i] = h;
    g_bwl[i] = __float2bfloat16(v - __bfloat162float(h));
}

// ======================= CSR build ==========================================
// hist ALSO zeroes stats slot 0 (block 0) — col_stats_k accumulates into it
// with atomics, so it must be reset every call (replay-safety invariant).
__global__ void hist_k(const int* __restrict__ er, int e) {
    int i = blockIdx.x * blockDim.x + threadIdx.x;
    if (blockIdx.x == 0 && threadIdx.x < DIM) {
        g_cs[0][threadIdx.x] = 0.f;
        g_cq[0][threadIdx.x] = 0.f;
    }
    if (i < e) atomicAdd(&g_cnt[er[i]], 1);
}

// two-level scan: block sums -> scan of partials -> apply
__global__ __launch_bounds__(256) void scan1_k(int n) {
    __shared__ int red[256];
    int tid = threadIdx.x;
    int i = blockIdx.x * 256 + tid;
    red[tid] = (i < n) ? g_cnt[i] : 0;
    __syncthreads();
    for (int off = 128; off > 0; off >>= 1) {
        if (tid < off) red[tid] += red[tid + off];
        __syncthreads();
    }
    if (tid == 0) g_bsum[blockIdx.x] = red[0];
}

__global__ __launch_bounds__(256) void scan2_k(int n, int nblk) {
    __shared__ int s[256];
    int tid = threadIdx.x;
    int v = (tid < nblk) ? g_bsum[tid] : 0;
    s[tid] = v;
    __syncthreads();
    for (int off = 1; off < 256; off <<= 1) {
        int t = (tid >= off) ? s[tid - off] : 0;
        __syncthreads();
        s[tid] += t;
        __syncthreads();
    }
    g_boff[tid] = s[tid] - v;
    if (tid == 255) g_rowptr[n] = s[255];
}

__global__ __launch_bounds__(256) void scan3_k(int n) {
    __shared__ int s[256];
    int tid = threadIdx.x;
    int i = blockIdx.x * 256 + tid;
    int v = (i < n) ? g_cnt[i] : 0;
    s[tid] = v;
    __syncthreads();
    for (int off = 1; off < 256; off <<= 1) {
        int t = (tid >= off) ? s[tid - off] : 0;
        __syncthreads();
        s[tid] += t;
        __syncthreads();
    }
    if (i < n) {
        int excl = s[tid] - v + g_boff[blockIdx.x];
        g_rowptr[i] = excl;
        g_wcur[i] = excl;
        g_cnt[i] = 0;      // restore zero invariant for next replay
    }
}

__global__ void scatter_k(const int* __restrict__ er, const int* __restrict__ ec,
                          const float* __restrict__ ev, int e) {
    int i = blockIdx.x * blockDim.x + threadIdx.x;
    if (i < e) {
        int r = er[i];
        int pos = atomicAdd(&g_wcur[r], 1);
        g_colidx[pos] = ec[i];
        g_vals[pos] = ev[i];
    }
}

// ======================= SPMM + fused PairNorm stats ========================
__global__ __launch_bounds__(256) void spmm_k(
    const float* __restrict__ g, const float* __restrict__ bias,
    float* __restrict__ h, int n, int slot) {
    __shared__ float red[256];   // [0:128) sum, [128:256) sumsq
    int tid = threadIdx.x;
    red[tid] = 0.f;
    int w = tid >> 5, lane = tid & 31;
    int gw = blockIdx.x * 8 + w;
    int c = lane * 4;
    float4 b4 = *reinterpret_cast<const float4*>(&bias[c]);
    float4 ssum = make_float4(0.f, 0.f, 0.f, 0.f);
    float4 ssq = make_float4(0.f, 0.f, 0.f, 0.f);
    __syncthreads();
#pragma unroll
    for (int rr = 0; rr < 4; rr++) {
        int row = gw * 4 + rr;
        if (row >= n) break;
        int s = g_rowptr[row];
        int e = g_rowptr[row + 1];
        float4 acc = make_float4(0.f, 0.f, 0.f, 0.f);
        int i = s;
        for (; i + 3 < e; i += 4) {
            int c0 = g_colidx[i], c1 = g_colidx[i + 1];
            int c2 = g_colidx[i + 2], c3 = g_colidx[i + 3];
            float v0 = g_vals[i], v1 = g_vals[i + 1];
            float v2 = g_vals[i + 2], v3 = g_vals[i + 3];
            float4 a0 = *reinterpret_cast<const float4*>(&g[(size_t)c0 * DIM + c]);
            float4 a1 = *reinterpret_cast<const float4*>(&g[(size_t)c1 * DIM + c]);
            float4 a2 = *reinterpret_cast<const float4*>(&g[(size_t)c2 * DIM + c]);
            float4 a3 = *reinterpret_cast<const float4*>(&g[(size_t)c3 * DIM + c]);
            acc.x += v0 * a0.x + v1 * a1.x + v2 * a2.x + v3 * a3.x;
            acc.y += v0 * a0.y + v1 * a1.y + v2 * a2.y + v3 * a3.y;
            acc.z += v0 * a0.z + v1 * a1.z + v2 * a2.z + v3 * a3.z;
            acc.w += v0 * a0.w + v1 * a1.w + v2 * a2.w + v3 * a3.w;
        }
        for (; i < e; i++) {
            int c0 = g_colidx[i];
            float v0 = g_vals[i];
            float4 a0 = *reinterpret_cast<const float4*>(&g[(size_t)c0 * DIM + c]);
            acc.x += v0 * a0.x; acc.y += v0 * a0.y; acc.z += v0 * a0.z; acc.w += v0 * a0.w;
        }
        acc.x += b4.x; acc.y += b4.y; acc.z += b4.z; acc.w += b4.w;
        *reinterpret_cast<float4*>(&h[(size_t)row * DIM + c]) = acc;
        ssum.x += acc.x; ssum.y += acc.y; ssum.z += acc.z; ssum.w += acc.w;
        ssq.x += acc.x * acc.x; ssq.y += acc.y * acc.y;
        ssq.z += acc.z * acc.z; ssq.w += acc.w * acc.w;
    }
    atomicAdd(&red[c], ssum.x);     atomicAdd(&red[c + 1], ssum.y);
    atomicAdd(&red[c + 2], ssum.z); atomicAdd(&red[c + 3], ssum.w);
    atomicAdd(&red[128 + c], ssq.x);     atomicAdd(&red[128 + c + 1], ssq.y);
    atomicAdd(&red[128 + c + 2], ssq.z); atomicAdd(&red[128 + c + 3], ssq.w);
    __syncthreads();
    if (tid < 128) atomicAdd(&g_cs[slot][tid], red[tid]);
    else atomicAdd(&g_cq[slot][tid - 128], red[tid]);
}

// ======================= output GEMM + fused final PairNorm =================
__global__ __launch_bounds__(256) void gemm_out_k(
    const float* __restrict__ H, const float* __restrict__ Xold,
    const float* __restrict__ W, const float* __restrict__ b,
    float* __restrict__ out, int n, int pn_slot, float n_inv) {
    __shared__ float sx[32 * DIM];
    __shared__ float sw[DIM * CDIM];
    __shared__ float smu[DIM];
    __shared__ float red[DIM];
    int tid = threadIdx.x;
    int row0 = blockIdx.x * 32;
    for (int i = tid; i < DIM * CDIM; i += 256) sw[i] = W[i];
    if (tid < DIM) {
        float mu = g_cs[pn_slot][tid] * n_inv;
        smu[tid] = mu;
        red[tid] = g_cq[pn_slot][tid] * n_inv - mu * mu;
    }
    __syncthreads();
    for (int off = 64; off > 0; off >>= 1) {
        if (tid < off) red[tid] += red[tid + off];
        __syncthreads();
    }
    if (tid == 0) red[0] = rsqrtf(1e-6f + red[0]);
    __syncthreads();
    float s = red[0];
#pragma unroll
    for (int q = 0; q < 4; q++) {
        int flat = (q * 256 + tid) * 4;
        int r = flat >> 7, c = flat & 127;
        int row = row0 + r;
        float4 v = make_float4(0.f, 0.f, 0.f, 0.f);
        if (row < n) {
            float4 hv = *reinterpret_cast<const float4*>(&H[(size_t)row * DIM + c]);
            float4 m = *reinterpret_cast<const float4*>(&smu[c]);
            float4 xo = *reinterpret_cast<const float4*>(&Xold[(size_t)row * DIM + c]);
            v.x = fmaxf((hv.x - m.x) * s, 0.f) + xo.x;
            v.y = fmaxf((hv.y - m.y) * s, 0.f) + xo.y;
            v.z = fmaxf((hv.z - m.z) * s, 0.f) + xo.z;
            v.w = fmaxf((hv.w - m.w) * s, 0.f) + xo.w;
        }
        *reinterpret_cast<float4*>(&sx[flat]) = v;
    }
    __syncthreads();
    int r = tid >> 3;
    int c0 = (tid & 7) * 5;
    float acc[5];
#pragma unroll
    for (int j = 0; j < 5; j++) acc[j] = b[c0 + j];
#pragma unroll 4
    for (int k = 0; k < DIM; k++) {
        float xv = sx[r * DIM + k];
#pragma unroll
        for (int j = 0; j < 5; j++) acc[j] += xv * sw[k * CDIM + c0 + j];
    }
    if (row0 + r < n) {
#pragma unroll
        for (int j = 0; j < 5; j++) out[(size_t)(row0 + r) * CDIM + c0 + j] = acc[j];
    }
}

// ======================= launch =============================================
extern "C" void kernel_launch(void* const* d_in, const int* in_sizes, int n_in,
                              void* d_out, int out_size) {
    const float* x      = (const float*)d_in[0];
    const int*   er     = (const int*)d_in[1];
    const int*   ec     = (const int*)d_in[2];
    const float* ev     = (const float*)d_in[3];
    const float* gamma  = (const float*)d_in[4];
    const float* beta   = (const float*)d_in[5];
    const float* fin_w  = (const float*)d_in[6];
    const float* fin_b  = (const float*)d_in[7];
    const float* gc_w   = (const float*)d_in[8];
    const float* gc_b   = (const float*)d_in[9];
    const float* fout_w = (const float*)d_in[10];
    const float* fout_b = (const float*)d_in[11];
    float* out = (float*)d_out;

    int n = in_sizes[0] / DIM;
    int e = in_sizes[1];
    float n_inv = 1.0f / (float)n;

    float *xbuf, *gbuf, *hbuf, *bfold;
    __nv_bfloat16 *bwh, *bwl;
    cudaGetSymbolAddress((void**)&xbuf, g_xbuf);
    cudaGetSymbolAddress((void**)&gbuf, g_gbuf);
    cudaGetSymbolAddress((void**)&hbuf, g_hbuf);
    cudaGetSymbolAddress((void**)&bfold, g_bfold);
    cudaGetSymbolAddress((void**)&bwh, g_bwh);
    cudaGetSymbolAddress((void**)&bwl, g_bwl);

    cudaFuncSetAttribute(gemm_mma_k, cudaFuncAttributeMaxDynamicSharedMemorySize, GEMM_SMEM_BYTES);
    cudaFuncSetAttribute(gemm_fused_k, cudaFuncAttributeMaxDynamicSharedMemorySize, GEMM_SMEM_BYTES);

    int gblocks = (n + 127) / 128;
    int sblocks = (n + 31) / 32;
    int nblk = (n + 255) / 256;
    const int WMAT = DIM * DIM;

    // ---- CSR build (two-level scan); hist zeroes stats slot 0 ----
    hist_k<<<(e + 255) / 256, 256>>>(er, e);
    scan1_k<<<nblk, 256>>>(n);
    scan2_k<<<1, 256>>>(n, nblk);
    scan3_k<<<nblk, 256>>>(n);
    scatter_k<<<(e + 255) / 256, 256>>>(er, ec, ev, e);

    // ---- BN stats -> fold -> weight pre-split ----
    col_stats_k<<<512, 256>>>(x, n);
    fold_bn_k<<<1, DIM>>>(fin_w, fin_b, gamma, beta, n_inv);
    wconvert_k<<<(5 * WMAT + 255) / 256, 256>>>(gc_w);

    // ---- fused fc_in + layer-0 GEMM (re-zeroes slot0 for layer-0 spmm) ----
    gemm_fused_k<<<gblocks, 512, GEMM_SMEM_BYTES>>>(
        x, bwh, bwl, bwh + WMAT, bwl + WMAT, bfold, gbuf, n);
    spmm_k<<<sblocks, 256>>>(gbuf, gc_b + 0 * DIM, hbuf, n, 0);

    // ---- layers 1..3: GEMM with fused PairNorm-apply on A ----
    // gemm layer i consumes slot[(i-1)&1], zeroes slot[i&1], addold = (i>=2)
    for (int i = 1; i < NLAYER; i++) {
        gemm_mma_k<<<gblocks, 512, GEMM_SMEM_BYTES>>>(
            hbuf, xbuf, xbuf, bwh + (i + 1) * WMAT, bwl + (i + 1) * WMAT,
            gbuf, n, (i - 1) & 1, i & 1, (i >= 2) ? 1 : 0, n_inv);
        spmm_k<<<sblocks, 256>>>(gbuf, gc_b + i * DIM, hbuf, n, i & 1);
    }

    // ---- output projection with fused final PairNorm (slot 1, addold) ----
    gemm_out_k<<<sblocks, 256>>>(hbuf, xbuf, fout_w, fout_b, out, n, (NLAYER - 1) & 1, n_inv);
}

// round 8
// speedup vs baseline: 1.7718x; 1.0132x over previous
#include <cuda_runtime.h>
#include <cuda_bf16.h>
#include <cstdint>

#define DIM 128
#define CDIM 40
#define NLAYER 4
#define NMAX 50000
#define EMAX 800000
#define NSM 148

// ---------------- device scratch (static: no allocations allowed) ----------
__device__ float g_xbuf[NMAX * DIM];
__device__ float g_gbuf[NMAX * DIM];
__device__ float g_hbuf[NMAX * DIM];
__device__ float g_bfold[DIM];
__device__ float g_cs[2][DIM];     // column sums   (parity slots)
__device__ float g_cq[2][DIM];     // column sumsq  (parity slots)
__device__ __nv_bfloat16 g_bwh[5 * DIM * DIM];  // weight hi parts (wfold, gc_w0..3)
__device__ __nv_bfloat16 g_bwl[5 * DIM * DIM];  // weight lo parts
__device__ int   g_rowptr[NMAX + 1];
__device__ int   g_cnt[NMAX];      // zero-initialized; invariant: zero between replays
__device__ int   g_wcur[NMAX];
__device__ int   g_bsum[256];
__device__ int   g_boff[256];
__device__ int2  g_edge[EMAX];     // (colidx, val-bits) packed

// ======================= helpers ===========================================
__device__ __forceinline__ uint32_t smem_u32(const void* p) {
    uint32_t a;
    asm("{ .reg .u64 t; cvta.to.shared.u64 t, %1; cvt.u32.u64 %0, t; }" : "=r"(a) : "l"(p));
    return a;
}
__device__ __forceinline__ void ldm_x4(uint32_t* r, uint32_t addr) {
    asm volatile("ldmatrix.sync.aligned.m8n8.x4.shared.b16 {%0,%1,%2,%3}, [%4];"
                 : "=r"(r[0]), "=r"(r[1]), "=r"(r[2]), "=r"(r[3]) : "r"(addr));
}
__device__ __forceinline__ void ldm_x4_t(uint32_t* r, uint32_t addr) {
    asm volatile("ldmatrix.sync.aligned.m8n8.x4.trans.shared.b16 {%0,%1,%2,%3}, [%4];"
                 : "=r"(r[0]), "=r"(r[1]), "=r"(r[2]), "=r"(r[3]) : "r"(addr));
}
__device__ __forceinline__ void mma_bf16(float* c, const uint32_t* a, const uint32_t* b) {
    asm volatile(
        "mma.sync.aligned.m16n8k16.row.col.f32.bf16.bf16.f32 "
        "{%0,%1,%2,%3}, {%4,%5,%6,%7}, {%8,%9}, {%0,%1,%2,%3};"
        : "+f"(c[0]), "+f"(c[1]), "+f"(c[2]), "+f"(c[3])
        : "r"(a[0]), "r"(a[1]), "r"(a[2]), "r"(a[3]), "r"(b[0]), "r"(b[1]));
}
__device__ __forceinline__ uint32_t pack_hi(float x, float y, uint32_t& lo) {
    __nv_bfloat16 hx = __float2bfloat16(x);
    __nv_bfloat16 hy = __float2bfloat16(y);
    __nv_bfloat16 lx = __float2bfloat16(x - __bfloat162float(hx));
    __nv_bfloat16 ly = __float2bfloat16(y - __bfloat162float(hy));
    lo = (uint32_t)__bfloat16_as_ushort(lx) | ((uint32_t)__bfloat16_as_ushort(ly) << 16);
    return (uint32_t)__bfloat16_as_ushort(hx) | ((uint32_t)__bfloat16_as_ushort(hy) << 16);
}

// ======================= GEMM common pieces =================================
// 512 threads / 16 warps, warp grid 4x4, warp tile m32 x n32. Persistent blocks.
// fp32 accuracy via bf16 hi/lo split: D = Ah*Bh + Ah*Bl + Al*Bh.
#define PADK 136
#define TILE_B (128 * PADK * 2)           // 34816 bytes per bf16 tile
#define OFF_AH 0
#define OFF_AL TILE_B
#define OFF_B1H (2 * TILE_B)
#define OFF_B1L (3 * TILE_B)
#define OFF_B2H (4 * TILE_B)
#define OFF_B2L (5 * TILE_B)
#define GEMM_SMEM_BYTES  (4 * TILE_B + 2048)
#define FUSED_SMEM_BYTES (6 * TILE_B + 2048)

__device__ __forceinline__ void mma_mainloop(uint32_t sb, int bOffH, int bOffL,
                                             int wm, int wn, int lane,
                                             float acc[2][4][4]) {
    int lrow = lane & 15;
    int lcol8 = (lane >> 4) << 3;
#pragma unroll
    for (int t = 0; t < 3; t++) {
        uint32_t aBase = sb + ((t == 2) ? OFF_AL : OFF_AH);
        uint32_t bBase = sb + ((t == 1) ? bOffL : bOffH);
#pragma unroll
        for (int k0 = 0; k0 < 128; k0 += 16) {
            uint32_t a[2][4];
#pragma unroll
            for (int mg = 0; mg < 2; mg++)
                ldm_x4(a[mg], aBase + (uint32_t)((wm + mg * 16 + lrow) * PADK + k0 + lcol8) * 2u);
            uint32_t b[2][4];
#pragma unroll
            for (int nc = 0; nc < 2; nc++)
                ldm_x4_t(b[nc], bBase + (uint32_t)((k0 + lrow) * PADK + wn + nc * 16 + lcol8) * 2u);
#pragma unroll
            for (int mg = 0; mg < 2; mg++)
#pragma unroll
                for (int ng = 0; ng < 4; ng++)
                    mma_bf16(acc[mg][ng], a[mg], &b[ng >> 1][(ng & 1) * 2]);
        }
    }
}

__device__ __forceinline__ void stage_B(char* sm, int offH, int offL,
                                        const __nv_bfloat16* Bh,
                                        const __nv_bfloat16* Bl, int tid) {
    for (int g = tid; g < 2048; g += 512) {
        int r = g >> 4;
        int c = (g & 15) * 8;
        uint4 vh = reinterpret_cast<const uint4*>(Bh)[g];
        uint4 vl = reinterpret_cast<const uint4*>(Bl)[g];
        uint32_t eoff = (uint32_t)(r * PADK + c) * 2u;
        *reinterpret_cast<uint4*>(sm + offH + eoff) = vh;
        *reinterpret_cast<uint4*>(sm + offL + eoff) = vl;
    }
}

// ======================= main GEMM (persistent, fused PairNorm on A) ========
__global__ __launch_bounds__(512) void gemm_mma_k(
    const float* __restrict__ A, const float* __restrict__ Xold,
    float* __restrict__ Xwrite,
    const __nv_bfloat16* __restrict__ Bh, const __nv_bfloat16* __restrict__ Bl,
    float* __restrict__ C, int n,
    int pn_slot, int zero_slot, int addold, float n_inv) {
    extern __shared__ char sm[];
    float* smu = reinterpret_cast<float*>(sm + 4 * TILE_B);
    float* red = smu + DIM;
    uint32_t sb = smem_u32(sm);
    int tid = threadIdx.x, wid = tid >> 5, lane = tid & 31;

    if (zero_slot >= 0 && blockIdx.x == 0 && tid < DIM) {
        g_cs[zero_slot][tid] = 0.f;
        g_cq[zero_slot][tid] = 0.f;
    }

    float pscale = 0.f;
    if (pn_slot >= 0) {
        if (tid < DIM) {
            float mu = g_cs[pn_slot][tid] * n_inv;
            smu[tid] = mu;
            red[tid] = g_cq[pn_slot][tid] * n_inv - mu * mu;
        }
        __syncthreads();
        for (int off = 64; off > 0; off >>= 1) {
            if (tid < off) red[tid] += red[tid + off];
            __syncthreads();
        }
        if (tid == 0) red[0] = rsqrtf(1e-6f + red[0]);
        __syncthreads();
        pscale = red[0];
    }

    int T = (n + 127) >> 7;
    int t = blockIdx.x;
    if (t >= T) return;

    stage_B(sm, OFF_B1H, OFF_B1L, Bh, Bl, tid);

    // stage first tile A (load + PN + split)
    {
        int row0 = t * 128;
        for (int g = tid; g < 4096; g += 512) {
            int r = g >> 5, c = (g & 31) * 4;
            int row = row0 + r;
            float4 av = make_float4(0.f, 0.f, 0.f, 0.f);
            if (row < n) {
                av = *reinterpret_cast<const float4*>(&A[(size_t)row * DIM + c]);
                if (pn_slot >= 0) {
                    float4 m = *reinterpret_cast<const float4*>(&smu[c]);
                    av.x = fmaxf((av.x - m.x) * pscale, 0.f);
                    av.y = fmaxf((av.y - m.y) * pscale, 0.f);
                    av.z = fmaxf((av.z - m.z) * pscale, 0.f);
                    av.w = fmaxf((av.w - m.w) * pscale, 0.f);
                    if (addold) {
                        float4 xo = *reinterpret_cast<const float4*>(&Xold[(size_t)row * DIM + c]);
                        av.x += xo.x; av.y += xo.y; av.z += xo.z; av.w += xo.w;
                    }
                    if (Xwrite)
                        *reinterpret_cast<float4*>(&Xwrite[(size_t)row * DIM + c]) = av;
                }
            }
            uint32_t eoff = (uint32_t)(r * PADK + c) * 2u;
            uint32_t al0, al1;
            uint32_t ah0 = pack_hi(av.x, av.y, al0);
            uint32_t ah1 = pack_hi(av.z, av.w, al1);
            *reinterpret_cast<uint2*>(sm + OFF_AH + eoff) = make_uint2(ah0, ah1);
            *reinterpret_cast<uint2*>(sm + OFF_AL + eoff) = make_uint2(al0, al1);
        }
    }
    __syncthreads();

    int wm = (wid & 3) * 32;
    int wn = (wid >> 2) * 32;

    while (true) {
        int tn = t + gridDim.x;
        bool hn = tn < T;
        float4 raw[8];
        if (hn) {                       // prefetch next tile's A during mma
            int row0n = tn * 128;
#pragma unroll
            for (int q = 0; q < 8; q++) {
                int g = q * 512 + tid;
                int r = g >> 5, c = (g & 31) * 4;
                int row = row0n + r;
                raw[q] = (row < n)
                    ? *reinterpret_cast<const float4*>(&A[(size_t)row * DIM + c])
                    : make_float4(0.f, 0.f, 0.f, 0.f);
            }
        }

        float acc[2][4][4];
#pragma unroll
        for (int mg = 0; mg < 2; mg++)
#pragma unroll
            for (int ng = 0; ng < 4; ng++)
#pragma unroll
                for (int q = 0; q < 4; q++) acc[mg][ng][q] = 0.f;

        mma_mainloop(sb, OFF_B1H, OFF_B1L, wm, wn, lane, acc);

        int row0 = t * 128;
        int rbase = row0 + wm + (lane >> 2);
        int cbase = wn + (lane & 3) * 2;
#pragma unroll
        for (int mg = 0; mg < 2; mg++)
#pragma unroll
            for (int half = 0; half < 2; half++) {
                int row = rbase + mg * 16 + half * 8;
                if (row < n) {
#pragma unroll
                    for (int ng = 0; ng < 4; ng++) {
                        int col = cbase + ng * 8;
                        float2 o;
                        o.x = acc[mg][ng][half * 2];
                        o.y = acc[mg][ng][half * 2 + 1];
                        *reinterpret_cast<float2*>(&C[(size_t)row * DIM + col]) = o;
                    }
                }
            }

        if (!hn) break;
        __syncthreads();
        // convert prefetched tile into A smem (+PN +residual +writeback)
        {
            int row0n = tn * 128;
#pragma unroll
            for (int q = 0; q < 8; q++) {
                int g = q * 512 + tid;
                int r = g >> 5, c = (g & 31) * 4;
                int row = row0n + r;
                float4 av = raw[q];
                if (pn_slot >= 0 && row < n) {
                    float4 m = *reinterpret_cast<const float4*>(&smu[c]);
                    av.x = fmaxf((av.x - m.x) * pscale, 0.f);
                    av.y = fmaxf((av.y - m.y) * pscale, 0.f);
                    av.z = fmaxf((av.z - m.z) * pscale, 0.f);
                    av.w = fmaxf((av.w - m.w) * pscale, 0.f);
                    if (addold) {
                        float4 xo = *reinterpret_cast<const float4*>(&Xold[(size_t)row * DIM + c]);
                        av.x += xo.x; av.y += xo.y; av.z += xo.z; av.w += xo.w;
                    }
                    if (Xwrite)
                        *reinterpret_cast<float4*>(&Xwrite[(size_t)row * DIM + c]) = av;
                }
                uint32_t eoff = (uint32_t)(r * PADK + c) * 2u;
                uint32_t al0, al1;
                uint32_t ah0 = pack_hi(av.x, av.y, al0);
                uint32_t ah1 = pack_hi(av.z, av.w, al1);
                *reinterpret_cast<uint2*>(sm + OFF_AH + eoff) = make_uint2(ah0, ah1);
                *reinterpret_cast<uint2*>(sm + OFF_AL + eoff) = make_uint2(al0, al1);
            }
        }
        __syncthreads();
        t = tn;
    }
}

// ======================= fused fc_in + layer-0 GEMM (persistent) ============
// C = (X @ Wfold + bfold) @ Wgc0 ; B1 and B2 both smem-resident.
__global__ __launch_bounds__(512) void gemm_fused_k(
    const float* __restrict__ X,
    const __nv_bfloat16* __restrict__ B1h, const __nv_bfloat16* __restrict__ B1l,
    const __nv_bfloat16* __restrict__ B2h, const __nv_bfloat16* __restrict__ B2l,
    const float* __restrict__ bias1, float* __restrict__ C, int n) {
    extern __shared__ char sm[];
    float* sbias = reinterpret_cast<float*>(sm + 6 * TILE_B);
    uint32_t sb = smem_u32(sm);
    int tid = threadIdx.x, wid = tid >> 5, lane = tid & 31;

    if (blockIdx.x == 0 && tid < DIM) {
        g_cs[0][tid] = 0.f;
        g_cq[0][tid] = 0.f;
    }
    if (tid < DIM) sbias[tid] = bias1[tid];

    int T = (n + 127) >> 7;
    int t = blockIdx.x;
    if (t >= T) return;

    stage_B(sm, OFF_B1H, OFF_B1L, B1h, B1l, tid);
    stage_B(sm, OFF_B2H, OFF_B2L, B2h, B2l, tid);

    // stage first tile
    {
        int row0 = t * 128;
        for (int g = tid; g < 4096; g += 512) {
            int r = g >> 5, c = (g & 31) * 4;
            int row = row0 + r;
            float4 av = make_float4(0.f, 0.f, 0.f, 0.f);
            if (row < n) av = *reinterpret_cast<const float4*>(&X[(size_t)row * DIM + c]);
            uint32_t eoff = (uint32_t)(r * PADK + c) * 2u;
            uint32_t al0, al1;
            uint32_t ah0 = pack_hi(av.x, av.y, al0);
            uint32_t ah1 = pack_hi(av.z, av.w, al1);
            *reinterpret_cast<uint2*>(sm + OFF_AH + eoff) = make_uint2(ah0, ah1);
            *reinterpret_cast<uint2*>(sm + OFF_AL + eoff) = make_uint2(al0, al1);
        }
    }
    __syncthreads();

    int wm = (wid & 3) * 32;
    int wn = (wid >> 2) * 32;

    while (true) {
        int tn = t + gridDim.x;
        bool hn = tn < T;
        float4 raw[8];
        if (hn) {
            int row0n = tn * 128;
#pragma unroll
            for (int q = 0; q < 8; q++) {
                int g = q * 512 + tid;
                int r = g >> 5, c = (g & 31) * 4;
                int row = row0n + r;
                raw[q] = (row < n)
                    ? *reinterpret_cast<const float4*>(&X[(size_t)row * DIM + c])
                    : make_float4(0.f, 0.f, 0.f, 0.f);
            }
        }

        float acc[2][4][4];
#pragma unroll
        for (int mg = 0; mg < 2; mg++)
#pragma unroll
            for (int ng = 0; ng < 4; ng++)
#pragma unroll
                for (int q = 0; q < 4; q++) acc[mg][ng][q] = 0.f;

        mma_mainloop(sb, OFF_B1H, OFF_B1L, wm, wn, lane, acc);
        __syncthreads();   // all warps done reading A tile

        // write intermediate (acc + bias) back into A smem as bf16 hi/lo
        {
            int rl = wm + (lane >> 2);
            int cb = wn + (lane & 3) * 2;
#pragma unroll
            for (int mg = 0; mg < 2; mg++)
#pragma unroll
                for (int half = 0; half < 2; half++) {
                    int r = rl + mg * 16 + half * 8;
#pragma unroll
                    for (int ng = 0; ng < 4; ng++) {
                        int col = cb + ng * 8;
                        float v0 = acc[mg][ng][half * 2] + sbias[col];
                        float v1 = acc[mg][ng][half * 2 + 1] + sbias[col + 1];
                        uint32_t lo;
                        uint32_t hi = pack_hi(v0, v1, lo);
                        uint32_t eoff = (uint32_t)(r * PADK + col) * 2u;
                        *reinterpret_cast<uint32_t*>(sm + OFF_AH + eoff) = hi;
                        *reinterpret_cast<uint32_t*>(sm + OFF_AL + eoff) = lo;
                    }
                }
        }
        __syncthreads();

#pragma unroll
        for (int mg = 0; mg < 2; mg++)
#pragma unroll
            for (int ng = 0; ng < 4; ng++)
#pragma unroll
                for (int q = 0; q < 4; q++) acc[mg][ng][q] = 0.f;

        mma_mainloop(sb, OFF_B2H, OFF_B2L, wm, wn, lane, acc);

        int row0 = t * 128;
        int rbase = row0 + wm + (lane >> 2);
        int cbase = wn + (lane & 3) * 2;
#pragma unroll
        for (int mg = 0; mg < 2; mg++)
#pragma unroll
            for (int half = 0; half < 2; half++) {
                int row = rbase + mg * 16 + half * 8;
                if (row < n) {
#pragma unroll
                    for (int ng = 0; ng < 4; ng++) {
                        int col = cbase + ng * 8;
                        float2 o;
                        o.x = acc[mg][ng][half * 2];
                        o.y = acc[mg][ng][half * 2 + 1];
                        *reinterpret_cast<float2*>(&C[(size_t)row * DIM + col]) = o;
                    }
                }
            }

        if (!hn) break;
        __syncthreads();
        {
            int row0n = tn * 128;
#pragma unroll
            for (int q = 0; q < 8; q++) {
                int g = q * 512 + tid;
                int r = g >> 5, c = (g & 31) * 4;
                float4 av = raw[q];
                uint32_t eoff = (uint32_t)(r * PADK + c) * 2u;
                uint32_t al0, al1;
                uint32_t ah0 = pack_hi(av.x, av.y, al0);
                uint32_t ah1 = pack_hi(av.z, av.w, al1);
                *reinterpret_cast<uint2*>(sm + OFF_AH + eoff) = make_uint2(ah0, ah1);
                *reinterpret_cast<uint2*>(sm + OFF_AL + eoff) = make_uint2(al0, al1);
                (void)row0n;
            }
        }
        __syncthreads();
        t = tn;
    }
}

// ======================= input BN stats (slot 0) ============================
__global__ __launch_bounds__(256) void col_stats_k(const float* __restrict__ x, int n) {
    __shared__ float red[256];
    int tid = threadIdx.x;
    red[tid] = 0.f;
    int w = tid >> 5, lane = tid & 31, c = lane * 4;
    int gw = blockIdx.x * 8 + w;
    const int STR = 512 * 8;
    float4 s = make_float4(0.f, 0.f, 0.f, 0.f);
    float4 q = make_float4(0.f, 0.f, 0.f, 0.f);
    __syncthreads();
    for (int r0 = gw; r0 < n; r0 += STR * 4) {
#pragma unroll
        for (int u = 0; u < 4; u++) {
            int row = r0 + u * STR;
            if (row < n) {
                float4 v = *reinterpret_cast<const float4*>(&x[(size_t)row * DIM + c]);
                s.x += v.x; s.y += v.y; s.z += v.z; s.w += v.w;
                q.x += v.x * v.x; q.y += v.y * v.y; q.z += v.z * v.z; q.w += v.w * v.w;
            }
        }
    }
    atomicAdd(&red[c], s.x);     atomicAdd(&red[c + 1], s.y);
    atomicAdd(&red[c + 2], s.z); atomicAdd(&red[c + 3], s.w);
    __syncthreads();
    __shared__ float redq[128];
    if (tid < 128) redq[tid] = 0.f;
    __syncthreads();
    atomicAdd(&redq[c], q.x);     atomicAdd(&redq[c + 1], q.y);
    atomicAdd(&redq[c + 2], q.z); atomicAdd(&redq[c + 3], q.w);
    __syncthreads();
    if (tid < 128) {
        atomicAdd(&g_cs[0][tid], red[tid]);
        atomicAdd(&g_cq[0][tid], redq[tid]);
    }
}

// ======================= BN fold + weight pre-split (merged) ================
// Block 0: folds BatchNorm into fc_in and emits its bf16 hi/lo split + bias.
// Blocks 1..: split the 4 gc_w matrices.
__global__ __launch_bounds__(256) void wconvert_fold_k(
    const float* __restrict__ fin_w, const float* __restrict__ fin_b,
    const float* __restrict__ gamma, const float* __restrict__ beta,
    const float* __restrict__ gc_w, float n_inv) {
    const int WMAT = DIM * DIM;
    if (blockIdx.x == 0) {
        __shared__ float sc[DIM], sh[DIM];
        int j = threadIdx.x;
        if (j < DIM) {
            float mu = g_cs[0][j] * n_inv;
            float var = g_cq[0][j] * n_inv - mu * mu;
            float s = gamma[j] * rsqrtf(var + 1e-5f);
            sc[j] = s;
            sh[j] = beta[j] - mu * s;
        }
        __syncthreads();
        if (j < DIM) {
            float acc = fin_b[j];
            for (int d = 0; d < DIM; d++) {
                float w = fin_w[d * DIM + j];
                acc += sh[d] * w;
                float wf = sc[d] * w;
                __nv_bfloat16 h = __float2bfloat16(wf);
                g_bwh[d * DIM + j] = h;
                g_bwl[d * DIM + j] = __float2bfloat16(wf - __bfloat162float(h));
            }
            g_bfold[j] = acc;
        }
    } else {
        int i = (blockIdx.x - 1) * 256 + threadIdx.x;
        if (i < 4 * WMAT) {
            float v = gc_w[i];
            __nv_bfloat16 h = __float2bfloat16(v);
            g_bwh[WMAT + i] = h;
            g_bwl[WMAT + i] = __float2bfloat16(v - __bfloat162float(h));
        }
    }
}

// ======================= CSR build ==========================================
// hist ALSO zeroes stats slot 0 (block 0) — replay-safety invariant.
__global__ void hist_k(const int* __restrict__ er, int e) {
    int i = blockIdx.x * blockDim.x + threadIdx.x;
    if (blockIdx.x == 0 && threadIdx.x < DIM) {
        g_cs[0][threadIdx.x] = 0.f;
        g_cq[0][threadIdx.x] = 0.f;
    }
    if (i < e) atomicAdd(&g_cnt[er[i]], 1);
}

__global__ __launch_bounds__(256) void scan1_k(int n) {
    __shared__ int red[256];
    int tid = threadIdx.x;
    int i = blockIdx.x * 256 + tid;
    red[tid] = (i < n) ? g_cnt[i] : 0;
    __syncthreads();
    for (int off = 128; off > 0; off >>= 1) {
        if (tid < off) red[tid] += red[tid + off];
        __syncthreads();
    }
    if (tid == 0) g_bsum[blockIdx.x] = red[0];
}

__global__ __launch_bounds__(256) void scan2_k(int n, int nblk) {
    __shared__ int s[256];
    int tid = threadIdx.x;
    int v = (tid < nblk) ? g_bsum[tid] : 0;
    s[tid] = v;
    __syncthreads();
    for (int off = 1; off < 256; off <<= 1) {
        int t = (tid >= off) ? s[tid - off] : 0;
        __syncthreads();
        s[tid] += t;
        __syncthreads();
    }
    g_boff[tid] = s[tid] - v;
    if (tid == 255) g_rowptr[n] = s[255];
}

__global__ __launch_bounds__(256) void scan3_k(int n) {
    __shared__ int s[256];
    int tid = threadIdx.x;
    int i = blockIdx.x * 256 + tid;
    int v = (i < n) ? g_cnt[i] : 0;
    s[tid] = v;
    __syncthreads();
    for (int off = 1; off < 256; off <<= 1) {
        int t = (tid >= off) ? s[tid - off] : 0;
        __syncthreads();
        s[tid] += t;
        __syncthreads();
    }
    if (i < n) {
        int excl = s[tid] - v + g_boff[blockIdx.x];
        g_rowptr[i] = excl;
        g_wcur[i] = excl;
        g_cnt[i] = 0;      // restore zero invariant for next replay
    }
}

__global__ void scatter_k(const int* __restrict__ er, const int* __restrict__ ec,
                          const float* __restrict__ ev, int e) {
    int i = blockIdx.x * blockDim.x + threadIdx.x;
    if (i < e) {
        int r = er[i];
        int pos = atomicAdd(&g_wcur[r], 1);
        g_edge[pos] = make_int2(ec[i], __float_as_int(ev[i]));
    }
}

// ======================= SPMM + fused PairNorm stats ========================
__global__ __launch_bounds__(256) void spmm_k(
    const float* __restrict__ g, const float* __restrict__ bias,
    float* __restrict__ h, int n, int slot) {
    __shared__ float red[256];   // [0:128) sum, [128:256) sumsq
    int tid = threadIdx.x;
    red[tid] = 0.f;
    int w = tid >> 5, lane = tid & 31;
    int gw = blockIdx.x * 8 + w;
    int c = lane * 4;
    float4 b4 = *reinterpret_cast<const float4*>(&bias[c]);
    float4 ssum = make_float4(0.f, 0.f, 0.f, 0.f);
    float4 ssq = make_float4(0.f, 0.f, 0.f, 0.f);
    __syncthreads();
#pragma unroll
    for (int rr = 0; rr < 4; rr++) {
        int row = gw * 4 + rr;
        if (row >= n) break;
        int s = g_rowptr[row];
        int e = g_rowptr[row + 1];
        float4 acc = make_float4(0.f, 0.f, 0.f, 0.f);
        int i = s;
        for (; i + 7 < e; i += 8) {
            float4 p[8];
            float vv[8];
#pragma unroll
            for (int u = 0; u < 8; u++) {
                int2 ed = g_edge[i + u];
                vv[u] = __int_as_float(ed.y);
                p[u] = *reinterpret_cast<const float4*>(&g[(size_t)ed.x * DIM + c]);
            }
#pragma unroll
            for (int u = 0; u < 8; u++) {
                acc.x += vv[u] * p[u].x;
                acc.y += vv[u] * p[u].y;
                acc.z += vv[u] * p[u].z;
                acc.w += vv[u] * p[u].w;
            }
        }
        for (; i + 1 < e; i += 2) {
            int2 e0 = g_edge[i], e1 = g_edge[i + 1];
            float v0 = __int_as_float(e0.y), v1 = __int_as_float(e1.y);
            float4 a0 = *reinterpret_cast<const float4*>(&g[(size_t)e0.x * DIM + c]);
            float4 a1 = *reinterpret_cast<const float4*>(&g[(size_t)e1.x * DIM + c]);
            acc.x += v0 * a0.x + v1 * a1.x;
            acc.y += v0 * a0.y + v1 * a1.y;
            acc.z += v0 * a0.z + v1 * a1.z;
            acc.w += v0 * a0.w + v1 * a1.w;
        }
        if (i < e) {
            int2 e0 = g_edge[i];
            float v0 = __int_as_float(e0.y);
            float4 a0 = *reinterpret_cast<const float4*>(&g[(size_t)e0.x * DIM + c]);
            acc.x += v0 * a0.x; acc.y += v0 * a0.y; acc.z += v0 * a0.z; acc.w += v0 * a0.w;
        }
        acc.x += b4.x; acc.y += b4.y; acc.z += b4.z; acc.w += b4.w;
        *reinterpret_cast<float4*>(&h[(size_t)row * DIM + c]) = acc;
        ssum.x += acc.x; ssum.y += acc.y; ssum.z += acc.z; ssum.w += acc.w;
        ssq.x += acc.x * acc.x; ssq.y += acc.y * acc.y;
        ssq.z += acc.z * acc.z; ssq.w += acc.w * acc.w;
    }
    atomicAdd(&red[c], ssum.x);     atomicAdd(&red[c + 1], ssum.y);
    atomicAdd(&red[c + 2], ssum.z); atomicAdd(&red[c + 3], ssum.w);
    atomicAdd(&red[128 + c], ssq.x);     atomicAdd(&red[128 + c + 1], ssq.y);
    atomicAdd(&red[128 + c + 2], ssq.z); atomicAdd(&red[128 + c + 3], ssq.w);
    __syncthreads();
    if (tid < 128) atomicAdd(&g_cs[slot][tid], red[tid]);
    else atomicAdd(&g_cq[slot][tid - 128], red[tid]);
}

// ======================= output GEMM + fused final PairNorm =================
__global__ __launch_bounds__(256) void gemm_out_k(
    const float* __restrict__ H, const float* __restrict__ Xold,
    const float* __restrict__ W, const float* __restrict__ b,
    float* __restrict__ out, int n, int pn_slot, float n_inv) {
    __shared__ float sx[32 * DIM];
    __shared__ float sw[DIM * CDIM];
    __shared__ float smu[DIM];
    __shared__ float red[DIM];
    int tid = threadIdx.x;
    int row0 = blockIdx.x * 32;
    for (int i = tid; i < DIM * CDIM; i += 256) sw[i] = W[i];
    if (tid < DIM) {
        float mu = g_cs[pn_slot][tid] * n_inv;
        smu[tid] = mu;
        red[tid] = g_cq[pn_slot][tid] * n_inv - mu * mu;
    }
    __syncthreads();
    for (int off = 64; off > 0; off >>= 1) {
        if (tid < off) red[tid] += red[tid + off];
        __syncthreads();
    }
    if (tid == 0) red[0] = rsqrtf(1e-6f + red[0]);
    __syncthreads();
    float s = red[0];
#pragma unroll
    for (int q = 0; q < 4; q++) {
        int flat = (q * 256 + tid) * 4;
        int r = flat >> 7, c = flat & 127;
        int row = row0 + r;
        float4 v = make_float4(0.f, 0.f, 0.f, 0.f);
        if (row < n) {
            float4 hv = *reinterpret_cast<const float4*>(&H[(size_t)row * DIM + c]);
            float4 m = *reinterpret_cast<const float4*>(&smu[c]);
            float4 xo = *reinterpret_cast<const float4*>(&Xold[(size_t)row * DIM + c]);
            v.x = fmaxf((hv.x - m.x) * s, 0.f) + xo.x;
            v.y = fmaxf((hv.y - m.y) * s, 0.f) + xo.y;
            v.z = fmaxf((hv.z - m.z) * s, 0.f) + xo.z;
            v.w = fmaxf((hv.w - m.w) * s, 0.f) + xo.w;
        }
        *reinterpret_cast<float4*>(&sx[flat]) = v;
    }
    __syncthreads();
    int r = tid >> 3;
    int c0 = (tid & 7) * 5;
    float acc[5];
#pragma unroll
    for (int j = 0; j < 5; j++) acc[j] = b[c0 + j];
#pragma unroll 4
    for (int k = 0; k < DIM; k++) {
        float xv = sx[r * DIM + k];
#pragma unroll
        for (int j = 0; j < 5; j++) acc[j] += xv * sw[k * CDIM + c0 + j];
    }
    if (row0 + r < n) {
#pragma unroll
        for (int j = 0; j < 5; j++) out[(size_t)(row0 + r) * CDIM + c0 + j] = acc[j];
    }
}

// ======================= launch =============================================
extern "C" void kernel_launch(void* const* d_in, const int* in_sizes, int n_in,
                              void* d_out, int out_size) {
    const float* x      = (const float*)d_in[0];
    const int*   er     = (const int*)d_in[1];
    const int*   ec     = (const int*)d_in[2];
    const float* ev     = (const float*)d_in[3];
    const float* gamma  = (const float*)d_in[4];
    const float* beta   = (const float*)d_in[5];
    const float* fin_w  = (const float*)d_in[6];
    const float* fin_b  = (const float*)d_in[7];
    const float* gc_w   = (const float*)d_in[8];
    const float* gc_b   = (const float*)d_in[9];
    const float* fout_w = (const float*)d_in[10];
    const float* fout_b = (const float*)d_in[11];
    float* out = (float*)d_out;

    int n = in_sizes[0] / DIM;
    int e = in_sizes[1];
    float n_inv = 1.0f / (float)n;

    float *xbuf, *gbuf, *hbuf, *bfold;
    __nv_bfloat16 *bwh, *bwl;
    cudaGetSymbolAddress((void**)&xbuf, g_xbuf);
    cudaGetSymbolAddress((void**)&gbuf, g_gbuf);
    cudaGetSymbolAddress((void**)&hbuf, g_hbuf);
    cudaGetSymbolAddress((void**)&bfold, g_bfold);
    cudaGetSymbolAddress((void**)&bwh, g_bwh);
    cudaGetSymbolAddress((void**)&bwl, g_bwl);

    cudaFuncSetAttribute(gemm_mma_k, cudaFuncAttributeMaxDynamicSharedMemorySize, GEMM_SMEM_BYTES);
    cudaFuncSetAttribute(gemm_fused_k, cudaFuncAttributeMaxDynamicSharedMemorySize, FUSED_SMEM_BYTES);

    int sblocks = (n + 31) / 32;
    int nblk = (n + 255) / 256;
    const int WMAT = DIM * DIM;

    // ---- CSR build (two-level scan); hist zeroes stats slot 0 ----
    hist_k<<<(e + 255) / 256, 256>>>(er, e);
    scan1_k<<<nblk, 256>>>(n);
    scan2_k<<<1, 256>>>(n, nblk);
    scan3_k<<<nblk, 256>>>(n);
    scatter_k<<<(e + 255) / 256, 256>>>(er, ec, ev, e);

    // ---- BN stats -> fold+pre-split (merged) ----
    col_stats_k<<<512, 256>>>(x, n);
    wconvert_fold_k<<<1 + (4 * WMAT + 255) / 256, 256>>>(fin_w, fin_b, gamma, beta, gc_w, n_inv);

    // ---- fused fc_in + layer-0 GEMM (persistent; re-zeroes slot0) ----
    gemm_fused_k<<<NSM, 512, FUSED_SMEM_BYTES>>>(
        x, bwh, bwl, bwh + WMAT, bwl + WMAT, bfold, gbuf, n);
    spmm_k<<<sblocks, 256>>>(gbuf, gc_b + 0 * DIM, hbuf, n, 0);

    // ---- layers 1..3: persistent GEMM with fused PairNorm-apply on A ----
    for (int i = 1; i < NLAYER; i++) {
        gemm_mma_k<<<NSM, 512, GEMM_SMEM_BYTES>>>(
            hbuf, xbuf, xbuf, bwh + (i + 1) * WMAT, bwl + (i + 1) * WMAT,
            gbuf, n, (i - 1) & 1, i & 1, (i >= 2) ? 1 : 0, n_inv);
        spmm_k<<<sblocks, 256>>>(gbuf, gc_b + i * DIM, hbuf, n, i & 1);
    }

    // ---- output projection with fused final PairNorm (slot 1, addold) ----
    gemm_out_k<<<sblocks, 256>>>(hbuf, xbuf, fout_w, fout_b, out, n, (NLAYER - 1) & 1, n_inv);
}

// round 9
// speedup vs baseline: 1.8531x; 1.0459x over previous
#include <cuda_runtime.h>
#include <cuda_bf16.h>
#include <cuda_fp16.h>
#include <cstdint>

#define DIM 128
#define CDIM 40
#define NLAYER 4
#define NMAX 50000
#define EMAX 800000
#define NSM 148

// ---------------- device scratch (static: no allocations allowed) ----------
__device__ float g_xbuf[NMAX * DIM];
__device__ __half g_g16[NMAX * DIM];   // fp16 gather buffer (GEMM out -> spmm in)
__device__ float g_hbuf[NMAX * DIM];
__device__ float g_bfold[DIM];
__device__ float g_cs[2][DIM];     // column sums   (parity slots)
__device__ float g_cq[2][DIM];     // column sumsq  (parity slots)
__device__ __nv_bfloat16 g_bwh[5 * DIM * DIM];  // weight hi parts (wfold, gc_w0..3)
__device__ __nv_bfloat16 g_bwl[5 * DIM * DIM];  // weight lo parts
__device__ int   g_rowptr[NMAX + 1];
__device__ int   g_cnt[NMAX];      // zero-initialized; invariant: zero between replays
__device__ int   g_wcur[NMAX];
__device__ int   g_bsum[256];
__device__ int   g_boff[256];
__device__ int2  g_edge[EMAX];     // (colidx, val-bits) packed

// ======================= helpers ===========================================
__device__ __forceinline__ uint32_t smem_u32(const void* p) {
    uint32_t a;
    asm("{ .reg .u64 t; cvta.to.shared.u64 t, %1; cvt.u32.u64 %0, t; }" : "=r"(a) : "l"(p));
    return a;
}
__device__ __forceinline__ void ldm_x4(uint32_t* r, uint32_t addr) {
    asm volatile("ldmatrix.sync.aligned.m8n8.x4.shared.b16 {%0,%1,%2,%3}, [%4];"
                 : "=r"(r[0]), "=r"(r[1]), "=r"(r[2]), "=r"(r[3]) : "r"(addr));
}
__device__ __forceinline__ void ldm_x4_t(uint32_t* r, uint32_t addr) {
    asm volatile("ldmatrix.sync.aligned.m8n8.x4.trans.shared.b16 {%0,%1,%2,%3}, [%4];"
                 : "=r"(r[0]), "=r"(r[1]), "=r"(r[2]), "=r"(r[3]) : "r"(addr));
}
__device__ __forceinline__ void mma_bf16(float* c, const uint32_t* a, const uint32_t* b) {
    asm volatile(
        "mma.sync.aligned.m16n8k16.row.col.f32.bf16.bf16.f32 "
        "{%0,%1,%2,%3}, {%4,%5,%6,%7}, {%8,%9}, {%0,%1,%2,%3};"
        : "+f"(c[0]), "+f"(c[1]), "+f"(c[2]), "+f"(c[3])
        : "r"(a[0]), "r"(a[1]), "r"(a[2]), "r"(a[3]), "r"(b[0]), "r"(b[1]));
}
__device__ __forceinline__ uint32_t pack_hi(float x, float y, uint32_t& lo) {
    __nv_bfloat16 hx = __float2bfloat16(x);
    __nv_bfloat16 hy = __float2bfloat16(y);
    __nv_bfloat16 lx = __float2bfloat16(x - __bfloat162float(hx));
    __nv_bfloat16 ly = __float2bfloat16(y - __bfloat162float(hy));
    lo = (uint32_t)__bfloat16_as_ushort(lx) | ((uint32_t)__bfloat16_as_ushort(ly) << 16);
    return (uint32_t)__bfloat16_as_ushort(hx) | ((uint32_t)__bfloat16_as_ushort(hy) << 16);
}

// ======================= GEMM common pieces =================================
// 512 threads / 16 warps, warp grid 4x4, warp tile m32 x n32. Persistent blocks.
// fp32 accuracy via bf16 hi/lo split: D = Ah*Bh + Ah*Bl + Al*Bh.
#define PADK 136
#define TILE_B (128 * PADK * 2)           // 34816 bytes per bf16 tile
#define OFF_AH 0
#define OFF_AL TILE_B
#define OFF_B1H (2 * TILE_B)
#define OFF_B1L (3 * TILE_B)
#define OFF_B2H (4 * TILE_B)
#define OFF_B2L (5 * TILE_B)
#define GEMM_SMEM_BYTES  (4 * TILE_B + 2048)
#define FUSED_SMEM_BYTES (6 * TILE_B + 2048)

__device__ __forceinline__ void mma_mainloop(uint32_t sb, int bOffH, int bOffL,
                                             int wm, int wn, int lane,
                                             float acc[2][4][4]) {
    int lrow = lane & 15;
    int lcol8 = (lane >> 4) << 3;
#pragma unroll
    for (int t = 0; t < 3; t++) {
        uint32_t aBase = sb + ((t == 2) ? OFF_AL : OFF_AH);
        uint32_t bBase = sb + ((t == 1) ? bOffL : bOffH);
#pragma unroll
        for (int k0 = 0; k0 < 128; k0 += 16) {
            uint32_t a[2][4];
#pragma unroll
            for (int mg = 0; mg < 2; mg++)
                ldm_x4(a[mg], aBase + (uint32_t)((wm + mg * 16 + lrow) * PADK + k0 + lcol8) * 2u);
            uint32_t b[2][4];
#pragma unroll
            for (int nc = 0; nc < 2; nc++)
                ldm_x4_t(b[nc], bBase + (uint32_t)((k0 + lrow) * PADK + wn + nc * 16 + lcol8) * 2u);
#pragma unroll
            for (int mg = 0; mg < 2; mg++)
#pragma unroll
                for (int ng = 0; ng < 4; ng++)
                    mma_bf16(acc[mg][ng], a[mg], &b[ng >> 1][(ng & 1) * 2]);
        }
    }
}

__device__ __forceinline__ void stage_B(char* sm, int offH, int offL,
                                        const __nv_bfloat16* Bh,
                                        const __nv_bfloat16* Bl, int tid) {
    for (int g = tid; g < 2048; g += 512) {
        int r = g >> 4;
        int c = (g & 15) * 8;
        uint4 vh = reinterpret_cast<const uint4*>(Bh)[g];
        uint4 vl = reinterpret_cast<const uint4*>(Bl)[g];
        uint32_t eoff = (uint32_t)(r * PADK + c) * 2u;
        *reinterpret_cast<uint4*>(sm + offH + eoff) = vh;
        *reinterpret_cast<uint4*>(sm + offL + eoff) = vl;
    }
}

// ======================= main GEMM (persistent, fused PairNorm on A) ========
// Writes C as fp16 (consumed only by spmm, which accumulates in fp32).
__global__ __launch_bounds__(512) void gemm_mma_k(
    const float* __restrict__ A, const float* __restrict__ Xold,
    float* __restrict__ Xwrite,
    const __nv_bfloat16* __restrict__ Bh, const __nv_bfloat16* __restrict__ Bl,
    __half* __restrict__ C, int n,
    int pn_slot, int zero_slot, int addold, float n_inv) {
    extern __shared__ char sm[];
    float* smu = reinterpret_cast<float*>(sm + 4 * TILE_B);
    float* red = smu + DIM;
    uint32_t sb = smem_u32(sm);
    int tid = threadIdx.x, wid = tid >> 5, lane = tid & 31;

    if (zero_slot >= 0 && blockIdx.x == 0 && tid < DIM) {
        g_cs[zero_slot][tid] = 0.f;
        g_cq[zero_slot][tid] = 0.f;
    }

    float pscale = 0.f;
    if (pn_slot >= 0) {
        if (tid < DIM) {
            float mu = g_cs[pn_slot][tid] * n_inv;
            smu[tid] = mu;
            red[tid] = g_cq[pn_slot][tid] * n_inv - mu * mu;
        }
        __syncthreads();
        for (int off = 64; off > 0; off >>= 1) {
            if (tid < off) red[tid] += red[tid + off];
            __syncthreads();
        }
        if (tid == 0) red[0] = rsqrtf(1e-6f + red[0]);
        __syncthreads();
        pscale = red[0];
    }

    int T = (n + 127) >> 7;
    int t = blockIdx.x;
    if (t >= T) return;

    stage_B(sm, OFF_B1H, OFF_B1L, Bh, Bl, tid);

    // stage first tile A (load + PN + split)
    {
        int row0 = t * 128;
        for (int g = tid; g < 4096; g += 512) {
            int r = g >> 5, c = (g & 31) * 4;
            int row = row0 + r;
            float4 av = make_float4(0.f, 0.f, 0.f, 0.f);
            if (row < n) {
                av = *reinterpret_cast<const float4*>(&A[(size_t)row * DIM + c]);
                if (pn_slot >= 0) {
                    float4 m = *reinterpret_cast<const float4*>(&smu[c]);
                    av.x = fmaxf((av.x - m.x) * pscale, 0.f);
                    av.y = fmaxf((av.y - m.y) * pscale, 0.f);
                    av.z = fmaxf((av.z - m.z) * pscale, 0.f);
                    av.w = fmaxf((av.w - m.w) * pscale, 0.f);
                    if (addold) {
                        float4 xo = *reinterpret_cast<const float4*>(&Xold[(size_t)row * DIM + c]);
                        av.x += xo.x; av.y += xo.y; av.z += xo.z; av.w += xo.w;
                    }
                    if (Xwrite)
                        *reinterpret_cast<float4*>(&Xwrite[(size_t)row * DIM + c]) = av;
                }
            }
            uint32_t eoff = (uint32_t)(r * PADK + c) * 2u;
            uint32_t al0, al1;
            uint32_t ah0 = pack_hi(av.x, av.y, al0);
            uint32_t ah1 = pack_hi(av.z, av.w, al1);
            *reinterpret_cast<uint2*>(sm + OFF_AH + eoff) = make_uint2(ah0, ah1);
            *reinterpret_cast<uint2*>(sm + OFF_AL + eoff) = make_uint2(al0, al1);
        }
    }
    __syncthreads();

    int wm = (wid & 3) * 32;
    int wn = (wid >> 2) * 32;

    while (true) {
        int tn = t + gridDim.x;
        bool hn = tn < T;
        float4 raw[8];
        if (hn) {                       // prefetch next tile's A during mma
            int row0n = tn * 128;
#pragma unroll
            for (int q = 0; q < 8; q++) {
                int g = q * 512 + tid;
                int r = g >> 5, c = (g & 31) * 4;
                int row = row0n + r;
                raw[q] = (row < n)
                    ? *reinterpret_cast<const float4*>(&A[(size_t)row * DIM + c])
                    : make_float4(0.f, 0.f, 0.f, 0.f);
            }
        }

        float acc[2][4][4];
#pragma unroll
        for (int mg = 0; mg < 2; mg++)
#pragma unroll
            for (int ng = 0; ng < 4; ng++)
#pragma unroll
                for (int q = 0; q < 4; q++) acc[mg][ng][q] = 0.f;

        mma_mainloop(sb, OFF_B1H, OFF_B1L, wm, wn, lane, acc);

        int row0 = t * 128;
        int rbase = row0 + wm + (lane >> 2);
        int cbase = wn + (lane & 3) * 2;
#pragma unroll
        for (int mg = 0; mg < 2; mg++)
#pragma unroll
            for (int half = 0; half < 2; half++) {
                int row = rbase + mg * 16 + half * 8;
                if (row < n) {
#pragma unroll
                    for (int ng = 0; ng < 4; ng++) {
                        int col = cbase + ng * 8;
                        __half2 o = __floats2half2_rn(acc[mg][ng][half * 2],
                                                      acc[mg][ng][half * 2 + 1]);
                        *reinterpret_cast<__half2*>(&C[(size_t)row * DIM + col]) = o;
                    }
                }
            }

        if (!hn) break;
        __syncthreads();
        // convert prefetched tile into A smem (+PN +residual +writeback)
        {
            int row0n = tn * 128;
#pragma unroll
            for (int q = 0; q < 8; q++) {
                int g = q * 512 + tid;
                int r = g >> 5, c = (g & 31) * 4;
                int row = row0n + r;
                float4 av = raw[q];
                if (pn_slot >= 0 && row < n) {
                    float4 m = *reinterpret_cast<const float4*>(&smu[c]);
                    av.x = fmaxf((av.x - m.x) * pscale, 0.f);
                    av.y = fmaxf((av.y - m.y) * pscale, 0.f);
                    av.z = fmaxf((av.z - m.z) * pscale, 0.f);
                    av.w = fmaxf((av.w - m.w) * pscale, 0.f);
                    if (addold) {
                        float4 xo = *reinterpret_cast<const float4*>(&Xold[(size_t)row * DIM + c]);
                        av.x += xo.x; av.y += xo.y; av.z += xo.z; av.w += xo.w;
                    }
                    if (Xwrite)
                        *reinterpret_cast<float4*>(&Xwrite[(size_t)row * DIM + c]) = av;
                }
                uint32_t eoff = (uint32_t)(r * PADK + c) * 2u;
                uint32_t al0, al1;
                uint32_t ah0 = pack_hi(av.x, av.y, al0);
                uint32_t ah1 = pack_hi(av.z, av.w, al1);
                *reinterpret_cast<uint2*>(sm + OFF_AH + eoff) = make_uint2(ah0, ah1);
                *reinterpret_cast<uint2*>(sm + OFF_AL + eoff) = make_uint2(al0, al1);
            }
        }
        __syncthreads();
        t = tn;
    }
}

// ======================= fused fc_in + layer-0 GEMM (persistent) ============
// C(fp16) = (X @ Wfold + bfold) @ Wgc0 ; B1 and B2 both smem-resident.
__global__ __launch_bounds__(512) void gemm_fused_k(
    const float* __restrict__ X,
    const __nv_bfloat16* __restrict__ B1h, const __nv_bfloat16* __restrict__ B1l,
    const __nv_bfloat16* __restrict__ B2h, const __nv_bfloat16* __restrict__ B2l,
    const float* __restrict__ bias1, __half* __restrict__ C, int n) {
    extern __shared__ char sm[];
    float* sbias = reinterpret_cast<float*>(sm + 6 * TILE_B);
    uint32_t sb = smem_u32(sm);
    int tid = threadIdx.x, wid = tid >> 5, lane = tid & 31;

    if (blockIdx.x == 0 && tid < DIM) {
        g_cs[0][tid] = 0.f;
        g_cq[0][tid] = 0.f;
    }
    if (tid < DIM) sbias[tid] = bias1[tid];

    int T = (n + 127) >> 7;
    int t = blockIdx.x;
    if (t >= T) return;

    stage_B(sm, OFF_B1H, OFF_B1L, B1h, B1l, tid);
    stage_B(sm, OFF_B2H, OFF_B2L, B2h, B2l, tid);

    // stage first tile
    {
        int row0 = t * 128;
        for (int g = tid; g < 4096; g += 512) {
            int r = g >> 5, c = (g & 31) * 4;
            int row = row0 + r;
            float4 av = make_float4(0.f, 0.f, 0.f, 0.f);
            if (row < n) av = *reinterpret_cast<const float4*>(&X[(size_t)row * DIM + c]);
            uint32_t eoff = (uint32_t)(r * PADK + c) * 2u;
            uint32_t al0, al1;
            uint32_t ah0 = pack_hi(av.x, av.y, al0);
            uint32_t ah1 = pack_hi(av.z, av.w, al1);
            *reinterpret_cast<uint2*>(sm + OFF_AH + eoff) = make_uint2(ah0, ah1);
            *reinterpret_cast<uint2*>(sm + OFF_AL + eoff) = make_uint2(al0, al1);
        }
    }
    __syncthreads();

    int wm = (wid & 3) * 32;
    int wn = (wid >> 2) * 32;

    while (true) {
        int tn = t + gridDim.x;
        bool hn = tn < T;
        float4 raw[8];
        if (hn) {
            int row0n = tn * 128;
#pragma unroll
            for (int q = 0; q < 8; q++) {
                int g = q * 512 + tid;
                int r = g >> 5, c = (g & 31) * 4;
                int row = row0n + r;
                raw[q] = (row < n)
                    ? *reinterpret_cast<const float4*>(&X[(size_t)row * DIM + c])
                    : make_float4(0.f, 0.f, 0.f, 0.f);
            }
        }

        float acc[2][4][4];
#pragma unroll
        for (int mg = 0; mg < 2; mg++)
#pragma unroll
            for (int ng = 0; ng < 4; ng++)
#pragma unroll
                for (int q = 0; q < 4; q++) acc[mg][ng][q] = 0.f;

        mma_mainloop(sb, OFF_B1H, OFF_B1L, wm, wn, lane, acc);
        __syncthreads();   // all warps done reading A tile

        // write intermediate (acc + bias) back into A smem as bf16 hi/lo
        {
            int rl = wm + (lane >> 2);
            int cb = wn + (lane & 3) * 2;
#pragma unroll
            for (int mg = 0; mg < 2; mg++)
#pragma unroll
                for (int half = 0; half < 2; half++) {
                    int r = rl + mg * 16 + half * 8;
#pragma unroll
                    for (int ng = 0; ng < 4; ng++) {
                        int col = cb + ng * 8;
                        float v0 = acc[mg][ng][half * 2] + sbias[col];
                        float v1 = acc[mg][ng][half * 2 + 1] + sbias[col + 1];
                        uint32_t lo;
                        uint32_t hi = pack_hi(v0, v1, lo);
                        uint32_t eoff = (uint32_t)(r * PADK + col) * 2u;
                        *reinterpret_cast<uint32_t*>(sm + OFF_AH + eoff) = hi;
                        *reinterpret_cast<uint32_t*>(sm + OFF_AL + eoff) = lo;
                    }
                }
        }
        __syncthreads();

#pragma unroll
        for (int mg = 0; mg < 2; mg++)
#pragma unroll
            for (int ng = 0; ng < 4; ng++)
#pragma unroll
                for (int q = 0; q < 4; q++) acc[mg][ng][q] = 0.f;

        mma_mainloop(sb, OFF_B2H, OFF_B2L, wm, wn, lane, acc);

        int row0 = t * 128;
        int rbase = row0 + wm + (lane >> 2);
        int cbase = wn + (lane & 3) * 2;
#pragma unroll
        for (int mg = 0; mg < 2; mg++)
#pragma unroll
            for (int half = 0; half < 2; half++) {
                int row = rbase + mg * 16 + half * 8;
                if (row < n) {
#pragma unroll
                    for (int ng = 0; ng < 4; ng++) {
                        int col = cbase + ng * 8;
                        __half2 o = __floats2half2_rn(acc[mg][ng][half * 2],
                                                      acc[mg][ng][half * 2 + 1]);
                        *reinterpret_cast<__half2*>(&C[(size_t)row * DIM + col]) = o;
                    }
                }
            }

        if (!hn) break;
        __syncthreads();
        {
#pragma unroll
            for (int q = 0; q < 8; q++) {
                int g = q * 512 + tid;
                int r = g >> 5, c = (g & 31) * 4;
                float4 av = raw[q];
                uint32_t eoff = (uint32_t)(r * PADK + c) * 2u;
                uint32_t al0, al1;
                uint32_t ah0 = pack_hi(av.x, av.y, al0);
                uint32_t ah1 = pack_hi(av.z, av.w, al1);
                *reinterpret_cast<uint2*>(sm + OFF_AH + eoff) = make_uint2(ah0, ah1);
                *reinterpret_cast<uint2*>(sm + OFF_AL + eoff) = make_uint2(al0, al1);
            }
        }
        __syncthreads();
        t = tn;
    }
}

// ======================= input BN stats (device fn, slot 0) =================
__device__ __forceinline__ void col_stats_body(const float* __restrict__ x, int n,
                                               int blk, int nblks) {
    __shared__ float red[256];
    __shared__ float redq[128];
    int tid = threadIdx.x;
    red[tid] = 0.f;
    if (tid < 128) redq[tid] = 0.f;
    int w = tid >> 5, lane = tid & 31, c = lane * 4;
    int gw = blk * 8 + w;
    const int STR = 512 * 8;
    float4 s = make_float4(0.f, 0.f, 0.f, 0.f);
    float4 q = make_float4(0.f, 0.f, 0.f, 0.f);
    __syncthreads();
    for (int r0 = gw; r0 < n; r0 += STR * 4) {
#pragma unroll
        for (int u = 0; u < 4; u++) {
            int row = r0 + u * STR;
            if (row < n) {
                float4 v = *reinterpret_cast<const float4*>(&x[(size_t)row * DIM + c]);
                s.x += v.x; s.y += v.y; s.z += v.z; s.w += v.w;
                q.x += v.x * v.x; q.y += v.y * v.y; q.z += v.z * v.z; q.w += v.w * v.w;
            }
        }
    }
    (void)nblks;
    atomicAdd(&red[c], s.x);     atomicAdd(&red[c + 1], s.y);
    atomicAdd(&red[c + 2], s.z); atomicAdd(&red[c + 3], s.w);
    atomicAdd(&redq[c], q.x);     atomicAdd(&redq[c + 1], q.y);
    atomicAdd(&redq[c + 2], q.z); atomicAdd(&redq[c + 3], q.w);
    __syncthreads();
    if (tid < 128) {
        atomicAdd(&g_cs[0][tid], red[tid]);
        atomicAdd(&g_cq[0][tid], redq[tid]);
    }
}

// ======================= BN fold + weight pre-split (merged) ================
__global__ __launch_bounds__(256) void wconvert_fold_k(
    const float* __restrict__ fin_w, const float* __restrict__ fin_b,
    const float* __restrict__ gamma, const float* __restrict__ beta,
    const float* __restrict__ gc_w, float n_inv) {
    const int WMAT = DIM * DIM;
    if (blockIdx.x == 0) {
        __shared__ float sc[DIM], sh[DIM];
        int j = threadIdx.x;
        if (j < DIM) {
            float mu = g_cs[0][j] * n_inv;
            float var = g_cq[0][j] * n_inv - mu * mu;
            float s = gamma[j] * rsqrtf(var + 1e-5f);
            sc[j] = s;
            sh[j] = beta[j] - mu * s;
        }
        __syncthreads();
        if (j < DIM) {
            float acc = fin_b[j];
            for (int d = 0; d < DIM; d++) {
                float w = fin_w[d * DIM + j];
                acc += sh[d] * w;
                float wf = sc[d] * w;
                __nv_bfloat16 h = __float2bfloat16(wf);
                g_bwh[d * DIM + j] = h;
                g_bwl[d * DIM + j] = __float2bfloat16(wf - __bfloat162float(h));
            }
            g_bfold[j] = acc;
        }
    } else {
        int i = (blockIdx.x - 1) * 256 + threadIdx.x;
        if (i < 4 * WMAT) {
            float v = gc_w[i];
            __nv_bfloat16 h = __float2bfloat16(v);
            g_bwh[WMAT + i] = h;
            g_bwl[WMAT + i] = __float2bfloat16(v - __bfloat162float(h));
        }
    }
}

// ======================= CSR build ==========================================
__global__ void hist_k(const int* __restrict__ er, int e) {
    int i = blockIdx.x * blockDim.x + threadIdx.x;
    if (i < e) atomicAdd(&g_cnt[er[i]], 1);
}

__global__ __launch_bounds__(256) void scan1_k(int n) {
    __shared__ int red[256];
    int tid = threadIdx.x;
    int i = blockIdx.x * 256 + tid;
    red[tid] = (i < n) ? g_cnt[i] : 0;
    __syncthreads();
    for (int off = 128; off > 0; off >>= 1) {
        if (tid < off) red[tid] += red[tid + off];
        __syncthreads();
    }
    if (tid == 0) g_bsum[blockIdx.x] = red[0];
}

__global__ __launch_bounds__(256) void scan2_k(int n, int nblk) {
    __shared__ int s[256];
    int tid = threadIdx.x;
    int v = (tid < nblk) ? g_bsum[tid] : 0;
    s[tid] = v;
    __syncthreads();
    for (int off = 1; off < 256; off <<= 1) {
        int t = (tid >= off) ? s[tid - off] : 0;
        __syncthreads();
        s[tid] += t;
        __syncthreads();
    }
    g_boff[tid] = s[tid] - v;
    if (tid == 255) g_rowptr[n] = s[255];
}

// scan3 ALSO zeroes stats slot 0 (block 0) — the merged scatter+col_stats
// launch that follows accumulates into it (replay-safety invariant).
__global__ __launch_bounds__(256) void scan3_k(int n) {
    __shared__ int s[256];
    int tid = threadIdx.x;
    if (blockIdx.x == 0 && tid < DIM) {
        g_cs[0][tid] = 0.f;
        g_cq[0][tid] = 0.f;
    }
    int i = blockIdx.x * 256 + tid;
    int v = (i < n) ? g_cnt[i] : 0;
    s[tid] = v;
    __syncthreads();
    for (int off = 1; off < 256; off <<= 1) {
        int t = (tid >= off) ? s[tid - off] : 0;
        __syncthreads();
        s[tid] += t;
        __syncthreads();
    }
    if (i < n) {
        int excl = s[tid] - v + g_boff[blockIdx.x];
        g_rowptr[i] = excl;
        g_wcur[i] = excl;
        g_cnt[i] = 0;      // restore zero invariant for next replay
    }
}

// merged: blocks [0, eblk) scatter edges; blocks [eblk, eblk+512) do BN stats.
__global__ __launch_bounds__(256) void scatter_stats_k(
    const int* __restrict__ er, const int* __restrict__ ec,
    const float* __restrict__ ev, int e,
    const float* __restrict__ x, int n, int eblk) {
    if ((int)blockIdx.x < eblk) {
        int i = blockIdx.x * 256 + threadIdx.x;
        if (i < e) {
            int r = er[i];
            int pos = atomicAdd(&g_wcur[r], 1);
            g_edge[pos] = make_int2(ec[i], __float_as_int(ev[i]));
        }
    } else {
        col_stats_body(x, n, blockIdx.x - eblk, 512);
    }
}

// ======================= SPMM (fp16 gather) + fused PairNorm stats ==========
__global__ __launch_bounds__(256) void spmm_k(
    const __half* __restrict__ g, const float* __restrict__ bias,
    float* __restrict__ h, int n, int slot) {
    __shared__ float red[256];   // [0:128) sum, [128:256) sumsq
    int tid = threadIdx.x;
    red[tid] = 0.f;
    int w = tid >> 5, lane = tid & 31;
    int gw = blockIdx.x * 8 + w;
    int c = lane * 4;
    float4 b4 = *reinterpret_cast<const float4*>(&bias[c]);
    float4 ssum = make_float4(0.f, 0.f, 0.f, 0.f);
    float4 ssq = make_float4(0.f, 0.f, 0.f, 0.f);
    __syncthreads();
#pragma unroll
    for (int rr = 0; rr < 4; rr++) {
        int row = gw * 4 + rr;
        if (row >= n) break;
        int s = g_rowptr[row];
        int e = g_rowptr[row + 1];
        float4 acc = make_float4(0.f, 0.f, 0.f, 0.f);
        int i = s;
        for (; i + 7 < e; i += 8) {
            uint2 p[8];
            float vv[8];
#pragma unroll
            for (int u = 0; u < 8; u++) {
                int2 ed = g_edge[i + u];
                vv[u] = __int_as_float(ed.y);
                p[u] = *reinterpret_cast<const uint2*>(&g[(size_t)ed.x * DIM + c]);
            }
#pragma unroll
            for (int u = 0; u < 8; u++) {
                float2 lo = __half22float2(*reinterpret_cast<__half2*>(&p[u].x));
                float2 hi = __half22float2(*reinterpret_cast<__half2*>(&p[u].y));
                acc.x += vv[u] * lo.x;
                acc.y += vv[u] * lo.y;
                acc.z += vv[u] * hi.x;
                acc.w += vv[u] * hi.y;
            }
        }
        for (; i < e; i++) {
            int2 ed = g_edge[i];
            float v0 = __int_as_float(ed.y);
            uint2 pv = *reinterpret_cast<const uint2*>(&g[(size_t)ed.x * DIM + c]);
            float2 lo = __half22float2(*reinterpret_cast<__half2*>(&pv.x));
            float2 hi = __half22float2(*reinterpret_cast<__half2*>(&pv.y));
            acc.x += v0 * lo.x; acc.y += v0 * lo.y;
            acc.z += v0 * hi.x; acc.w += v0 * hi.y;
        }
        acc.x += b4.x; acc.y += b4.y; acc.z += b4.z; acc.w += b4.w;
        *reinterpret_cast<float4*>(&h[(size_t)row * DIM + c]) = acc;
        ssum.x += acc.x; ssum.y += acc.y; ssum.z += acc.z; ssum.w += acc.w;
        ssq.x += acc.x * acc.x; ssq.y += acc.y * acc.y;
        ssq.z += acc.z * acc.z; ssq.w += acc.w * acc.w;
    }
    atomicAdd(&red[c], ssum.x);     atomicAdd(&red[c + 1], ssum.y);
    atomicAdd(&red[c + 2], ssum.z); atomicAdd(&red[c + 3], ssum.w);
    atomicAdd(&red[128 + c], ssq.x);     atomicAdd(&red[128 + c + 1], ssq.y);
    atomicAdd(&red[128 + c + 2], ssq.z); atomicAdd(&red[128 + c + 3], ssq.w);
    __syncthreads();
    if (tid < 128) atomicAdd(&g_cs[slot][tid], red[tid]);
    else atomicAdd(&g_cq[slot][tid - 128], red[tid]);
}

// ======================= output GEMM + fused final PairNorm =================
__global__ __launch_bounds__(256) void gemm_out_k(
    const float* __restrict__ H, const float* __restrict__ Xold,
    const float* __restrict__ W, const float* __restrict__ b,
    float* __restrict__ out, int n, int pn_slot, float n_inv) {
    __shared__ float sx[32 * DIM];
    __shared__ float sw[DIM * CDIM];
    __shared__ float smu[DIM];
    __shared__ float red[DIM];
    int tid = threadIdx.x;
    int row0 = blockIdx.x * 32;
    for (int i = tid; i < DIM * CDIM; i += 256) sw[i] = W[i];
    if (tid < DIM) {
        float mu = g_cs[pn_slot][tid] * n_inv;
        smu[tid] = mu;
        red[tid] = g_cq[pn_slot][tid] * n_inv - mu * mu;
    }
    __syncthreads();
    for (int off = 64; off > 0; off >>= 1) {
        if (tid < off) red[tid] += red[tid + off];
        __syncthreads();
    }
    if (tid == 0) red[0] = rsqrtf(1e-6f + red[0]);
    __syncthreads();
    float s = red[0];
#pragma unroll
    for (int q = 0; q < 4; q++) {
        int flat = (q * 256 + tid) * 4;
        int r = flat >> 7, c = flat & 127;
        int row = row0 + r;
        float4 v = make_float4(0.f, 0.f, 0.f, 0.f);
        if (row < n) {
            float4 hv = *reinterpret_cast<const float4*>(&H[(size_t)row * DIM + c]);
            float4 m = *reinterpret_cast<const float4*>(&smu[c]);
            float4 xo = *reinterpret_cast<const float4*>(&Xold[(size_t)row * DIM + c]);
            v.x = fmaxf((hv.x - m.x) * s, 0.f) + xo.x;
            v.y = fmaxf((hv.y - m.y) * s, 0.f) + xo.y;
            v.z = fmaxf((hv.z - m.z) * s, 0.f) + xo.z;
            v.w = fmaxf((hv.w - m.w) * s, 0.f) + xo.w;
        }
        *reinterpret_cast<float4*>(&sx[flat]) = v;
    }
    __syncthreads();
    int r = tid >> 3;
    int c0 = (tid & 7) * 5;
    float acc[5];
#pragma unroll
    for (int j = 0; j < 5; j++) acc[j] = b[c0 + j];
#pragma unroll 4
    for (int k = 0; k < DIM; k++) {
        float xv = sx[r * DIM + k];
#pragma unroll
        for (int j = 0; j < 5; j++) acc[j] += xv * sw[k * CDIM + c0 + j];
    }
    if (row0 + r < n) {
#pragma unroll
        for (int j = 0; j < 5; j++) out[(size_t)(row0 + r) * CDIM + c0 + j] = acc[j];
    }
}

// ======================= launch =============================================
extern "C" void kernel_launch(void* const* d_in, const int* in_sizes, int n_in,
                              void* d_out, int out_size) {
    const float* x      = (const float*)d_in[0];
    const int*   er     = (const int*)d_in[1];
    const int*   ec     = (const int*)d_in[2];
    const float* ev     = (const float*)d_in[3];
    const float* gamma  = (const float*)d_in[4];
    const float* beta   = (const float*)d_in[5];
    const float* fin_w  = (const float*)d_in[6];
    const float* fin_b  = (const float*)d_in[7];
    const float* gc_w   = (const float*)d_in[8];
    const float* gc_b   = (const float*)d_in[9];
    const float* fout_w = (const float*)d_in[10];
    const float* fout_b = (const float*)d_in[11];
    float* out = (float*)d_out;

    int n = in_sizes[0] / DIM;
    int e = in_sizes[1];
    float n_inv = 1.0f / (float)n;

    float *xbuf, *hbuf, *bfold;
    __half* g16;
    __nv_bfloat16 *bwh, *bwl;
    cudaGetSymbolAddress((void**)&xbuf, g_xbuf);
    cudaGetSymbolAddress((void**)&g16, g_g16);
    cudaGetSymbolAddress((void**)&hbuf, g_hbuf);
    cudaGetSymbolAddress((void**)&bfold, g_bfold);
    cudaGetSymbolAddress((void**)&bwh, g_bwh);
    cudaGetSymbolAddress((void**)&bwl, g_bwl);

    cudaFuncSetAttribute(gemm_mma_k, cudaFuncAttributeMaxDynamicSharedMemorySize, GEMM_SMEM_BYTES);
    cudaFuncSetAttribute(gemm_fused_k, cudaFuncAttributeMaxDynamicSharedMemorySize, FUSED_SMEM_BYTES);

    int sblocks = (n + 31) / 32;
    int nblk = (n + 255) / 256;
    int eblk = (e + 255) / 256;
    const int WMAT = DIM * DIM;

    // ---- CSR build; scan3 zeroes stats slot 0; scatter+col_stats merged ----
    hist_k<<<eblk, 256>>>(er, e);
    scan1_k<<<nblk, 256>>>(n);
    scan2_k<<<1, 256>>>(n, nblk);
    scan3_k<<<nblk, 256>>>(n);
    scatter_stats_k<<<eblk + 512, 256>>>(er, ec, ev, e, x, n, eblk);

    // ---- BN fold + weight pre-split ----
    wconvert_fold_k<<<1 + (4 * WMAT + 255) / 256, 256>>>(fin_w, fin_b, gamma, beta, gc_w, n_inv);

    // ---- fused fc_in + layer-0 GEMM (persistent; re-zeroes slot0) ----
    gemm_fused_k<<<NSM, 512, FUSED_SMEM_BYTES>>>(
        x, bwh, bwl, bwh + WMAT, bwl + WMAT, bfold, g16, n);
    spmm_k<<<sblocks, 256>>>(g16, gc_b + 0 * DIM, hbuf, n, 0);

    // ---- layers 1..3: persistent GEMM with fused PairNorm-apply on A ----
    for (int i = 1; i < NLAYER; i++) {
        gemm_mma_k<<<NSM, 512, GEMM_SMEM_BYTES>>>(
            hbuf, xbuf, xbuf, bwh + (i + 1) * WMAT, bwl + (i + 1) * WMAT,
            g16, n, (i - 1) & 1, i & 1, (i >= 2) ? 1 : 0, n_inv);
        spmm_k<<<sblocks, 256>>>(g16, gc_b + i * DIM, hbuf, n, i & 1);
    }

    // ---- output projection with fused final PairNorm (slot 1, addold) ----
    gemm_out_k<<<sblocks, 256>>>(hbuf, xbuf, fout_w, fout_b, out, n, (NLAYER - 1) & 1, n_inv);
}

// round 10
// speedup vs baseline: 1.9052x; 1.0282x over previous
#include <cuda_runtime.h>
#include <cuda_bf16.h>
#include <cuda_fp16.h>
#include <cstdint>

#define DIM 128
#define CDIM 40
#define NLAYER 4
#define NMAX 50000
#define EMAX 800000
#define NSM 148

// ---------------- device scratch (static: no allocations allowed) ----------
__device__ float  g_xbuf[NMAX * DIM];     // fp32 residual
__device__ __half g_g16[NMAX * DIM];      // fp16 gather buffer (GEMM -> spmm)
__device__ __half g_h16[NMAX * DIM];      // fp16 spmm output (spmm -> GEMM)
__device__ float g_cs[2][DIM];            // PairNorm column sums (parity slots)
__device__ float g_cq[2][DIM];            // PairNorm column sumsq
__device__ float g_bn_cs[DIM];            // BatchNorm input stats (dedicated)
__device__ float g_bn_cq[DIM];
__device__ int   g_rowptr[NMAX + 1];
__device__ int   g_cnt[NMAX];             // invariant: zero between replays
__device__ int   g_wcur[NMAX];
__device__ int   g_bsum[256];
__device__ int   g_boff[256];
__device__ int2  g_edge[EMAX];            // (colidx, val-bits) packed

// ======================= helpers ===========================================
__device__ __forceinline__ uint32_t smem_u32(const void* p) {
    uint32_t a;
    asm("{ .reg .u64 t; cvta.to.shared.u64 t, %1; cvt.u32.u64 %0, t; }" : "=r"(a) : "l"(p));
    return a;
}
__device__ __forceinline__ void ldm_x4(uint32_t* r, uint32_t addr) {
    asm volatile("ldmatrix.sync.aligned.m8n8.x4.shared.b16 {%0,%1,%2,%3}, [%4];"
                 : "=r"(r[0]), "=r"(r[1]), "=r"(r[2]), "=r"(r[3]) : "r"(addr));
}
__device__ __forceinline__ void ldm_x4_t(uint32_t* r, uint32_t addr) {
    asm volatile("ldmatrix.sync.aligned.m8n8.x4.trans.shared.b16 {%0,%1,%2,%3}, [%4];"
                 : "=r"(r[0]), "=r"(r[1]), "=r"(r[2]), "=r"(r[3]) : "r"(addr));
}
__device__ __forceinline__ void mma_bf16(float* c, const uint32_t* a, const uint32_t* b) {
    asm volatile(
        "mma.sync.aligned.m16n8k16.row.col.f32.bf16.bf16.f32 "
        "{%0,%1,%2,%3}, {%4,%5,%6,%7}, {%8,%9}, {%0,%1,%2,%3};"
        : "+f"(c[0]), "+f"(c[1]), "+f"(c[2]), "+f"(c[3])
        : "r"(a[0]), "r"(a[1]), "r"(a[2]), "r"(a[3]), "r"(b[0]), "r"(b[1]));
}
__device__ __forceinline__ uint32_t pack_hi(float x, float y, uint32_t& lo) {
    __nv_bfloat16 hx = __float2bfloat16(x);
    __nv_bfloat16 hy = __float2bfloat16(y);
    __nv_bfloat16 lx = __float2bfloat16(x - __bfloat162float(hx));
    __nv_bfloat16 ly = __float2bfloat16(y - __bfloat162float(hy));
    lo = (uint32_t)__bfloat16_as_ushort(lx) | ((uint32_t)__bfloat16_as_ushort(ly) << 16);
    return (uint32_t)__bfloat16_as_ushort(hx) | ((uint32_t)__bfloat16_as_ushort(hy) << 16);
}
__device__ __forceinline__ float4 h4_to_f4(uint2 hv) {
    float2 lo = __half22float2(*reinterpret_cast<__half2*>(&hv.x));
    float2 hi = __half22float2(*reinterpret_cast<__half2*>(&hv.y));
    return make_float4(lo.x, lo.y, hi.x, hi.y);
}

// ======================= GEMM common pieces =================================
#define PADK 136
#define TILE_B (128 * PADK * 2)
#define OFF_AH 0
#define OFF_AL TILE_B
#define OFF_B1H (2 * TILE_B)
#define OFF_B1L (3 * TILE_B)
#define OFF_B2H (4 * TILE_B)
#define OFF_B2L (5 * TILE_B)
#define GEMM_SMEM_BYTES  (4 * TILE_B + 2048)
#define FUSED_SMEM_BYTES (6 * TILE_B + 2048)

__device__ __forceinline__ void mma_mainloop(uint32_t sb, int bOffH, int bOffL,
                                             int wm, int wn, int lane,
                                             float acc[2][4][4]) {
    int lrow = lane & 15;
    int lcol8 = (lane >> 4) << 3;
#pragma unroll
    for (int t = 0; t < 3; t++) {
        uint32_t aBase = sb + ((t == 2) ? OFF_AL : OFF_AH);
        uint32_t bBase = sb + ((t == 1) ? bOffL : bOffH);
#pragma unroll
        for (int k0 = 0; k0 < 128; k0 += 16) {
            uint32_t a[2][4];
#pragma unroll
            for (int mg = 0; mg < 2; mg++)
                ldm_x4(a[mg], aBase + (uint32_t)((wm + mg * 16 + lrow) * PADK + k0 + lcol8) * 2u);
            uint32_t b[2][4];
#pragma unroll
            for (int nc = 0; nc < 2; nc++)
                ldm_x4_t(b[nc], bBase + (uint32_t)((k0 + lrow) * PADK + wn + nc * 16 + lcol8) * 2u);
#pragma unroll
            for (int mg = 0; mg < 2; mg++)
#pragma unroll
                for (int ng = 0; ng < 4; ng++)
                    mma_bf16(acc[mg][ng], a[mg], &b[ng >> 1][(ng & 1) * 2]);
        }
    }
}

// stage a weight matrix from fp32 gmem, splitting to bf16 hi/lo in smem.
// optional per-row (K-dim) scale for the BN fold.
__device__ __forceinline__ void stage_B_f32(char* sm, int offH, int offL,
                                            const float* __restrict__ W,
                                            const float* rscale, int tid) {
    for (int g = tid; g < 4096; g += 512) {
        int r = g >> 5, c = (g & 31) * 4;
        float4 w = *reinterpret_cast<const float4*>(&W[r * DIM + c]);
        if (rscale) {
            float s = rscale[r];
            w.x *= s; w.y *= s; w.z *= s; w.w *= s;
        }
        uint32_t eoff = (uint32_t)(r * PADK + c) * 2u;
        uint32_t l0, l1;
        uint32_t h0 = pack_hi(w.x, w.y, l0);
        uint32_t h1 = pack_hi(w.z, w.w, l1);
        *reinterpret_cast<uint2*>(sm + offH + eoff) = make_uint2(h0, h1);
        *reinterpret_cast<uint2*>(sm + offL + eoff) = make_uint2(l0, l1);
    }
}

// ======================= main GEMM (persistent, fused PairNorm on A) ========
// A is fp16 (spmm output); C is fp16 (spmm input). Weights split on the fly.
__global__ __launch_bounds__(512) void gemm_mma_k(
    const __half* __restrict__ A, const float* __restrict__ Xold,
    float* __restrict__ Xwrite, const float* __restrict__ Wf32,
    __half* __restrict__ C, int n,
    int pn_slot, int zero_slot, int addold, float n_inv) {
    extern __shared__ char sm[];
    float* smu = reinterpret_cast<float*>(sm + 4 * TILE_B);
    float* red = smu + DIM;
    uint32_t sb = smem_u32(sm);
    int tid = threadIdx.x, wid = tid >> 5, lane = tid & 31;

    if (zero_slot >= 0 && blockIdx.x == 0 && tid < DIM) {
        g_cs[zero_slot][tid] = 0.f;
        g_cq[zero_slot][tid] = 0.f;
    }

    // PairNorm scale from slot
    if (tid < DIM) {
        float mu = g_cs[pn_slot][tid] * n_inv;
        smu[tid] = mu;
        red[tid] = g_cq[pn_slot][tid] * n_inv - mu * mu;
    }
    __syncthreads();
    for (int off = 64; off > 0; off >>= 1) {
        if (tid < off) red[tid] += red[tid + off];
        __syncthreads();
    }
    if (tid == 0) red[0] = rsqrtf(1e-6f + red[0]);
    __syncthreads();
    float pscale = red[0];

    int T = (n + 127) >> 7;
    int t = blockIdx.x;
    if (t >= T) return;

    stage_B_f32(sm, OFF_B1H, OFF_B1L, Wf32, nullptr, tid);

    // stage first tile A (fp16 load + PN + residual + split)
    {
        int row0 = t * 128;
        for (int g = tid; g < 4096; g += 512) {
            int r = g >> 5, c = (g & 31) * 4;
            int row = row0 + r;
            float4 av = make_float4(0.f, 0.f, 0.f, 0.f);
            if (row < n) {
                av = h4_to_f4(*reinterpret_cast<const uint2*>(&A[(size_t)row * DIM + c]));
                float4 m = *reinterpret_cast<const float4*>(&smu[c]);
                av.x = fmaxf((av.x - m.x) * pscale, 0.f);
                av.y = fmaxf((av.y - m.y) * pscale, 0.f);
                av.z = fmaxf((av.z - m.z) * pscale, 0.f);
                av.w = fmaxf((av.w - m.w) * pscale, 0.f);
                if (addold) {
                    float4 xo = *reinterpret_cast<const float4*>(&Xold[(size_t)row * DIM + c]);
                    av.x += xo.x; av.y += xo.y; av.z += xo.z; av.w += xo.w;
                }
                *reinterpret_cast<float4*>(&Xwrite[(size_t)row * DIM + c]) = av;
            }
            uint32_t eoff = (uint32_t)(r * PADK + c) * 2u;
            uint32_t al0, al1;
            uint32_t ah0 = pack_hi(av.x, av.y, al0);
            uint32_t ah1 = pack_hi(av.z, av.w, al1);
            *reinterpret_cast<uint2*>(sm + OFF_AH + eoff) = make_uint2(ah0, ah1);
            *reinterpret_cast<uint2*>(sm + OFF_AL + eoff) = make_uint2(al0, al1);
        }
    }
    __syncthreads();

    int wm = (wid & 3) * 32;
    int wn = (wid >> 2) * 32;

    while (true) {
        int tn = t + gridDim.x;
        bool hn = tn < T;
        uint2 raw[8];
        if (hn) {                       // prefetch next tile's A during mma
            int row0n = tn * 128;
#pragma unroll
            for (int q = 0; q < 8; q++) {
                int g = q * 512 + tid;
                int r = g >> 5, c = (g & 31) * 4;
                int row = row0n + r;
                raw[q] = (row < n)
                    ? *reinterpret_cast<const uint2*>(&A[(size_t)row * DIM + c])
                    : make_uint2(0u, 0u);
            }
        }

        float acc[2][4][4];
#pragma unroll
        for (int mg = 0; mg < 2; mg++)
#pragma unroll
            for (int ng = 0; ng < 4; ng++)
#pragma unroll
                for (int q = 0; q < 4; q++) acc[mg][ng][q] = 0.f;

        mma_mainloop(sb, OFF_B1H, OFF_B1L, wm, wn, lane, acc);

        int row0 = t * 128;
        int rbase = row0 + wm + (lane >> 2);
        int cbase = wn + (lane & 3) * 2;
#pragma unroll
        for (int mg = 0; mg < 2; mg++)
#pragma unroll
            for (int half = 0; half < 2; half++) {
                int row = rbase + mg * 16 + half * 8;
                if (row < n) {
#pragma unroll
                    for (int ng = 0; ng < 4; ng++) {
                        int col = cbase + ng * 8;
                        __half2 o = __floats2half2_rn(acc[mg][ng][half * 2],
                                                      acc[mg][ng][half * 2 + 1]);
                        *reinterpret_cast<__half2*>(&C[(size_t)row * DIM + col]) = o;
                    }
                }
            }

        if (!hn) break;
        __syncthreads();
        {
            int row0n = tn * 128;
#pragma unroll
            for (int q = 0; q < 8; q++) {
                int g = q * 512 + tid;
                int r = g >> 5, c = (g & 31) * 4;
                int row = row0n + r;
                float4 av = make_float4(0.f, 0.f, 0.f, 0.f);
                if (row < n) {
                    av = h4_to_f4(raw[q]);
                    float4 m = *reinterpret_cast<const float4*>(&smu[c]);
                    av.x = fmaxf((av.x - m.x) * pscale, 0.f);
                    av.y = fmaxf((av.y - m.y) * pscale, 0.f);
                    av.z = fmaxf((av.z - m.z) * pscale, 0.f);
                    av.w = fmaxf((av.w - m.w) * pscale, 0.f);
                    if (addold) {
                        float4 xo = *reinterpret_cast<const float4*>(&Xold[(size_t)row * DIM + c]);
                        av.x += xo.x; av.y += xo.y; av.z += xo.z; av.w += xo.w;
                    }
                    *reinterpret_cast<float4*>(&Xwrite[(size_t)row * DIM + c]) = av;
                }
                uint32_t eoff = (uint32_t)(r * PADK + c) * 2u;
                uint32_t al0, al1;
                uint32_t ah0 = pack_hi(av.x, av.y, al0);
                uint32_t ah1 = pack_hi(av.z, av.w, al1);
                *reinterpret_cast<uint2*>(sm + OFF_AH + eoff) = make_uint2(ah0, ah1);
                *reinterpret_cast<uint2*>(sm + OFF_AL + eoff) = make_uint2(al0, al1);
            }
        }
        __syncthreads();
        t = tn;
    }
}

// ======================= fused fc_in + layer-0 GEMM (persistent) ============
// Per-block: BN fold (sc/sh/bias from g_bn stats), both weight splits in smem.
__global__ __launch_bounds__(512) void gemm_fused_k(
    const float* __restrict__ X,
    const float* __restrict__ fin_w, const float* __restrict__ fin_b,
    const float* __restrict__ gamma, const float* __restrict__ beta,
    const float* __restrict__ W2,
    __half* __restrict__ C, int n, float n_inv) {
    extern __shared__ char sm[];
    float* ssc = reinterpret_cast<float*>(sm + 6 * TILE_B);
    float* ssh = ssc + DIM;
    float* sbias = ssh + DIM;
    uint32_t sb = smem_u32(sm);
    int tid = threadIdx.x, wid = tid >> 5, lane = tid & 31;

    // zero PN slot 0 for layer-0 spmm (separate arrays from g_bn: no race)
    if (blockIdx.x == 0 && tid < DIM) {
        g_cs[0][tid] = 0.f;
        g_cq[0][tid] = 0.f;
    }
    // BN fold coefficients
    if (tid < DIM) {
        float mu = g_bn_cs[tid] * n_inv;
        float var = g_bn_cq[tid] * n_inv - mu * mu;
        float s = gamma[tid] * rsqrtf(var + 1e-5f);
        ssc[tid] = s;
        ssh[tid] = beta[tid] - mu * s;
    }
    __syncthreads();

    int T = (n + 127) >> 7;
    int t = blockIdx.x;
    if (t >= T) return;

    stage_B_f32(sm, OFF_B1H, OFF_B1L, fin_w, ssc, tid);
    stage_B_f32(sm, OFF_B2H, OFF_B2L, W2, nullptr, tid);
    // folded bias: b'[j] = fin_b[j] + sum_d sh[d]*W[d][j]
    if (tid < DIM) {
        float acc = fin_b[tid];
        for (int d = 0; d < DIM; d++) acc += ssh[d] * fin_w[d * DIM + tid];
        sbias[tid] = acc;
    }

    // stage first tile (fp32 input x)
    {
        int row0 = t * 128;
        for (int g = tid; g < 4096; g += 512) {
            int r = g >> 5, c = (g & 31) * 4;
            int row = row0 + r;
            float4 av = make_float4(0.f, 0.f, 0.f, 0.f);
            if (row < n) av = *reinterpret_cast<const float4*>(&X[(size_t)row * DIM + c]);
            uint32_t eoff = (uint32_t)(r * PADK + c) * 2u;
            uint32_t al0, al1;
            uint32_t ah0 = pack_hi(av.x, av.y, al0);
            uint32_t ah1 = pack_hi(av.z, av.w, al1);
            *reinterpret_cast<uint2*>(sm + OFF_AH + eoff) = make_uint2(ah0, ah1);
            *reinterpret_cast<uint2*>(sm + OFF_AL + eoff) = make_uint2(al0, al1);
        }
    }
    __syncthreads();

    int wm = (wid & 3) * 32;
    int wn = (wid >> 2) * 32;

    while (true) {
        int tn = t + gridDim.x;
        bool hn = tn < T;
        float4 raw[8];
        if (hn) {
            int row0n = tn * 128;
#pragma unroll
            for (int q = 0; q < 8; q++) {
                int g = q * 512 + tid;
                int r = g >> 5, c = (g & 31) * 4;
                int row = row0n + r;
                raw[q] = (row < n)
                    ? *reinterpret_cast<const float4*>(&X[(size_t)row * DIM + c])
                    : make_float4(0.f, 0.f, 0.f, 0.f);
            }
        }

        float acc[2][4][4];
#pragma unroll
        for (int mg = 0; mg < 2; mg++)
#pragma unroll
            for (int ng = 0; ng < 4; ng++)
#pragma unroll
                for (int q = 0; q < 4; q++) acc[mg][ng][q] = 0.f;

        mma_mainloop(sb, OFF_B1H, OFF_B1L, wm, wn, lane, acc);
        __syncthreads();

        {
            int rl = wm + (lane >> 2);
            int cb = wn + (lane & 3) * 2;
#pragma unroll
            for (int mg = 0; mg < 2; mg++)
#pragma unroll
                for (int half = 0; half < 2; half++) {
                    int r = rl + mg * 16 + half * 8;
#pragma unroll
                    for (int ng = 0; ng < 4; ng++) {
                        int col = cb + ng * 8;
                        float v0 = acc[mg][ng][half * 2] + sbias[col];
                        float v1 = acc[mg][ng][half * 2 + 1] + sbias[col + 1];
                        uint32_t lo;
                        uint32_t hi = pack_hi(v0, v1, lo);
                        uint32_t eoff = (uint32_t)(r * PADK + col) * 2u;
                        *reinterpret_cast<uint32_t*>(sm + OFF_AH + eoff) = hi;
                        *reinterpret_cast<uint32_t*>(sm + OFF_AL + eoff) = lo;
                    }
                }
        }
        __syncthreads();

#pragma unroll
        for (int mg = 0; mg < 2; mg++)
#pragma unroll
            for (int ng = 0; ng < 4; ng++)
#pragma unroll
                for (int q = 0; q < 4; q++) acc[mg][ng][q] = 0.f;

        mma_mainloop(sb, OFF_B2H, OFF_B2L, wm, wn, lane, acc);

        int row0 = t * 128;
        int rbase = row0 + wm + (lane >> 2);
        int cbase = wn + (lane & 3) * 2;
#pragma unroll
        for (int mg = 0; mg < 2; mg++)
#pragma unroll
            for (int half = 0; half < 2; half++) {
                int row = rbase + mg * 16 + half * 8;
                if (row < n) {
#pragma unroll
                    for (int ng = 0; ng < 4; ng++) {
                        int col = cbase + ng * 8;
                        __half2 o = __floats2half2_rn(acc[mg][ng][half * 2],
                                                      acc[mg][ng][half * 2 + 1]);
                        *reinterpret_cast<__half2*>(&C[(size_t)row * DIM + col]) = o;
                    }
                }
            }

        if (!hn) break;
        __syncthreads();
        {
#pragma unroll
            for (int q = 0; q < 8; q++) {
                int g = q * 512 + tid;
                int r = g >> 5, c = (g & 31) * 4;
                float4 av = raw[q];
                uint32_t eoff = (uint32_t)(r * PADK + c) * 2u;
                uint32_t al0, al1;
                uint32_t ah0 = pack_hi(av.x, av.y, al0);
                uint32_t ah1 = pack_hi(av.z, av.w, al1);
                *reinterpret_cast<uint2*>(sm + OFF_AH + eoff) = make_uint2(ah0, ah1);
                *reinterpret_cast<uint2*>(sm + OFF_AL + eoff) = make_uint2(al0, al1);
            }
        }
        __syncthreads();
        t = tn;
    }
}

// ======================= input BN stats (device fn -> g_bn) =================
__device__ __forceinline__ void col_stats_body(const float* __restrict__ x, int n,
                                               int blk) {
    __shared__ float red[256];
    __shared__ float redq[128];
    int tid = threadIdx.x;
    red[tid] = 0.f;
    if (tid < 128) redq[tid] = 0.f;
    int w = tid >> 5, lane = tid & 31, c = lane * 4;
    int gw = blk * 8 + w;
    const int STR = 512 * 8;
    float4 s = make_float4(0.f, 0.f, 0.f, 0.f);
    float4 q = make_float4(0.f, 0.f, 0.f, 0.f);
    __syncthreads();
    for (int r0 = gw; r0 < n; r0 += STR * 4) {
#pragma unroll
        for (int u = 0; u < 4; u++) {
            int row = r0 + u * STR;
            if (row < n) {
                float4 v = *reinterpret_cast<const float4*>(&x[(size_t)row * DIM + c]);
                s.x += v.x; s.y += v.y; s.z += v.z; s.w += v.w;
                q.x += v.x * v.x; q.y += v.y * v.y; q.z += v.z * v.z; q.w += v.w * v.w;
            }
        }
    }
    atomicAdd(&red[c], s.x);     atomicAdd(&red[c + 1], s.y);
    atomicAdd(&red[c + 2], s.z); atomicAdd(&red[c + 3], s.w);
    atomicAdd(&redq[c], q.x);     atomicAdd(&redq[c + 1], q.y);
    atomicAdd(&redq[c + 2], q.z); atomicAdd(&redq[c + 3], q.w);
    __syncthreads();
    if (tid < 128) {
        atomicAdd(&g_bn_cs[tid], red[tid]);
        atomicAdd(&g_bn_cq[tid], redq[tid]);
    }
}

// ======================= CSR build ==========================================
__global__ void hist_k(const int* __restrict__ er, int e) {
    int i = blockIdx.x * blockDim.x + threadIdx.x;
    if (i < e) atomicAdd(&g_cnt[er[i]], 1);
}

__global__ __launch_bounds__(256) void scan1_k(int n) {
    __shared__ int red[256];
    int tid = threadIdx.x;
    int i = blockIdx.x * 256 + tid;
    red[tid] = (i < n) ? g_cnt[i] : 0;
    __syncthreads();
    for (int off = 128; off > 0; off >>= 1) {
        if (tid < off) red[tid] += red[tid + off];
        __syncthreads();
    }
    if (tid == 0) g_bsum[blockIdx.x] = red[0];
}

__global__ __launch_bounds__(256) void scan2_k(int n, int nblk) {
    __shared__ int s[256];
    int tid = threadIdx.x;
    int v = (tid < nblk) ? g_bsum[tid] : 0;
    s[tid] = v;
    __syncthreads();
    for (int off = 1; off < 256; off <<= 1) {
        int t = (tid >= off) ? s[tid - off] : 0;
        __syncthreads();
        s[tid] += t;
        __syncthreads();
    }
    g_boff[tid] = s[tid] - v;
    if (tid == 255) g_rowptr[n] = s[255];
}

// scan3 ALSO zeroes BN stats (block 0) — scatter_stats accumulates into them.
__global__ __launch_bounds__(256) void scan3_k(int n) {
    __shared__ int s[256];
    int tid = threadIdx.x;
    if (blockIdx.x == 0 && tid < DIM) {
        g_bn_cs[tid] = 0.f;
        g_bn_cq[tid] = 0.f;
    }
    int i = blockIdx.x * 256 + tid;
    int v = (i < n) ? g_cnt[i] : 0;
    s[tid] = v;
    __syncthreads();
    for (int off = 1; off < 256; off <<= 1) {
        int t = (tid >= off) ? s[tid - off] : 0;
        __syncthreads();
        s[tid] += t;
        __syncthreads();
    }
    if (i < n) {
        int excl = s[tid] - v + g_boff[blockIdx.x];
        g_rowptr[i] = excl;
        g_wcur[i] = excl;
        g_cnt[i] = 0;      // restore zero invariant for next replay
    }
}

// merged: blocks [0, eblk) scatter edges; blocks [eblk, eblk+512) do BN stats.
__global__ __launch_bounds__(256) void scatter_stats_k(
    const int* __restrict__ er, const int* __restrict__ ec,
    const float* __restrict__ ev, int e,
    const float* __restrict__ x, int n, int eblk) {
    if ((int)blockIdx.x < eblk) {
        int i = blockIdx.x * 256 + threadIdx.x;
        if (i < e) {
            int r = er[i];
            int pos = atomicAdd(&g_wcur[r], 1);
            g_edge[pos] = make_int2(ec[i], __float_as_int(ev[i]));
        }
    } else {
        col_stats_body(x, n, blockIdx.x - eblk);
    }
}

// ======================= SPMM (fp16 in/out) + fused PairNorm stats ==========
__global__ __launch_bounds__(256) void spmm_k(
    const __half* __restrict__ g, const float* __restrict__ bias,
    __half* __restrict__ h, int n, int slot) {
    __shared__ float red[256];   // [0:128) sum, [128:256) sumsq
    int tid = threadIdx.x;
    red[tid] = 0.f;
    int w = tid >> 5, lane = tid & 31;
    int gw = blockIdx.x * 8 + w;
    int c = lane * 4;
    float4 b4 = *reinterpret_cast<const float4*>(&bias[c]);
    float4 ssum = make_float4(0.f, 0.f, 0.f, 0.f);
    float4 ssq = make_float4(0.f, 0.f, 0.f, 0.f);
    __syncthreads();
#pragma unroll
    for (int rr = 0; rr < 4; rr++) {
        int row = gw * 4 + rr;
        if (row >= n) break;
        int s = g_rowptr[row];
        int e = g_rowptr[row + 1];
        float4 acc = make_float4(0.f, 0.f, 0.f, 0.f);
        int i = s;
        for (; i + 7 < e; i += 8) {
            uint2 p[8];
            float vv[8];
#pragma unroll
            for (int u = 0; u < 8; u++) {
                int2 ed = g_edge[i + u];
                vv[u] = __int_as_float(ed.y);
                p[u] = *reinterpret_cast<const uint2*>(&g[(size_t)ed.x * DIM + c]);
            }
#pragma unroll
            for (int u = 0; u < 8; u++) {
                float4 gv = h4_to_f4(p[u]);
                acc.x += vv[u] * gv.x;
                acc.y += vv[u] * gv.y;
                acc.z += vv[u] * gv.z;
                acc.w += vv[u] * gv.w;
            }
        }
        if (i + 3 < e) {
            uint2 p[4];
            float vv[4];
#pragma unroll
            for (int u = 0; u < 4; u++) {
                int2 ed = g_edge[i + u];
                vv[u] = __int_as_float(ed.y);
                p[u] = *reinterpret_cast<const uint2*>(&g[(size_t)ed.x * DIM + c]);
            }
#pragma unroll
            for (int u = 0; u < 4; u++) {
                float4 gv = h4_to_f4(p[u]);
                acc.x += vv[u] * gv.x;
                acc.y += vv[u] * gv.y;
                acc.z += vv[u] * gv.z;
                acc.w += vv[u] * gv.w;
            }
            i += 4;
        }
        for (; i < e; i++) {
            int2 ed = g_edge[i];
            float v0 = __int_as_float(ed.y);
            float4 gv = h4_to_f4(*reinterpret_cast<const uint2*>(&g[(size_t)ed.x * DIM + c]));
            acc.x += v0 * gv.x; acc.y += v0 * gv.y;
            acc.z += v0 * gv.z; acc.w += v0 * gv.w;
        }
        acc.x += b4.x; acc.y += b4.y; acc.z += b4.z; acc.w += b4.w;
        __half2 o0 = __floats2half2_rn(acc.x, acc.y);
        __half2 o1 = __floats2half2_rn(acc.z, acc.w);
        uint2 ov;
        ov.x = *reinterpret_cast<uint32_t*>(&o0);
        ov.y = *reinterpret_cast<uint32_t*>(&o1);
        *reinterpret_cast<uint2*>(&h[(size_t)row * DIM + c]) = ov;
        ssum.x += acc.x; ssum.y += acc.y; ssum.z += acc.z; ssum.w += acc.w;
        ssq.x += acc.x * acc.x; ssq.y += acc.y * acc.y;
        ssq.z += acc.z * acc.z; ssq.w += acc.w * acc.w;
    }
    atomicAdd(&red[c], ssum.x);     atomicAdd(&red[c + 1], ssum.y);
    atomicAdd(&red[c + 2], ssum.z); atomicAdd(&red[c + 3], ssum.w);
    atomicAdd(&red[128 + c], ssq.x);     atomicAdd(&red[128 + c + 1], ssq.y);
    atomicAdd(&red[128 + c + 2], ssq.z); atomicAdd(&red[128 + c + 3], ssq.w);
    __syncthreads();
    if (tid < 128) atomicAdd(&g_cs[slot][tid], red[tid]);
    else atomicAdd(&g_cq[slot][tid - 128], red[tid]);
}

// ======================= output GEMM + fused final PairNorm =================
__global__ __launch_bounds__(256) void gemm_out_k(
    const __half* __restrict__ H, const float* __restrict__ Xold,
    const float* __restrict__ W, const float* __restrict__ b,
    float* __restrict__ out, int n, int pn_slot, float n_inv) {
    __shared__ float sx[32 * DIM];
    __shared__ float sw[DIM * CDIM];
    __shared__ float smu[DIM];
    __shared__ float red[DIM];
    int tid = threadIdx.x;
    int row0 = blockIdx.x * 32;
    for (int i = tid; i < DIM * CDIM; i += 256) sw[i] = W[i];
    if (tid < DIM) {
        float mu = g_cs[pn_slot][tid] * n_inv;
        smu[tid] = mu;
        red[tid] = g_cq[pn_slot][tid] * n_inv - mu * mu;
    }
    __syncthreads();
    for (int off = 64; off > 0; off >>= 1) {
        if (tid < off) red[tid] += red[tid + off];
        __syncthreads();
    }
    if (tid == 0) red[0] = rsqrtf(1e-6f + red[0]);
    __syncthreads();
    float s = red[0];
#pragma unroll
    for (int q = 0; q < 4; q++) {
        int flat = (q * 256 + tid) * 4;
        int r = flat >> 7, c = flat & 127;
        int row = row0 + r;
        float4 v = make_float4(0.f, 0.f, 0.f, 0.f);
        if (row < n) {
            float4 hv = h4_to_f4(*reinterpret_cast<const uint2*>(&H[(size_t)row * DIM + c]));
            float4 m = *reinterpret_cast<const float4*>(&smu[c]);
            float4 xo = *reinterpret_cast<const float4*>(&Xold[(size_t)row * DIM + c]);
            v.x = fmaxf((hv.x - m.x) * s, 0.f) + xo.x;
            v.y = fmaxf((hv.y - m.y) * s, 0.f) + xo.y;
            v.z = fmaxf((hv.z - m.z) * s, 0.f) + xo.z;
            v.w = fmaxf((hv.w - m.w) * s, 0.f) + xo.w;
        }
        *reinterpret_cast<float4*>(&sx[flat]) = v;
    }
    __syncthreads();
    int r = tid >> 3;
    int c0 = (tid & 7) * 5;
    float acc[5];
#pragma unroll
    for (int j = 0; j < 5; j++) acc[j] = b[c0 + j];
#pragma unroll 4
    for (int k = 0; k < DIM; k++) {
        float xv = sx[r * DIM + k];
#pragma unroll
        for (int j = 0; j < 5; j++) acc[j] += xv * sw[k * CDIM + c0 + j];
    }
    if (row0 + r < n) {
#pragma unroll
        for (int j = 0; j < 5; j++) out[(size_t)(row0 + r) * CDIM + c0 + j] = acc[j];
    }
}

// ======================= launch =============================================
extern "C" void kernel_launch(void* const* d_in, const int* in_sizes, int n_in,
                              void* d_out, int out_size) {
    const float* x      = (const float*)d_in[0];
    const int*   er     = (const int*)d_in[1];
    const int*   ec     = (const int*)d_in[2];
    const float* ev     = (const float*)d_in[3];
    const float* gamma  = (const float*)d_in[4];
    const float* beta   = (const float*)d_in[5];
    const float* fin_w  = (const float*)d_in[6];
    const float* fin_b  = (const float*)d_in[7];
    const float* gc_w   = (const float*)d_in[8];
    const float* gc_b   = (const float*)d_in[9];
    const float* fout_w = (const float*)d_in[10];
    const float* fout_b = (const float*)d_in[11];
    float* out = (float*)d_out;

    int n = in_sizes[0] / DIM;
    int e = in_sizes[1];
    float n_inv = 1.0f / (float)n;

    float* xbuf;
    __half *g16, *h16;
    cudaGetSymbolAddress((void**)&xbuf, g_xbuf);
    cudaGetSymbolAddress((void**)&g16, g_g16);
    cudaGetSymbolAddress((void**)&h16, g_h16);

    cudaFuncSetAttribute(gemm_mma_k, cudaFuncAttributeMaxDynamicSharedMemorySize, GEMM_SMEM_BYTES);
    cudaFuncSetAttribute(gemm_fused_k, cudaFuncAttributeMaxDynamicSharedMemorySize, FUSED_SMEM_BYTES);

    int sblocks = (n + 31) / 32;
    int nblk = (n + 255) / 256;
    int eblk = (e + 255) / 256;
    const int WMAT = DIM * DIM;

    // ---- CSR build; scan3 zeroes BN stats; scatter+col_stats merged ----
    hist_k<<<eblk, 256>>>(er, e);
    scan1_k<<<nblk, 256>>>(n);
    scan2_k<<<1, 256>>>(n, nblk);
    scan3_k<<<nblk, 256>>>(n);
    scatter_stats_k<<<eblk + 512, 256>>>(er, ec, ev, e, x, n, eblk);

    // ---- fused fc_in + layer-0 GEMM (per-block BN fold; zeroes PN slot 0) --
    gemm_fused_k<<<NSM, 512, FUSED_SMEM_BYTES>>>(
        x, fin_w, fin_b, gamma, beta, gc_w, g16, n, n_inv);
    spmm_k<<<sblocks, 256>>>(g16, gc_b + 0 * DIM, h16, n, 0);

    // ---- layers 1..3: persistent GEMM with fused PairNorm-apply on A ----
    for (int i = 1; i < NLAYER; i++) {
        gemm_mma_k<<<NSM, 512, GEMM_SMEM_BYTES>>>(
            h16, xbuf, xbuf, gc_w + i * WMAT,
            g16, n, (i - 1) & 1, i & 1, (i >= 2) ? 1 : 0, n_inv);
        spmm_k<<<sblocks, 256>>>(g16, gc_b + i * DIM, h16, n, i & 1);
    }

    // ---- output projection with fused final PairNorm (slot 1, addold) ----
    gemm_out_k<<<sblocks, 256>>>(h16, xbuf, fout_w, fout_b, out, n, (NLAYER - 1) & 1, n_inv);
}

// round 11
// speedup vs baseline: 1.9170x; 1.0062x over previous
#include <cuda_runtime.h>
#include <cuda_bf16.h>
#include <cuda_fp16.h>
#include <cstdint>

#define DIM 128
#define CDIM 40
#define NLAYER 4
#define NMAX 50000
#define EMAX 800000
#define NSM 148

// ---------------- device scratch (static: no allocations allowed) ----------
__device__ float  g_xbuf[NMAX * DIM];     // fp32 residual
__device__ __half g_g16[NMAX * DIM];      // fp16 gather buffer (GEMM -> spmm)
__device__ __half g_h16[NMAX * DIM];      // fp16 spmm output (spmm -> GEMM)
__device__ float g_cs[2][DIM];            // PairNorm column sums (parity slots)
__device__ float g_cq[2][DIM];            // PairNorm column sumsq
__device__ float g_bn_ps[256][DIM];       // BN stats partials (no zero needed)
__device__ float g_bn_pq[256][DIM];
__device__ int   g_rowptr[NMAX + 1];
__device__ int   g_cnt[NMAX];             // invariant: zero between replays
__device__ int   g_wcur[NMAX];
__device__ int   g_bsum[256];
__device__ int2  g_edge[EMAX];            // (colidx, val-bits) packed

// ======================= helpers ===========================================
__device__ __forceinline__ uint32_t smem_u32(const void* p) {
    uint32_t a;
    asm("{ .reg .u64 t; cvta.to.shared.u64 t, %1; cvt.u32.u64 %0, t; }" : "=r"(a) : "l"(p));
    return a;
}
__device__ __forceinline__ void ldm_x4(uint32_t* r, uint32_t addr) {
    asm volatile("ldmatrix.sync.aligned.m8n8.x4.shared.b16 {%0,%1,%2,%3}, [%4];"
                 : "=r"(r[0]), "=r"(r[1]), "=r"(r[2]), "=r"(r[3]) : "r"(addr));
}
__device__ __forceinline__ void ldm_x4_t(uint32_t* r, uint32_t addr) {
    asm volatile("ldmatrix.sync.aligned.m8n8.x4.trans.shared.b16 {%0,%1,%2,%3}, [%4];"
                 : "=r"(r[0]), "=r"(r[1]), "=r"(r[2]), "=r"(r[3]) : "r"(addr));
}
__device__ __forceinline__ void mma_bf16(float* c, const uint32_t* a, const uint32_t* b) {
    asm volatile(
        "mma.sync.aligned.m16n8k16.row.col.f32.bf16.bf16.f32 "
        "{%0,%1,%2,%3}, {%4,%5,%6,%7}, {%8,%9}, {%0,%1,%2,%3};"
        : "+f"(c[0]), "+f"(c[1]), "+f"(c[2]), "+f"(c[3])
        : "r"(a[0]), "r"(a[1]), "r"(a[2]), "r"(a[3]), "r"(b[0]), "r"(b[1]));
}
__device__ __forceinline__ uint32_t pack_hi(float x, float y, uint32_t& lo) {
    __nv_bfloat16 hx = __float2bfloat16(x);
    __nv_bfloat16 hy = __float2bfloat16(y);
    __nv_bfloat16 lx = __float2bfloat16(x - __bfloat162float(hx));
    __nv_bfloat16 ly = __float2bfloat16(y - __bfloat162float(hy));
    lo = (uint32_t)__bfloat16_as_ushort(lx) | ((uint32_t)__bfloat16_as_ushort(ly) << 16);
    return (uint32_t)__bfloat16_as_ushort(hx) | ((uint32_t)__bfloat16_as_ushort(hy) << 16);
}
__device__ __forceinline__ float4 h4_to_f4(uint2 hv) {
    float2 lo = __half22float2(*reinterpret_cast<__half2*>(&hv.x));
    float2 hi = __half22float2(*reinterpret_cast<__half2*>(&hv.y));
    return make_float4(lo.x, lo.y, hi.x, hi.y);
}

// ======================= GEMM common pieces =================================
#define PADK 136
#define TILE_B (128 * PADK * 2)
#define OFF_AH 0
#define OFF_AL TILE_B
#define OFF_B1H (2 * TILE_B)
#define OFF_B1L (3 * TILE_B)
#define OFF_B2H (4 * TILE_B)
#define OFF_B2L (5 * TILE_B)
#define GEMM_SMEM_BYTES  (4 * TILE_B + 2048)
#define FUSED_SMEM_BYTES (6 * TILE_B + 2048)

__device__ __forceinline__ void mma_mainloop(uint32_t sb, int bOffH, int bOffL,
                                             int wm, int wn, int lane,
                                             float acc[2][4][4]) {
    int lrow = lane & 15;
    int lcol8 = (lane >> 4) << 3;
#pragma unroll
    for (int t = 0; t < 3; t++) {
        uint32_t aBase = sb + ((t == 2) ? OFF_AL : OFF_AH);
        uint32_t bBase = sb + ((t == 1) ? bOffL : bOffH);
#pragma unroll
        for (int k0 = 0; k0 < 128; k0 += 16) {
            uint32_t a[2][4];
#pragma unroll
            for (int mg = 0; mg < 2; mg++)
                ldm_x4(a[mg], aBase + (uint32_t)((wm + mg * 16 + lrow) * PADK + k0 + lcol8) * 2u);
            uint32_t b[2][4];
#pragma unroll
            for (int nc = 0; nc < 2; nc++)
                ldm_x4_t(b[nc], bBase + (uint32_t)((k0 + lrow) * PADK + wn + nc * 16 + lcol8) * 2u);
#pragma unroll
            for (int mg = 0; mg < 2; mg++)
#pragma unroll
                for (int ng = 0; ng < 4; ng++)
                    mma_bf16(acc[mg][ng], a[mg], &b[ng >> 1][(ng & 1) * 2]);
        }
    }
}

__device__ __forceinline__ void stage_B_f32(char* sm, int offH, int offL,
                                            const float* __restrict__ W,
                                            const float* rscale, int tid) {
    for (int g = tid; g < 4096; g += 512) {
        int r = g >> 5, c = (g & 31) * 4;
        float4 w = *reinterpret_cast<const float4*>(&W[r * DIM + c]);
        if (rscale) {
            float s = rscale[r];
            w.x *= s; w.y *= s; w.z *= s; w.w *= s;
        }
        uint32_t eoff = (uint32_t)(r * PADK + c) * 2u;
        uint32_t l0, l1;
        uint32_t h0 = pack_hi(w.x, w.y, l0);
        uint32_t h1 = pack_hi(w.z, w.w, l1);
        *reinterpret_cast<uint2*>(sm + offH + eoff) = make_uint2(h0, h1);
        *reinterpret_cast<uint2*>(sm + offL + eoff) = make_uint2(l0, l1);
    }
}

// ======================= main GEMM (persistent, fused PairNorm on A) ========
__global__ __launch_bounds__(512) void gemm_mma_k(
    const __half* __restrict__ A, const float* __restrict__ Xold,
    float* __restrict__ Xwrite, const float* __restrict__ Wf32,
    __half* __restrict__ C, int n,
    int pn_slot, int zero_slot, int addold, float n_inv) {
    extern __shared__ char sm[];
    float* smu = reinterpret_cast<float*>(sm + 4 * TILE_B);
    float* red = smu + DIM;
    uint32_t sb = smem_u32(sm);
    int tid = threadIdx.x, wid = tid >> 5, lane = tid & 31;

    if (zero_slot >= 0 && blockIdx.x == 0 && tid < DIM) {
        g_cs[zero_slot][tid] = 0.f;
        g_cq[zero_slot][tid] = 0.f;
    }

    if (tid < DIM) {
        float mu = g_cs[pn_slot][tid] * n_inv;
        smu[tid] = mu;
        red[tid] = g_cq[pn_slot][tid] * n_inv - mu * mu;
    }
    __syncthreads();
    for (int off = 64; off > 0; off >>= 1) {
        if (tid < off) red[tid] += red[tid + off];
        __syncthreads();
    }
    if (tid == 0) red[0] = rsqrtf(1e-6f + red[0]);
    __syncthreads();
    float pscale = red[0];

    int T = (n + 127) >> 7;
    int t = blockIdx.x;
    if (t >= T) return;

    stage_B_f32(sm, OFF_B1H, OFF_B1L, Wf32, nullptr, tid);

    {
        int row0 = t * 128;
        for (int g = tid; g < 4096; g += 512) {
            int r = g >> 5, c = (g & 31) * 4;
            int row = row0 + r;
            float4 av = make_float4(0.f, 0.f, 0.f, 0.f);
            if (row < n) {
                av = h4_to_f4(*reinterpret_cast<const uint2*>(&A[(size_t)row * DIM + c]));
                float4 m = *reinterpret_cast<const float4*>(&smu[c]);
                av.x = fmaxf((av.x - m.x) * pscale, 0.f);
                av.y = fmaxf((av.y - m.y) * pscale, 0.f);
                av.z = fmaxf((av.z - m.z) * pscale, 0.f);
                av.w = fmaxf((av.w - m.w) * pscale, 0.f);
                if (addold) {
                    float4 xo = *reinterpret_cast<const float4*>(&Xold[(size_t)row * DIM + c]);
                    av.x += xo.x; av.y += xo.y; av.z += xo.z; av.w += xo.w;
                }
                *reinterpret_cast<float4*>(&Xwrite[(size_t)row * DIM + c]) = av;
            }
            uint32_t eoff = (uint32_t)(r * PADK + c) * 2u;
            uint32_t al0, al1;
            uint32_t ah0 = pack_hi(av.x, av.y, al0);
            uint32_t ah1 = pack_hi(av.z, av.w, al1);
            *reinterpret_cast<uint2*>(sm + OFF_AH + eoff) = make_uint2(ah0, ah1);
            *reinterpret_cast<uint2*>(sm + OFF_AL + eoff) = make_uint2(al0, al1);
        }
    }
    __syncthreads();

    int wm = (wid & 3) * 32;
    int wn = (wid >> 2) * 32;

    while (true) {
        int tn = t + gridDim.x;
        bool hn = tn < T;
        uint2 raw[8];
        if (hn) {
            int row0n = tn * 128;
#pragma unroll
            for (int q = 0; q < 8; q++) {
                int g = q * 512 + tid;
                int r = g >> 5, c = (g & 31) * 4;
                int row = row0n + r;
                raw[q] = (row < n)
                    ? *reinterpret_cast<const uint2*>(&A[(size_t)row * DIM + c])
                    : make_uint2(0u, 0u);
            }
        }

        float acc[2][4][4];
#pragma unroll
        for (int mg = 0; mg < 2; mg++)
#pragma unroll
            for (int ng = 0; ng < 4; ng++)
#pragma unroll
                for (int q = 0; q < 4; q++) acc[mg][ng][q] = 0.f;

        mma_mainloop(sb, OFF_B1H, OFF_B1L, wm, wn, lane, acc);

        int row0 = t * 128;
        int rbase = row0 + wm + (lane >> 2);
        int cbase = wn + (lane & 3) * 2;
#pragma unroll
        for (int mg = 0; mg < 2; mg++)
#pragma unroll
            for (int half = 0; half < 2; half++) {
                int row = rbase + mg * 16 + half * 8;
                if (row < n) {
#pragma unroll
                    for (int ng = 0; ng < 4; ng++) {
                        int col = cbase + ng * 8;
                        __half2 o = __floats2half2_rn(acc[mg][ng][half * 2],
                                                      acc[mg][ng][half * 2 + 1]);
                        *reinterpret_cast<__half2*>(&C[(size_t)row * DIM + col]) = o;
                    }
                }
            }

        if (!hn) break;
        __syncthreads();
        {
            int row0n = tn * 128;
#pragma unroll
            for (int q = 0; q < 8; q++) {
                int g = q * 512 + tid;
                int r = g >> 5, c = (g & 31) * 4;
                int row = row0n + r;
                float4 av = make_float4(0.f, 0.f, 0.f, 0.f);
                if (row < n) {
                    av = h4_to_f4(raw[q]);
                    float4 m = *reinterpret_cast<const float4*>(&smu[c]);
                    av.x = fmaxf((av.x - m.x) * pscale, 0.f);
                    av.y = fmaxf((av.y - m.y) * pscale, 0.f);
                    av.z = fmaxf((av.z - m.z) * pscale, 0.f);
                    av.w = fmaxf((av.w - m.w) * pscale, 0.f);
                    if (addold) {
                        float4 xo = *reinterpret_cast<const float4*>(&Xold[(size_t)row * DIM + c]);
                        av.x += xo.x; av.y += xo.y; av.z += xo.z; av.w += xo.w;
                    }
                    *reinterpret_cast<float4*>(&Xwrite[(size_t)row * DIM + c]) = av;
                }
                uint32_t eoff = (uint32_t)(r * PADK + c) * 2u;
                uint32_t al0, al1;
                uint32_t ah0 = pack_hi(av.x, av.y, al0);
                uint32_t ah1 = pack_hi(av.z, av.w, al1);
                *reinterpret_cast<uint2*>(sm + OFF_AH + eoff) = make_uint2(ah0, ah1);
                *reinterpret_cast<uint2*>(sm + OFF_AL + eoff) = make_uint2(al0, al1);
            }
        }
        __syncthreads();
        t = tn;
    }
}

// ======================= fused fc_in + layer-0 GEMM (persistent) ============
// Reduces BN partials per-block (no atomics, no zeroing) -> fold -> 2 GEMMs.
__global__ __launch_bounds__(512) void gemm_fused_k(
    const float* __restrict__ X,
    const float* __restrict__ fin_w, const float* __restrict__ fin_b,
    const float* __restrict__ gamma, const float* __restrict__ beta,
    const float* __restrict__ W2,
    __half* __restrict__ C, int n, float n_inv) {
    extern __shared__ char sm[];
    float* ssc = reinterpret_cast<float*>(sm + 6 * TILE_B);
    float* ssh = ssc + DIM;
    float* sbias = ssh + DIM;
    uint32_t sb = smem_u32(sm);
    int tid = threadIdx.x, wid = tid >> 5, lane = tid & 31;

    if (blockIdx.x == 0 && tid < DIM) {
        g_cs[0][tid] = 0.f;
        g_cq[0][tid] = 0.f;
    }
    // reduce BN partials -> fold coefficients
    if (tid < DIM) {
        float s0 = 0.f, s1 = 0.f, s2 = 0.f, s3 = 0.f;
        float q0 = 0.f, q1 = 0.f, q2 = 0.f, q3 = 0.f;
        for (int p = 0; p < 256; p += 4) {
            s0 += g_bn_ps[p][tid];     s1 += g_bn_ps[p + 1][tid];
            s2 += g_bn_ps[p + 2][tid]; s3 += g_bn_ps[p + 3][tid];
            q0 += g_bn_pq[p][tid];     q1 += g_bn_pq[p + 1][tid];
            q2 += g_bn_pq[p + 2][tid]; q3 += g_bn_pq[p + 3][tid];
        }
        float mu = ((s0 + s1) + (s2 + s3)) * n_inv;
        float var = ((q0 + q1) + (q2 + q3)) * n_inv - mu * mu;
        float s = gamma[tid] * rsqrtf(var + 1e-5f);
        ssc[tid] = s;
        ssh[tid] = beta[tid] - mu * s;
    }
    __syncthreads();

    int T = (n + 127) >> 7;
    int t = blockIdx.x;
    if (t >= T) return;

    stage_B_f32(sm, OFF_B1H, OFF_B1L, fin_w, ssc, tid);
    stage_B_f32(sm, OFF_B2H, OFF_B2L, W2, nullptr, tid);
    if (tid < DIM) {
        float acc = fin_b[tid];
        for (int d = 0; d < DIM; d++) acc += ssh[d] * fin_w[d * DIM + tid];
        sbias[tid] = acc;
    }

    {
        int row0 = t * 128;
        for (int g = tid; g < 4096; g += 512) {
            int r = g >> 5, c = (g & 31) * 4;
            int row = row0 + r;
            float4 av = make_float4(0.f, 0.f, 0.f, 0.f);
            if (row < n) av = *reinterpret_cast<const float4*>(&X[(size_t)row * DIM + c]);
            uint32_t eoff = (uint32_t)(r * PADK + c) * 2u;
            uint32_t al0, al1;
            uint32_t ah0 = pack_hi(av.x, av.y, al0);
            uint32_t ah1 = pack_hi(av.z, av.w, al1);
            *reinterpret_cast<uint2*>(sm + OFF_AH + eoff) = make_uint2(ah0, ah1);
            *reinterpret_cast<uint2*>(sm + OFF_AL + eoff) = make_uint2(al0, al1);
        }
    }
    __syncthreads();

    int wm = (wid & 3) * 32;
    int wn = (wid >> 2) * 32;

    while (true) {
        int tn = t + gridDim.x;
        bool hn = tn < T;
        float4 raw[8];
        if (hn) {
            int row0n = tn * 128;
#pragma unroll
            for (int q = 0; q < 8; q++) {
                int g = q * 512 + tid;
                int r = g >> 5, c = (g & 31) * 4;
                int row = row0n + r;
                raw[q] = (row < n)
                    ? *reinterpret_cast<const float4*>(&X[(size_t)row * DIM + c])
                    : make_float4(0.f, 0.f, 0.f, 0.f);
            }
        }

        float acc[2][4][4];
#pragma unroll
        for (int mg = 0; mg < 2; mg++)
#pragma unroll
            for (int ng = 0; ng < 4; ng++)
#pragma unroll
                for (int q = 0; q < 4; q++) acc[mg][ng][q] = 0.f;

        mma_mainloop(sb, OFF_B1H, OFF_B1L, wm, wn, lane, acc);
        __syncthreads();

        {
            int rl = wm + (lane >> 2);
            int cb = wn + (lane & 3) * 2;
#pragma unroll
            for (int mg = 0; mg < 2; mg++)
#pragma unroll
                for (int half = 0; half < 2; half++) {
                    int r = rl + mg * 16 + half * 8;
#pragma unroll
                    for (int ng = 0; ng < 4; ng++) {
                        int col = cb + ng * 8;
                        float v0 = acc[mg][ng][half * 2] + sbias[col];
                        float v1 = acc[mg][ng][half * 2 + 1] + sbias[col + 1];
                        uint32_t lo;
                        uint32_t hi = pack_hi(v0, v1, lo);
                        uint32_t eoff = (uint32_t)(r * PADK + col) * 2u;
                        *reinterpret_cast<uint32_t*>(sm + OFF_AH + eoff) = hi;
                        *reinterpret_cast<uint32_t*>(sm + OFF_AL + eoff) = lo;
                    }
                }
        }
        __syncthreads();

#pragma unroll
        for (int mg = 0; mg < 2; mg++)
#pragma unroll
            for (int ng = 0; ng < 4; ng++)
#pragma unroll
                for (int q = 0; q < 4; q++) acc[mg][ng][q] = 0.f;

        mma_mainloop(sb, OFF_B2H, OFF_B2L, wm, wn, lane, acc);

        int row0 = t * 128;
        int rbase = row0 + wm + (lane >> 2);
        int cbase = wn + (lane & 3) * 2;
#pragma unroll
        for (int mg = 0; mg < 2; mg++)
#pragma unroll
            for (int half = 0; half < 2; half++) {
                int row = rbase + mg * 16 + half * 8;
                if (row < n) {
#pragma unroll
                    for (int ng = 0; ng < 4; ng++) {
                        int col = cbase + ng * 8;
                        __half2 o = __floats2half2_rn(acc[mg][ng][half * 2],
                                                      acc[mg][ng][half * 2 + 1]);
                        *reinterpret_cast<__half2*>(&C[(size_t)row * DIM + col]) = o;
                    }
                }
            }

        if (!hn) break;
        __syncthreads();
        {
#pragma unroll
            for (int q = 0; q < 8; q++) {
                int g = q * 512 + tid;
                int r = g >> 5, c = (g & 31) * 4;
                float4 av = raw[q];
                uint32_t eoff = (uint32_t)(r * PADK + c) * 2u;
                uint32_t al0, al1;
                uint32_t ah0 = pack_hi(av.x, av.y, al0);
                uint32_t ah1 = pack_hi(av.z, av.w, al1);
                *reinterpret_cast<uint2*>(sm + OFF_AH + eoff) = make_uint2(ah0, ah1);
                *reinterpret_cast<uint2*>(sm + OFF_AL + eoff) = make_uint2(al0, al1);
            }
        }
        __syncthreads();
        t = tn;
    }
}

// ======================= input BN stats -> per-block partials ===============
// Exactly 256 blocks. Non-atomic partial writes (no zero-init required).
__global__ __launch_bounds__(256) void col_stats_k(const float* __restrict__ x, int n) {
    __shared__ float red[256];
    __shared__ float redq[128];
    int tid = threadIdx.x;
    red[tid] = 0.f;
    if (tid < 128) redq[tid] = 0.f;
    int w = tid >> 5, lane = tid & 31, c = lane * 4;
    int gw = blockIdx.x * 8 + w;
    const int STR = 256 * 8;
    float4 s = make_float4(0.f, 0.f, 0.f, 0.f);
    float4 q = make_float4(0.f, 0.f, 0.f, 0.f);
    __syncthreads();
    for (int r0 = gw; r0 < n; r0 += STR * 4) {
#pragma unroll
        for (int u = 0; u < 4; u++) {
            int row = r0 + u * STR;
            if (row < n) {
                float4 v = *reinterpret_cast<const float4*>(&x[(size_t)row * DIM + c]);
                s.x += v.x; s.y += v.y; s.z += v.z; s.w += v.w;
                q.x += v.x * v.x; q.y += v.y * v.y; q.z += v.z * v.z; q.w += v.w * v.w;
            }
        }
    }
    atomicAdd(&red[c], s.x);     atomicAdd(&red[c + 1], s.y);
    atomicAdd(&red[c + 2], s.z); atomicAdd(&red[c + 3], s.w);
    atomicAdd(&redq[c], q.x);     atomicAdd(&redq[c + 1], q.y);
    atomicAdd(&redq[c + 2], q.z); atomicAdd(&redq[c + 3], q.w);
    __syncthreads();
    if (tid < 128) {
        g_bn_ps[blockIdx.x][tid] = red[tid];
        g_bn_pq[blockIdx.x][tid] = redq[tid];
    }
}

// ======================= CSR build ==========================================
__global__ void hist_k(const int* __restrict__ er, int e) {
    int i = blockIdx.x * blockDim.x + threadIdx.x;
    if (i < e) atomicAdd(&g_cnt[er[i]], 1);
}

__global__ __launch_bounds__(256) void scan1_k(int n) {
    __shared__ int red[256];
    int tid = threadIdx.x;
    int i = blockIdx.x * 256 + tid;
    red[tid] = (i < n) ? g_cnt[i] : 0;
    __syncthreads();
    for (int off = 128; off > 0; off >>= 1) {
        if (tid < off) red[tid] += red[tid + off];
        __syncthreads();
    }
    if (tid == 0) g_bsum[blockIdx.x] = red[0];
}

// scan3: computes its own block prefix from g_bsum (nblk <= 256), then the
// per-element exclusive scan. Also restores g_cnt zero invariant.
__global__ __launch_bounds__(256) void scan3_k(int n, int nblk) {
    __shared__ int bs[256];
    __shared__ int s[256];
    int tid = threadIdx.x;
    bs[tid] = (tid < nblk) ? g_bsum[tid] : 0;
    __syncthreads();
    for (int off = 1; off < 256; off <<= 1) {
        int t = (tid >= off) ? bs[tid - off] : 0;
        __syncthreads();
        bs[tid] += t;
        __syncthreads();
    }
    int bpref = (blockIdx.x == 0) ? 0 : bs[blockIdx.x - 1];
    if (blockIdx.x == 0 && tid == 0) g_rowptr[n] = bs[255];
    int i = blockIdx.x * 256 + tid;
    int v = (i < n) ? g_cnt[i] : 0;
    s[tid] = v;
    __syncthreads();
    for (int off = 1; off < 256; off <<= 1) {
        int t = (tid >= off) ? s[tid - off] : 0;
        __syncthreads();
        s[tid] += t;
        __syncthreads();
    }
    if (i < n) {
        int excl = s[tid] - v + bpref;
        g_rowptr[i] = excl;
        g_wcur[i] = excl;
        g_cnt[i] = 0;
    }
}

__global__ void scatter_k(const int* __restrict__ er, const int* __restrict__ ec,
                          const float* __restrict__ ev, int e) {
    int i = blockIdx.x * blockDim.x + threadIdx.x;
    if (i < e) {
        int r = er[i];
        int pos = atomicAdd(&g_wcur[r], 1);
        g_edge[pos] = make_int2(ec[i], __float_as_int(ev[i]));
    }
}

// ======================= SPMM (fp16 in/out) + fused PairNorm stats ==========
__global__ __launch_bounds__(256) void spmm_k(
    const __half* __restrict__ g, const float* __restrict__ bias,
    __half* __restrict__ h, int n, int slot) {
    __shared__ float red[256];
    int tid = threadIdx.x;
    red[tid] = 0.f;
    int w = tid >> 5, lane = tid & 31;
    int gw = blockIdx.x * 8 + w;
    int c = lane * 4;
    float4 b4 = *reinterpret_cast<const float4*>(&bias[c]);
    float4 ssum = make_float4(0.f, 0.f, 0.f, 0.f);
    float4 ssq = make_float4(0.f, 0.f, 0.f, 0.f);
    __syncthreads();
#pragma unroll
    for (int rr = 0; rr < 4; rr++) {
        int row = gw * 4 + rr;
        if (row >= n) break;
        int s = g_rowptr[row];
        int e = g_rowptr[row + 1];
        float4 acc = make_float4(0.f, 0.f, 0.f, 0.f);
        int i = s;
        for (; i + 7 < e; i += 8) {
            uint2 p[8];
            float vv[8];
#pragma unroll
            for (int u = 0; u < 8; u++) {
                int2 ed = g_edge[i + u];
                vv[u] = __int_as_float(ed.y);
                p[u] = *reinterpret_cast<const uint2*>(&g[(size_t)ed.x * DIM + c]);
            }
#pragma unroll
            for (int u = 0; u < 8; u++) {
                float4 gv = h4_to_f4(p[u]);
                acc.x += vv[u] * gv.x;
                acc.y += vv[u] * gv.y;
                acc.z += vv[u] * gv.z;
                acc.w += vv[u] * gv.w;
            }
        }
        if (i + 3 < e) {
            uint2 p[4];
            float vv[4];
#pragma unroll
            for (int u = 0; u < 4; u++) {
                int2 ed = g_edge[i + u];
                vv[u] = __int_as_float(ed.y);
                p[u] = *reinterpret_cast<const uint2*>(&g[(size_t)ed.x * DIM + c]);
            }
#pragma unroll
            for (int u = 0; u < 4; u++) {
                float4 gv = h4_to_f4(p[u]);
                acc.x += vv[u] * gv.x;
                acc.y += vv[u] * gv.y;
                acc.z += vv[u] * gv.z;
                acc.w += vv[u] * gv.w;
            }
            i += 4;
        }
        for (; i < e; i++) {
            int2 ed = g_edge[i];
            float v0 = __int_as_float(ed.y);
            float4 gv = h4_to_f4(*reinterpret_cast<const uint2*>(&g[(size_t)ed.x * DIM + c]));
            acc.x += v0 * gv.x; acc.y += v0 * gv.y;
            acc.z += v0 * gv.z; acc.w += v0 * gv.w;
        }
        acc.x += b4.x; acc.y += b4.y; acc.z += b4.z; acc.w += b4.w;
        __half2 o0 = __floats2half2_rn(acc.x, acc.y);
        __half2 o1 = __floats2half2_rn(acc.z, acc.w);
        uint2 ov;
        ov.x = *reinterpret_cast<uint32_t*>(&o0);
        ov.y = *reinterpret_cast<uint32_t*>(&o1);
        *reinterpret_cast<uint2*>(&h[(size_t)row * DIM + c]) = ov;
        ssum.x += acc.x; ssum.y += acc.y; ssum.z += acc.z; ssum.w += acc.w;
        ssq.x += acc.x * acc.x; ssq.y += acc.y * acc.y;
        ssq.z += acc.z * acc.z; ssq.w += acc.w * acc.w;
    }
    atomicAdd(&red[c], ssum.x);     atomicAdd(&red[c + 1], ssum.y);
    atomicAdd(&red[c + 2], ssum.z); atomicAdd(&red[c + 3], ssum.w);
    atomicAdd(&red[128 + c], ssq.x);     atomicAdd(&red[128 + c + 1], ssq.y);
    atomicAdd(&red[128 + c + 2], ssq.z); atomicAdd(&red[128 + c + 3], ssq.w);
    __syncthreads();
    if (tid < 128) atomicAdd(&g_cs[slot][tid], red[tid]);
    else atomicAdd(&g_cq[slot][tid - 128], red[tid]);
}

// ======================= output GEMM + fused final PairNorm =================
__global__ __launch_bounds__(256) void gemm_out_k(
    const __half* __restrict__ H, const float* __restrict__ Xold,
    const float* __restrict__ W, const float* __restrict__ b,
    float* __restrict__ out, int n, int pn_slot, float n_inv) {
    __shared__ float sx[32 * DIM];
    __shared__ float sw[DIM * CDIM];
    __shared__ float smu[DIM];
    __shared__ float red[DIM];
    int tid = threadIdx.x;
    int row0 = blockIdx.x * 32;
    for (int i = tid; i < DIM * CDIM; i += 256) sw[i] = W[i];
    if (tid < DIM) {
        float mu = g_cs[pn_slot][tid] * n_inv;
        smu[tid] = mu;
        red[tid] = g_cq[pn_slot][tid] * n_inv - mu * mu;
    }
    __syncthreads();
    for (int off = 64; off > 0; off >>= 1) {
        if (tid < off) red[tid] += red[tid + off];
        __syncthreads();
    }
    if (tid == 0) red[0] = rsqrtf(1e-6f + red[0]);
    __syncthreads();
    float s = red[0];
#pragma unroll
    for (int q = 0; q < 4; q++) {
        int flat = (q * 256 + tid) * 4;
        int r = flat >> 7, c = flat & 127;
        int row = row0 + r;
        float4 v = make_float4(0.f, 0.f, 0.f, 0.f);
        if (row < n) {
            float4 hv = h4_to_f4(*reinterpret_cast<const uint2*>(&H[(size_t)row * DIM + c]));
            float4 m = *reinterpret_cast<const float4*>(&smu[c]);
            float4 xo = *reinterpret_cast<const float4*>(&Xold[(size_t)row * DIM + c]);
            v.x = fmaxf((hv.x - m.x) * s, 0.f) + xo.x;
            v.y = fmaxf((hv.y - m.y) * s, 0.f) + xo.y;
            v.z = fmaxf((hv.z - m.z) * s, 0.f) + xo.z;
            v.w = fmaxf((hv.w - m.w) * s, 0.f) + xo.w;
        }
        *reinterpret_cast<float4*>(&sx[flat]) = v;
    }
    __syncthreads();
    int r = tid >> 3;
    int c0 = (tid & 7) * 5;
    float acc[5];
#pragma unroll
    for (int j = 0; j < 5; j++) acc[j] = b[c0 + j];
#pragma unroll 4
    for (int k = 0; k < DIM; k++) {
        float xv = sx[r * DIM + k];
#pragma unroll
        for (int j = 0; j < 5; j++) acc[j] += xv * sw[k * CDIM + c0 + j];
    }
    if (row0 + r < n) {
#pragma unroll
        for (int j = 0; j < 5; j++) out[(size_t)(row0 + r) * CDIM + c0 + j] = acc[j];
    }
}

// ======================= launch =============================================
extern "C" void kernel_launch(void* const* d_in, const int* in_sizes, int n_in,
                              void* d_out, int out_size) {
    const float* x      = (const float*)d_in[0];
    const int*   er     = (const int*)d_in[1];
    const int*   ec     = (const int*)d_in[2];
    const float* ev     = (const float*)d_in[3];
    const float* gamma  = (const float*)d_in[4];
    const float* beta   = (const float*)d_in[5];
    const float* fin_w  = (const float*)d_in[6];
    const float* fin_b  = (const float*)d_in[7];
    const float* gc_w   = (const float*)d_in[8];
    const float* gc_b   = (const float*)d_in[9];
    const float* fout_w = (const float*)d_in[10];
    const float* fout_b = (const float*)d_in[11];
    float* out = (float*)d_out;

    int n = in_sizes[0] / DIM;
    int e = in_sizes[1];
    float n_inv = 1.0f / (float)n;

    float* xbuf;
    __half *g16, *h16;
    cudaGetSymbolAddress((void**)&xbuf, g_xbuf);
    cudaGetSymbolAddress((void**)&g16, g_g16);
    cudaGetSymbolAddress((void**)&h16, g_h16);

    // one-time host objects (created on the uncaptured correctness call)
    static cudaStream_t s2 = nullptr;
    static cudaEvent_t evFork = nullptr, evJoin = nullptr;
    if (s2 == nullptr) {
        cudaStreamCreateWithFlags(&s2, cudaStreamNonBlocking);
        cudaEventCreateWithFlags(&evFork, cudaEventDisableTiming);
        cudaEventCreateWithFlags(&evJoin, cudaEventDisableTiming);
        cudaFuncSetAttribute(gemm_mma_k, cudaFuncAttributeMaxDynamicSharedMemorySize, GEMM_SMEM_BYTES);
        cudaFuncSetAttribute(gemm_fused_k, cudaFuncAttributeMaxDynamicSharedMemorySize, FUSED_SMEM_BYTES);
    }

    int sblocks = (n + 31) / 32;
    int nblk = (n + 255) / 256;
    int eblk = (e + 255) / 256;
    const int WMAT = DIM * DIM;

    // ---- fork: branch B (BN stats -> fused GEMM) runs concurrently with
    //      the CSR build chain on the main stream. Disjoint state.
    cudaEventRecord(evFork, 0);
    cudaStreamWaitEvent(s2, evFork, 0);

    // branch B (stream s2)
    col_stats_k<<<256, 256, 0, s2>>>(x, n);
    gemm_fused_k<<<NSM, 512, FUSED_SMEM_BYTES, s2>>>(
        x, fin_w, fin_b, gamma, beta, gc_w, g16, n, n_inv);

    // main stream: CSR build
    hist_k<<<eblk, 256>>>(er, e);
    scan1_k<<<nblk, 256>>>(n);
    scan3_k<<<nblk, 256>>>(n, nblk);
    scatter_k<<<eblk, 256>>>(er, ec, ev, e);

    // ---- join
    cudaEventRecord(evJoin, s2);
    cudaStreamWaitEvent(0, evJoin, 0);

    // ---- layer 0 spmm (needs CSR + g16 + PN slot 0 zeroed by gemm_fused) --
    spmm_k<<<sblocks, 256>>>(g16, gc_b + 0 * DIM, h16, n, 0);

    // ---- layers 1..3: persistent GEMM with fused PairNorm-apply on A ----
    for (int i = 1; i < NLAYER; i++) {
        gemm_mma_k<<<NSM, 512, GEMM_SMEM_BYTES>>>(
            h16, xbuf, xbuf, gc_w + i * WMAT,
            g16, n, (i - 1) & 1, i & 1, (i >= 2) ? 1 : 0, n_inv);
        spmm_k<<<sblocks, 256>>>(g16, gc_b + i * DIM, h16, n, i & 1);
    }

    // ---- output projection with fused final PairNorm (slot 1, addold) ----
    gemm_out_k<<<sblocks, 256>>>(h16, xbuf, fout_w, fout_b, out, n, (NLAYER - 1) & 1, n_inv);
}